// round 2
// baseline (speedup 1.0000x reference)
#include <cuda_runtime.h>
#include <math.h>

// ---------------- problem constants ----------------
#define B_    32
#define M_    512
#define E_    512
#define S_    513
#define NTOK  (B_*S_)          // 16416
#define NHEAD_ 8
#define DH_   64
#define DFF_  2048
#define F_    768

// ---------------- scratch (device globals: allocation-guard-safe) ----------------
__device__ float d_PE[M_*E_];
__device__ int   d_SPAN[B_*M_];
__device__ float d_X  [(size_t)NTOK*E_];
__device__ float d_Y  [(size_t)NTOK*E_];
__device__ float d_CTX[(size_t)NTOK*E_];
__device__ float d_QKV[(size_t)NTOK*3*E_];
__device__ float d_H  [(size_t)NTOK*DFF_];
__device__ float d_POSF[(size_t)NTOK*F_];

// ---------------- PE table (double math to match numpy float64 path) ----------------
__global__ void pe_kernel(float* pe) {
    int idx = blockIdx.x * blockDim.x + threadIdx.x;
    if (idx >= M_ * E_) return;
    int pos = idx / E_, i = idx % E_;
    double e2  = (double)((i / 2) * 2);
    double ang = (double)pos / pow(10000.0, e2 / (double)E_);
    pe[idx] = (float)((i % 2 == 0) ? sin(ang) : cos(ang));
}

// ---------------- span id: one block per batch ----------------
__global__ void span_kernel(const int* __restrict__ pos1, int* __restrict__ span) {
    int b = blockIdx.x;
    int j = threadIdx.x;                 // 512 threads
    __shared__ int firstZero;
    span[b*M_ + j] = -1;
    if (j == 0) firstZero = M_;
    __syncthreads();
    int endv = pos1[((size_t)b*M_ + j)*2 + 1];
    if (endv == 0) atomicMin(&firstZero, j);
    __syncthreads();
    if (j < firstZero) {
        int st = pos1[((size_t)b*M_ + j)*2];
        int en = endv; if (en > M_) en = M_;
        for (int k = st; k < en; k++)
            atomicMax(&span[b*M_ + k], j);
    }
}

// ---------------- build x [B,S,E] ----------------
__global__ void build_x_kernel(const int* __restrict__ pos2,
                               const float* __restrict__ fbase,
                               const float* __restrict__ emb,
                               const int* __restrict__ span,
                               const float* __restrict__ pe,
                               float* __restrict__ X) {
    int row = blockIdx.x;                // token index n = b*S + s
    int b = row / S_, s = row % S_;
    float* out = X + (size_t)row * E_;
    if (s == 0) {
        for (int e = threadIdx.x; e < E_; e += blockDim.x)
            out[e] = emb[(size_t)1*E_ + e];
        return;
    }
    int k = s - 1;
    int sid = span[b*M_ + k];
    if (sid >= 0) {
        int p = pos2[b*M_ + sid];
        const float* er = emb + (size_t)p * E_;
        const float* pr = pe  + (size_t)sid * E_;
        for (int e = threadIdx.x; e < E_; e += blockDim.x)
            out[e] = (p == 0 ? 0.0f : er[e]) + pr[e];
    } else {
        const float* fr = fbase + ((size_t)b*M_ + k) * E_;
        for (int e = threadIdx.x; e < E_; e += blockDim.x)
            out[e] = fr[e];
    }
}

// ---------------- generic tiled GEMM (NT): C = act(alpha*A@B^T + bias) ----------------
template<int BM, int BN, int BK, int TM, int TN>
__global__ void gemm_nt_kernel(const float* __restrict__ A, int lda,
                               const float* __restrict__ Bp, int ldb,
                               float* __restrict__ C, int ldc,
                               int Mdim, int Ndim, int Kdim,
                               const float* __restrict__ bias,
                               int act)
{
    constexpr int NTHR = (BM/TM)*(BN/TN);
    __shared__ __align__(16) float As[BK][BM+4];
    __shared__ __align__(16) float Bs[BK][BN+4];

    const int tile_m = blockIdx.y * BM;
    const int tile_n = blockIdx.x * BN;
    const int tid = threadIdx.x;
    const int tx  = tid % (BN/TN);
    const int ty  = tid / (BN/TN);

    float acc[TM][TN];
    #pragma unroll
    for (int i = 0; i < TM; i++)
        #pragma unroll
        for (int j = 0; j < TN; j++) acc[i][j] = 0.0f;

    for (int k0 = 0; k0 < Kdim; k0 += BK) {
        #pragma unroll
        for (int idx = tid; idx < BM*BK; idx += NTHR) {
            int m = idx / BK, k = idx % BK;
            int gm = tile_m + m, gk = k0 + k;
            As[k][m] = (gm < Mdim) ? A[(long long)gm * lda + gk] : 0.0f;
        }
        #pragma unroll
        for (int idx = tid; idx < BN*BK; idx += NTHR) {
            int n = idx / BK, k = idx % BK;
            int gn = tile_n + n, gk = k0 + k;
            Bs[k][n] = (gn < Ndim) ? Bp[(long long)gn * ldb + gk] : 0.0f;
        }
        __syncthreads();

        #pragma unroll
        for (int kk = 0; kk < BK; kk++) {
            float af[TM], bf[TN];
            #pragma unroll
            for (int i = 0; i < TM; i += 4)
                *reinterpret_cast<float4*>(&af[i]) =
                    *reinterpret_cast<const float4*>(&As[kk][ty*TM + i]);
            #pragma unroll
            for (int j = 0; j < TN; j += 4)
                *reinterpret_cast<float4*>(&bf[j]) =
                    *reinterpret_cast<const float4*>(&Bs[kk][tx*TN + j]);
            #pragma unroll
            for (int i = 0; i < TM; i++)
                #pragma unroll
                for (int j = 0; j < TN; j++)
                    acc[i][j] += af[i] * bf[j];
        }
        __syncthreads();
    }

    #pragma unroll
    for (int i = 0; i < TM; i++) {
        int gm = tile_m + ty*TM + i;
        if (gm >= Mdim) continue;
        #pragma unroll
        for (int j = 0; j < TN; j++) {
            int gn = tile_n + tx*TN + j;
            if (gn >= Ndim) continue;
            float v = acc[i][j];
            if (bias) v += bias[gn];
            if (act == 1) v = fmaxf(v, 0.0f);
            else if (act == 2) v = tanhf(v);
            C[(long long)gm * ldc + gn] = v;
        }
    }
}

// ---------------- fused attention over the B axis ----------------
// Torch-style encoder on [B,S,E] treats dim0 (B) as sequence: for each
// (s, h), attend l,m over the 32 batch positions.
// One CTA per z = s*NHEAD + h. 256 threads.
__global__ void attn_kernel(const float* __restrict__ QKV,
                            float* __restrict__ CTX) {
    int z = blockIdx.x;
    int s = z / NHEAD_, h = z % NHEAD_;
    __shared__ float q[B_][DH_];
    __shared__ float k[B_][DH_];
    __shared__ float v[B_][DH_];
    __shared__ float sc[B_][B_ + 1];

    const float* base = QKV + (size_t)s * 3*E_ + (size_t)h * DH_;
    int t = threadIdx.x;

    for (int i = t; i < B_*DH_; i += 256) {
        int b = i / DH_, d = i % DH_;
        size_t off = (size_t)b * S_ * 3*E_ + d;
        q[b][d] = base[off];
        k[b][d] = base[off + E_];
        v[b][d] = base[off + 2*E_];
    }
    __syncthreads();

    // scores [32,32]: each thread 4 entries
    for (int i = t; i < B_*B_; i += 256) {
        int l = i / B_, m = i % B_;
        float acc = 0.0f;
        #pragma unroll
        for (int d = 0; d < DH_; d++) acc += q[l][d] * k[m][d];
        sc[l][m] = acc * 0.125f;          // 1/sqrt(64)
    }
    __syncthreads();

    // softmax: 8 warps, each handles 4 rows; lane = column (m)
    int warp = t >> 5, lane = t & 31;
    for (int l = warp; l < B_; l += 8) {
        float val = sc[l][lane];
        float mx = val;
        #pragma unroll
        for (int o = 16; o; o >>= 1) mx = fmaxf(mx, __shfl_xor_sync(0xffffffffu, mx, o));
        float e = expf(val - mx);
        float sum = e;
        #pragma unroll
        for (int o = 16; o; o >>= 1) sum += __shfl_xor_sync(0xffffffffu, sum, o);
        sc[l][lane] = e / sum;
    }
    __syncthreads();

    // ctx [32,64]: each thread 8 entries
    for (int i = t; i < B_*DH_; i += 256) {
        int l = i / DH_, d = i % DH_;
        float acc = 0.0f;
        #pragma unroll
        for (int m = 0; m < B_; m++) acc += sc[l][m] * v[m][d];
        CTX[((size_t)l * S_ + s) * E_ + (size_t)h * DH_ + d] = acc;
    }
}

// ---------------- residual add + layernorm, in place on x ----------------
__global__ void add_ln_kernel(float* __restrict__ x, const float* __restrict__ y,
                              const float* __restrict__ w, const float* __restrict__ b) {
    long long row = blockIdx.x;
    __shared__ float red[256];
    int t = threadIdx.x;
    float v0 = x[row*E_ + t]       + y[row*E_ + t];
    float v1 = x[row*E_ + 256 + t] + y[row*E_ + 256 + t];
    red[t] = v0 + v1;
    __syncthreads();
    #pragma unroll
    for (int s2 = 128; s2 > 0; s2 >>= 1) { if (t < s2) red[t] += red[t + s2]; __syncthreads(); }
    float mean = red[0] * (1.0f / E_);
    __syncthreads();
    float d0 = v0 - mean, d1 = v1 - mean;
    red[t] = d0*d0 + d1*d1;
    __syncthreads();
    #pragma unroll
    for (int s2 = 128; s2 > 0; s2 >>= 1) { if (t < s2) red[t] += red[t + s2]; __syncthreads(); }
    float rstd = rsqrtf(red[0] * (1.0f / E_) + 1e-5f);
    x[row*E_ + t]       = d0 * rstd * w[t]       + b[t];
    x[row*E_ + 256 + t] = d1 * rstd * w[t + 256] + b[t + 256];
}

// ---------------- discriminator head: warp per token ----------------
__global__ void disc_kernel(const float* __restrict__ bert,
                            const float* __restrict__ posf,
                            const float* __restrict__ wd,
                            const float* __restrict__ bd,
                            float* __restrict__ out, int ntok) {
    int n = (blockIdx.x * blockDim.x + threadIdx.x) >> 5;
    int lane = threadIdx.x & 31;
    if (n >= ntok) return;
    float acc = 0.0f;
    const float* br = bert + (size_t)n * F_;
    const float* pr = posf + (size_t)n * F_;
    for (int i = lane; i < F_; i += 32) acc += br[i] * wd[i];
    for (int i = lane; i < F_; i += 32) acc += pr[i] * wd[F_ + i];
    #pragma unroll
    for (int o = 16; o; o >>= 1) acc += __shfl_xor_sync(0xffffffffu, acc, o);
    if (lane == 0) out[n] = 1.0f / (1.0f + expf(-(acc + bd[0])));
}

// ---------------- host orchestration ----------------
static inline int cdiv(int a, int b) { return (a + b - 1) / b; }

extern "C" void kernel_launch(void* const* d_in, const int* in_sizes, int n_in,
                              void* d_out, int out_size) {
    const int*   pos1  = (const int*)d_in[0];
    const int*   pos2  = (const int*)d_in[1];
    const float* bert  = (const float*)d_in[2];
    const float* fbase = (const float*)d_in[3];
    const float* emb   = (const float*)d_in[4];
    const float* wqkv  = (const float*)d_in[5];   // [2,1536,512]
    const float* bqkv  = (const float*)d_in[6];   // [2,1536]
    const float* wo    = (const float*)d_in[7];   // [2,512,512]
    const float* bo    = (const float*)d_in[8];   // [2,512]
    const float* ln1w  = (const float*)d_in[9];
    const float* ln1b  = (const float*)d_in[10];
    const float* ln2w  = (const float*)d_in[11];
    const float* ln2b  = (const float*)d_in[12];
    const float* w1    = (const float*)d_in[13];  // [2,2048,512]
    const float* b1    = (const float*)d_in[14];  // [2,2048]
    const float* w2    = (const float*)d_in[15];  // [2,512,2048]
    const float* b2    = (const float*)d_in[16];  // [2,512]
    const float* wm    = (const float*)d_in[17];  // [768,512]
    const float* wd    = (const float*)d_in[18];  // [1,1536]
    const float* bd    = (const float*)d_in[19];  // [1]
    float* out = (float*)d_out;

    float *PE, *X, *Y, *CTX, *QKV, *H, *POSF; int* SPAN;
    cudaGetSymbolAddress((void**)&PE,   d_PE);
    cudaGetSymbolAddress((void**)&SPAN, d_SPAN);
    cudaGetSymbolAddress((void**)&X,    d_X);
    cudaGetSymbolAddress((void**)&Y,    d_Y);
    cudaGetSymbolAddress((void**)&CTX,  d_CTX);
    cudaGetSymbolAddress((void**)&QKV,  d_QKV);
    cudaGetSymbolAddress((void**)&H,    d_H);
    cudaGetSymbolAddress((void**)&POSF, d_POSF);

    // ---- preamble ----
    pe_kernel<<<cdiv(M_*E_, 256), 256>>>(PE);
    span_kernel<<<B_, M_>>>(pos1, SPAN);
    build_x_kernel<<<NTOK, 256>>>(pos2, fbase, emb, SPAN, PE, X);

    for (int l = 0; l < 2; l++) {
        const float* Wqkv = wqkv + (size_t)l * 3*E_ * E_;
        const float* Bqkv = bqkv + (size_t)l * 3*E_;
        const float* Wo   = wo   + (size_t)l * E_ * E_;
        const float* Bo   = bo   + (size_t)l * E_;
        const float* W1   = w1   + (size_t)l * DFF_ * E_;
        const float* B1   = b1   + (size_t)l * DFF_;
        const float* W2   = w2   + (size_t)l * E_ * DFF_;
        const float* B2   = b2   + (size_t)l * E_;

        // QKV = X @ Wqkv^T + bqkv     [NTOK, 1536]
        {
            dim3 g(cdiv(3*E_, 128), cdiv(NTOK, 128), 1);
            gemm_nt_kernel<128,128,16,8,8><<<g, 256>>>(
                X, E_, Wqkv, E_, QKV, 3*E_, NTOK, 3*E_, E_, Bqkv, 0);
        }
        // fused attention over B axis (torch seq-dim = dim0)
        attn_kernel<<<S_*NHEAD_, 256>>>(QKV, CTX);
        // Y = CTX @ Wo^T + bo
        {
            dim3 g(cdiv(E_, 128), cdiv(NTOK, 128), 1);
            gemm_nt_kernel<128,128,16,8,8><<<g, 256>>>(
                CTX, E_, Wo, E_, Y, E_, NTOK, E_, E_, Bo, 0);
        }
        // X = LN1(X + Y)
        add_ln_kernel<<<NTOK, 256>>>(X, Y, ln1w + l*E_, ln1b + l*E_);

        // H = relu(X @ W1^T + b1)   [NTOK, 2048]
        {
            dim3 g(cdiv(DFF_, 128), cdiv(NTOK, 128), 1);
            gemm_nt_kernel<128,128,16,8,8><<<g, 256>>>(
                X, E_, W1, E_, H, DFF_, NTOK, DFF_, E_, B1, 1);
        }
        // Y = H @ W2^T + b2
        {
            dim3 g(cdiv(E_, 128), cdiv(NTOK, 128), 1);
            gemm_nt_kernel<128,128,16,8,8><<<g, 256>>>(
                H, DFF_, W2, DFF_, Y, E_, NTOK, E_, DFF_, B2, 0);
        }
        // X = LN2(X + Y)
        add_ln_kernel<<<NTOK, 256>>>(X, Y, ln2w + l*E_, ln2b + l*E_);
    }

    // POSF = tanh(X @ wm^T)   [NTOK, 768]
    {
        dim3 g(cdiv(F_, 128), cdiv(NTOK, 128), 1);
        gemm_nt_kernel<128,128,16,8,8><<<g, 256>>>(
            X, E_, wm, E_, POSF, F_, NTOK, F_, E_, nullptr, 2);
    }
    // out = sigmoid(concat(bert, posf) @ wd^T + bd)
    disc_kernel<<<cdiv(NTOK*32, 256), 256>>>(bert, POSF, wd, bd, out, NTOK);
}

// round 4
// speedup vs baseline: 3.5853x; 3.5853x over previous
#include <cuda_runtime.h>
#include <cuda_bf16.h>
#include <math.h>
#include <stdint.h>

// ---------------- problem constants ----------------
#define B_    32
#define M_    512
#define E_    512
#define S_    513
#define NTOK  (B_*S_)          // 16416
#define NHEAD_ 8
#define DH_   64
#define DFF_  2048
#define F_    768

// ---------------- scratch (device globals) ----------------
__device__ float d_PE[M_*E_];
__device__ int   d_SPAN[B_*M_];
__device__ float d_X  [(size_t)NTOK*E_];
__device__ float d_Y  [(size_t)NTOK*E_];
__device__ float d_CTX[(size_t)NTOK*E_];
__device__ float d_QKV[(size_t)NTOK*3*E_];
__device__ float d_H  [(size_t)NTOK*DFF_];
__device__ float d_POSF[(size_t)NTOK*F_];

// ================= bf16-split tensor-core GEMM (mma.sync, arch-generic) ========
// C[M,N] = act( A[M,K] @ B[N,K]^T + bias ),  fp32 in/out, fp32 accum.
// Split: x = hi + lo (bf16 each); D = Ah*Bh + Ah*Bl + Al*Bh.
#define BM_T 128
#define BN_T 128
#define BK_T 32
#define LDS_ 40                     // padded bf16 row stride (40*2=80B, 16B aligned)
#define ARR_BYTES (128*LDS_*2)      // 10240 B per tile array
#define STAGE_BYTES (4*ARR_BYTES)   // Ah, Al, Bh, Bl
#define SMEM_GEMM (2*STAGE_BYTES)   // 81920 B

__device__ __forceinline__ uint32_t smem_u32(const void* p) {
    uint32_t a;
    asm("{ .reg .u64 t; cvta.to.shared.u64 t, %1; cvt.u32.u64 %0, t; }"
        : "=r"(a) : "l"(p));
    return a;
}
__device__ __forceinline__ void ldsm4(uint32_t* r, uint32_t addr) {
    asm volatile("ldmatrix.sync.aligned.m8n8.x4.shared.b16 {%0,%1,%2,%3}, [%4];"
        : "=r"(r[0]), "=r"(r[1]), "=r"(r[2]), "=r"(r[3]) : "r"(addr));
}
__device__ __forceinline__ void ldsm2(uint32_t* r, uint32_t addr) {
    asm volatile("ldmatrix.sync.aligned.m8n8.x2.shared.b16 {%0,%1}, [%2];"
        : "=r"(r[0]), "=r"(r[1]) : "r"(addr));
}
__device__ __forceinline__ void mma16816(float* c, const uint32_t* a, const uint32_t* b) {
    asm volatile(
        "mma.sync.aligned.m16n8k16.row.col.f32.bf16.bf16.f32 "
        "{%0,%1,%2,%3}, {%4,%5,%6,%7}, {%8,%9}, {%0,%1,%2,%3};"
        : "+f"(c[0]), "+f"(c[1]), "+f"(c[2]), "+f"(c[3])
        : "r"(a[0]), "r"(a[1]), "r"(a[2]), "r"(a[3]), "r"(b[0]), "r"(b[1]));
}

// convert float4 -> (hi bf16x4, lo bf16x4) packed as uint2 each
__device__ __forceinline__ void split4(float4 v, uint2& hi, uint2& lo) {
    __nv_bfloat162 h01, h23, l01, l23;
    h01.x = __float2bfloat16_rn(v.x); h01.y = __float2bfloat16_rn(v.y);
    h23.x = __float2bfloat16_rn(v.z); h23.y = __float2bfloat16_rn(v.w);
    l01.x = __float2bfloat16_rn(v.x - __bfloat162float(h01.x));
    l01.y = __float2bfloat16_rn(v.y - __bfloat162float(h01.y));
    l23.x = __float2bfloat16_rn(v.z - __bfloat162float(h23.x));
    l23.y = __float2bfloat16_rn(v.w - __bfloat162float(h23.y));
    hi.x = *reinterpret_cast<uint32_t*>(&h01); hi.y = *reinterpret_cast<uint32_t*>(&h23);
    lo.x = *reinterpret_cast<uint32_t*>(&l01); lo.y = *reinterpret_cast<uint32_t*>(&l23);
}

__global__ __launch_bounds__(256, 1)
void gemm_tc(const float* __restrict__ A, const float* __restrict__ Bw,
             float* __restrict__ C, int Mdim, int Ndim, int Kdim,
             const float* __restrict__ bias, int act)
{
    extern __shared__ __align__(16) char smem[];
    const uint32_t sb = smem_u32(smem);
    const int tid    = threadIdx.x;
    const int tile_m = blockIdx.y * BM_T;
    const int tile_n = blockIdx.x * BN_T;

    // loader mapping: 128 rows x 32 cols fp32, thread -> (row=tid/2, 16-col half)
    const int lr   = tid >> 1;
    const int lc   = (tid & 1) * 16;
    const bool a_valid = (tile_m + lr) < Mdim;
    const float* aptr = A  + (size_t)(tile_m + lr) * Kdim + lc;
    const float* bptr = Bw + (size_t)(tile_n + lr) * Kdim + lc;

    // warp tiling: 8 warps as 4(M) x 2(N); warp tile 32x64
    const int warp = tid >> 5, lane = tid & 31;
    const int wm = warp & 3, wn = warp >> 2;

    float acc[2][8][4];
    #pragma unroll
    for (int i = 0; i < 2; i++)
        #pragma unroll
        for (int j = 0; j < 8; j++)
            #pragma unroll
            for (int q = 0; q < 4; q++) acc[i][j][q] = 0.0f;

    const int nst = Kdim >> 5;

    float4 pa[4], pb[4];   // prefetch registers (chunk s+1)

    // ---- prologue: chunk 0 -> smem stage 0; prefetch chunk 1 ----
    {
        #pragma unroll
        for (int j = 0; j < 4; j++) {
            pa[j] = a_valid ? *reinterpret_cast<const float4*>(aptr + j*4)
                            : make_float4(0.f,0.f,0.f,0.f);
            pb[j] = *reinterpret_cast<const float4*>(bptr + j*4);
        }
        char* sp = smem;
        #pragma unroll
        for (int j = 0; j < 4; j++) {
            uint2 hi, lo;
            uint32_t off = (lr*LDS_ + lc + j*4) * 2;
            split4(pa[j], hi, lo);
            *reinterpret_cast<uint2*>(sp + off)              = hi;
            *reinterpret_cast<uint2*>(sp + ARR_BYTES + off)  = lo;
            split4(pb[j], hi, lo);
            *reinterpret_cast<uint2*>(sp + 2*ARR_BYTES + off) = hi;
            *reinterpret_cast<uint2*>(sp + 3*ARR_BYTES + off) = lo;
        }
        if (nst > 1) {
            #pragma unroll
            for (int j = 0; j < 4; j++) {
                pa[j] = a_valid ? *reinterpret_cast<const float4*>(aptr + 32 + j*4)
                                : make_float4(0.f,0.f,0.f,0.f);
                pb[j] = *reinterpret_cast<const float4*>(bptr + 32 + j*4);
            }
        }
    }
    __syncthreads();

    // precomputed ldmatrix lane offsets (bytes within an array)
    // A: row = wm*32 + mi*16 + (lane&7) + ((lane>>3)&1)*8 ; kcol = (lane>>4)*8
    const uint32_t a_row = wm*32 + (lane & 7) + ((lane >> 3) & 1) * 8;
    const uint32_t a_kof = (lane >> 4) * 16;               // *8 cols *2B
    // B: row = wn*64 + ni*8 + (lane&7) ; kcol = ((lane>>3)&1)*8  (lanes 0-15 used)
    const uint32_t b_row = wn*64 + (lane & 7);
    const uint32_t b_kof = ((lane >> 3) & 1) * 16;

    for (int s = 0; s < nst; s++) {
        const uint32_t st = sb + (s & 1) * STAGE_BYTES;

        // ---- compute on stage s ----
        #pragma unroll
        for (int ks = 0; ks < 2; ks++) {
            const uint32_t kb = ks * 32;  // 16 cols * 2B
            uint32_t ah[2][4], al[2][4], bh[8][2], bl[8][2];
            #pragma unroll
            for (int mi = 0; mi < 2; mi++) {
                uint32_t ad = st + (a_row + mi*16) * (LDS_*2) + kb + a_kof;
                ldsm4(ah[mi], ad);
                ldsm4(al[mi], ad + ARR_BYTES);
            }
            #pragma unroll
            for (int ni = 0; ni < 8; ni++) {
                uint32_t bd = st + 2*ARR_BYTES + (b_row + ni*8) * (LDS_*2) + kb + b_kof;
                ldsm2(bh[ni], bd);
                ldsm2(bl[ni], bd + ARR_BYTES);
            }
            #pragma unroll
            for (int mi = 0; mi < 2; mi++)
                #pragma unroll
                for (int ni = 0; ni < 8; ni++) {
                    mma16816(acc[mi][ni], ah[mi], bh[ni]);
                    mma16816(acc[mi][ni], ah[mi], bl[ni]);
                    mma16816(acc[mi][ni], al[mi], bh[ni]);
                }
        }

        if (s + 1 < nst) {
            __syncthreads();   // everyone done reading stage (s+1)&1 (from iter s-1)
            char* sp = smem + ((s + 1) & 1) * STAGE_BYTES;
            #pragma unroll
            for (int j = 0; j < 4; j++) {
                uint2 hi, lo;
                uint32_t off = (lr*LDS_ + lc + j*4) * 2;
                split4(pa[j], hi, lo);
                *reinterpret_cast<uint2*>(sp + off)              = hi;
                *reinterpret_cast<uint2*>(sp + ARR_BYTES + off)  = lo;
                split4(pb[j], hi, lo);
                *reinterpret_cast<uint2*>(sp + 2*ARR_BYTES + off) = hi;
                *reinterpret_cast<uint2*>(sp + 3*ARR_BYTES + off) = lo;
            }
            if (s + 2 < nst) {
                const int k0 = (s + 2) << 5;
                #pragma unroll
                for (int j = 0; j < 4; j++) {
                    pa[j] = a_valid ? *reinterpret_cast<const float4*>(aptr + k0 + j*4)
                                    : make_float4(0.f,0.f,0.f,0.f);
                    pb[j] = *reinterpret_cast<const float4*>(bptr + k0 + j*4);
                }
            }
            __syncthreads();   // stores visible before compute on s+1
        }
    }

    // ---- epilogue ----
    const int er = lane >> 2;          // 0..7
    const int ec = (lane & 3) * 2;     // 0,2,4,6
    #pragma unroll
    for (int mi = 0; mi < 2; mi++) {
        const int gm0 = tile_m + wm*32 + mi*16 + er;
        #pragma unroll
        for (int ni = 0; ni < 8; ni++) {
            const int gn = tile_n + wn*64 + ni*8 + ec;
            float2 b2 = make_float2(0.f, 0.f);
            if (bias) b2 = *reinterpret_cast<const float2*>(bias + gn);
            float v0 = acc[mi][ni][0] + b2.x;
            float v1 = acc[mi][ni][1] + b2.y;
            float v2 = acc[mi][ni][2] + b2.x;
            float v3 = acc[mi][ni][3] + b2.y;
            if (act == 1) {
                v0 = fmaxf(v0, 0.f); v1 = fmaxf(v1, 0.f);
                v2 = fmaxf(v2, 0.f); v3 = fmaxf(v3, 0.f);
            } else if (act == 2) {
                v0 = tanhf(v0); v1 = tanhf(v1); v2 = tanhf(v2); v3 = tanhf(v3);
            }
            if (gm0 < Mdim)
                *reinterpret_cast<float2*>(C + (size_t)gm0 * Ndim + gn) = make_float2(v0, v1);
            if (gm0 + 8 < Mdim)
                *reinterpret_cast<float2*>(C + (size_t)(gm0 + 8) * Ndim + gn) = make_float2(v2, v3);
        }
    }
}

// ---------------- PE table ----------------
__global__ void pe_kernel(float* pe) {
    int idx = blockIdx.x * blockDim.x + threadIdx.x;
    if (idx >= M_ * E_) return;
    int pos = idx / E_, i = idx % E_;
    double e2  = (double)((i / 2) * 2);
    double ang = (double)pos / pow(10000.0, e2 / (double)E_);
    pe[idx] = (float)((i % 2 == 0) ? sin(ang) : cos(ang));
}

// ---------------- span id ----------------
__global__ void span_kernel(const int* __restrict__ pos1, int* __restrict__ span) {
    int b = blockIdx.x;
    int j = threadIdx.x;
    __shared__ int firstZero;
    span[b*M_ + j] = -1;
    if (j == 0) firstZero = M_;
    __syncthreads();
    int endv = pos1[((size_t)b*M_ + j)*2 + 1];
    if (endv == 0) atomicMin(&firstZero, j);
    __syncthreads();
    if (j < firstZero) {
        int st = pos1[((size_t)b*M_ + j)*2];
        int en = endv; if (en > M_) en = M_;
        for (int k = st; k < en; k++)
            atomicMax(&span[b*M_ + k], j);
    }
}

// ---------------- build x [B,S,E] ----------------
__global__ void build_x_kernel(const int* __restrict__ pos2,
                               const float* __restrict__ fbase,
                               const float* __restrict__ emb,
                               const int* __restrict__ span,
                               const float* __restrict__ pe,
                               float* __restrict__ X) {
    int row = blockIdx.x;
    int b = row / S_, s = row % S_;
    float* out = X + (size_t)row * E_;
    if (s == 0) {
        for (int e = threadIdx.x; e < E_; e += blockDim.x)
            out[e] = emb[(size_t)1*E_ + e];
        return;
    }
    int k = s - 1;
    int sid = span[b*M_ + k];
    if (sid >= 0) {
        int p = pos2[b*M_ + sid];
        const float* er = emb + (size_t)p * E_;
        const float* pr = pe  + (size_t)sid * E_;
        for (int e = threadIdx.x; e < E_; e += blockDim.x)
            out[e] = (p == 0 ? 0.0f : er[e]) + pr[e];
    } else {
        const float* fr = fbase + ((size_t)b*M_ + k) * E_;
        for (int e = threadIdx.x; e < E_; e += blockDim.x)
            out[e] = fr[e];
    }
}

// ---------------- fused attention over the B axis ----------------
__global__ void attn_kernel(const float* __restrict__ QKV,
                            float* __restrict__ CTX) {
    int z = blockIdx.x;
    int s = z / NHEAD_, h = z % NHEAD_;
    __shared__ float q[B_][DH_];
    __shared__ float k[B_][DH_];
    __shared__ float v[B_][DH_];
    __shared__ float sc[B_][B_ + 1];

    const float* base = QKV + (size_t)s * 3*E_ + (size_t)h * DH_;
    int t = threadIdx.x;

    for (int i = t; i < B_*DH_; i += 256) {
        int b = i / DH_, d = i % DH_;
        size_t off = (size_t)b * S_ * 3*E_ + d;
        q[b][d] = base[off];
        k[b][d] = base[off + E_];
        v[b][d] = base[off + 2*E_];
    }
    __syncthreads();

    for (int i = t; i < B_*B_; i += 256) {
        int l = i / B_, m = i % B_;
        float acc = 0.0f;
        #pragma unroll
        for (int d = 0; d < DH_; d++) acc += q[l][d] * k[m][d];
        sc[l][m] = acc * 0.125f;
    }
    __syncthreads();

    int warp = t >> 5, lane = t & 31;
    for (int l = warp; l < B_; l += 8) {
        float val = sc[l][lane];
        float mx = val;
        #pragma unroll
        for (int o = 16; o; o >>= 1) mx = fmaxf(mx, __shfl_xor_sync(0xffffffffu, mx, o));
        float e = expf(val - mx);
        float sum = e;
        #pragma unroll
        for (int o = 16; o; o >>= 1) sum += __shfl_xor_sync(0xffffffffu, sum, o);
        sc[l][lane] = e / sum;
    }
    __syncthreads();

    for (int i = t; i < B_*DH_; i += 256) {
        int l = i / DH_, d = i % DH_;
        float acc = 0.0f;
        #pragma unroll
        for (int m = 0; m < B_; m++) acc += sc[l][m] * v[m][d];
        CTX[((size_t)l * S_ + s) * E_ + (size_t)h * DH_ + d] = acc;
    }
}

// ---------------- residual add + layernorm ----------------
__global__ void add_ln_kernel(float* __restrict__ x, const float* __restrict__ y,
                              const float* __restrict__ w, const float* __restrict__ b) {
    long long row = blockIdx.x;
    __shared__ float red[256];
    int t = threadIdx.x;
    float v0 = x[row*E_ + t]       + y[row*E_ + t];
    float v1 = x[row*E_ + 256 + t] + y[row*E_ + 256 + t];
    red[t] = v0 + v1;
    __syncthreads();
    #pragma unroll
    for (int s2 = 128; s2 > 0; s2 >>= 1) { if (t < s2) red[t] += red[t + s2]; __syncthreads(); }
    float mean = red[0] * (1.0f / E_);
    __syncthreads();
    float d0 = v0 - mean, d1 = v1 - mean;
    red[t] = d0*d0 + d1*d1;
    __syncthreads();
    #pragma unroll
    for (int s2 = 128; s2 > 0; s2 >>= 1) { if (t < s2) red[t] += red[t + s2]; __syncthreads(); }
    float rstd = rsqrtf(red[0] * (1.0f / E_) + 1e-5f);
    x[row*E_ + t]       = d0 * rstd * w[t]       + b[t];
    x[row*E_ + 256 + t] = d1 * rstd * w[t + 256] + b[t + 256];
}

// ---------------- discriminator head ----------------
__global__ void disc_kernel(const float* __restrict__ bert,
                            const float* __restrict__ posf,
                            const float* __restrict__ wd,
                            const float* __restrict__ bd,
                            float* __restrict__ out, int ntok) {
    int n = (blockIdx.x * blockDim.x + threadIdx.x) >> 5;
    int lane = threadIdx.x & 31;
    if (n >= ntok) return;
    float acc = 0.0f;
    const float* br = bert + (size_t)n * F_;
    const float* pr = posf + (size_t)n * F_;
    for (int i = lane; i < F_; i += 32) acc += br[i] * wd[i];
    for (int i = lane; i < F_; i += 32) acc += pr[i] * wd[F_ + i];
    #pragma unroll
    for (int o = 16; o; o >>= 1) acc += __shfl_xor_sync(0xffffffffu, acc, o);
    if (lane == 0) out[n] = 1.0f / (1.0f + expf(-(acc + bd[0])));
}

// ---------------- host orchestration ----------------
static inline int cdiv(int a, int b) { return (a + b - 1) / b; }

extern "C" void kernel_launch(void* const* d_in, const int* in_sizes, int n_in,
                              void* d_out, int out_size) {
    const int*   pos1  = (const int*)d_in[0];
    const int*   pos2  = (const int*)d_in[1];
    const float* bert  = (const float*)d_in[2];
    const float* fbase = (const float*)d_in[3];
    const float* emb   = (const float*)d_in[4];
    const float* wqkv  = (const float*)d_in[5];
    const float* bqkv  = (const float*)d_in[6];
    const float* wo    = (const float*)d_in[7];
    const float* bo    = (const float*)d_in[8];
    const float* ln1w  = (const float*)d_in[9];
    const float* ln1b  = (const float*)d_in[10];
    const float* ln2w  = (const float*)d_in[11];
    const float* ln2b  = (const float*)d_in[12];
    const float* w1    = (const float*)d_in[13];
    const float* b1    = (const float*)d_in[14];
    const float* w2    = (const float*)d_in[15];
    const float* b2    = (const float*)d_in[16];
    const float* wm    = (const float*)d_in[17];
    const float* wd    = (const float*)d_in[18];
    const float* bd    = (const float*)d_in[19];
    float* out = (float*)d_out;

    float *PE, *X, *Y, *CTX, *QKV, *H, *POSF; int* SPAN;
    cudaGetSymbolAddress((void**)&PE,   d_PE);
    cudaGetSymbolAddress((void**)&SPAN, d_SPAN);
    cudaGetSymbolAddress((void**)&X,    d_X);
    cudaGetSymbolAddress((void**)&Y,    d_Y);
    cudaGetSymbolAddress((void**)&CTX,  d_CTX);
    cudaGetSymbolAddress((void**)&QKV,  d_QKV);
    cudaGetSymbolAddress((void**)&H,    d_H);
    cudaGetSymbolAddress((void**)&POSF, d_POSF);

    cudaFuncSetAttribute(gemm_tc, cudaFuncAttributeMaxDynamicSharedMemorySize, SMEM_GEMM);

    // ---- preamble ----
    pe_kernel<<<cdiv(M_*E_, 256), 256>>>(PE);
    span_kernel<<<B_, M_>>>(pos1, SPAN);
    build_x_kernel<<<NTOK, 256>>>(pos2, fbase, emb, SPAN, PE, X);

    const int MY = cdiv(NTOK, 128);

    for (int l = 0; l < 2; l++) {
        const float* Wqkv = wqkv + (size_t)l * 3*E_ * E_;
        const float* Bqkv = bqkv + (size_t)l * 3*E_;
        const float* Wo   = wo   + (size_t)l * E_ * E_;
        const float* Bo   = bo   + (size_t)l * E_;
        const float* W1   = w1   + (size_t)l * DFF_ * E_;
        const float* B1   = b1   + (size_t)l * DFF_;
        const float* W2   = w2   + (size_t)l * E_ * DFF_;
        const float* B2   = b2   + (size_t)l * E_;

        { dim3 g(3*E_/128, MY);
          gemm_tc<<<g, 256, SMEM_GEMM>>>(X, Wqkv, QKV, NTOK, 3*E_, E_, Bqkv, 0); }

        attn_kernel<<<S_*NHEAD_, 256>>>(QKV, CTX);

        { dim3 g(E_/128, MY);
          gemm_tc<<<g, 256, SMEM_GEMM>>>(CTX, Wo, Y, NTOK, E_, E_, Bo, 0); }

        add_ln_kernel<<<NTOK, 256>>>(X, Y, ln1w + l*E_, ln1b + l*E_);

        { dim3 g(DFF_/128, MY);
          gemm_tc<<<g, 256, SMEM_GEMM>>>(X, W1, H, NTOK, DFF_, E_, B1, 1); }

        { dim3 g(E_/128, MY);
          gemm_tc<<<g, 256, SMEM_GEMM>>>(H, W2, Y, NTOK, E_, DFF_, B2, 0); }

        add_ln_kernel<<<NTOK, 256>>>(X, Y, ln2w + l*E_, ln2b + l*E_);
    }

    { dim3 g(F_/128, MY);
      gemm_tc<<<g, 256, SMEM_GEMM>>>(X, wm, POSF, NTOK, F_, E_, nullptr, 2); }

    disc_kernel<<<cdiv(NTOK*32, 256), 256>>>(bert, POSF, wd, bd, out, NTOK);
}

// round 5
// speedup vs baseline: 4.4296x; 1.2355x over previous
#include <cuda_runtime.h>
#include <cuda_bf16.h>
#include <math.h>
#include <stdint.h>

// ---------------- problem constants ----------------
#define B_    32
#define M_    512
#define E_    512
#define S_    513
#define NTOK  (B_*S_)          // 16416
#define NHEAD_ 8
#define DH_   64
#define DFF_  2048
#define F_    768

// ---------------- fp32 scratch ----------------
__device__ float d_PE[M_*E_];
__device__ int   d_SPAN[B_*M_];
__device__ float d_X  [(size_t)NTOK*E_];
__device__ float d_Y  [(size_t)NTOK*E_];
__device__ float d_QKV[(size_t)NTOK*3*E_];
__device__ float d_POSF[(size_t)NTOK*F_];

// ---------------- bf16 hi/lo split operand buffers ----------------
__device__ __align__(16) __nv_bfloat16 d_Xh [(size_t)NTOK*E_];
__device__ __align__(16) __nv_bfloat16 d_Xl [(size_t)NTOK*E_];
__device__ __align__(16) __nv_bfloat16 d_CXh[(size_t)NTOK*E_];
__device__ __align__(16) __nv_bfloat16 d_CXl[(size_t)NTOK*E_];
__device__ __align__(16) __nv_bfloat16 d_Hh [(size_t)NTOK*DFF_];
__device__ __align__(16) __nv_bfloat16 d_Hl [(size_t)NTOK*DFF_];
__device__ __align__(16) __nv_bfloat16 d_WQh[(size_t)2*3*E_*E_];
__device__ __align__(16) __nv_bfloat16 d_WQl[(size_t)2*3*E_*E_];
__device__ __align__(16) __nv_bfloat16 d_WOh[(size_t)2*E_*E_];
__device__ __align__(16) __nv_bfloat16 d_WOl[(size_t)2*E_*E_];
__device__ __align__(16) __nv_bfloat16 d_W1h[(size_t)2*DFF_*E_];
__device__ __align__(16) __nv_bfloat16 d_W1l[(size_t)2*DFF_*E_];
__device__ __align__(16) __nv_bfloat16 d_W2h[(size_t)2*E_*DFF_];
__device__ __align__(16) __nv_bfloat16 d_W2l[(size_t)2*E_*DFF_];
__device__ __align__(16) __nv_bfloat16 d_WMh[(size_t)F_*E_];
__device__ __align__(16) __nv_bfloat16 d_WMl[(size_t)F_*E_];

// ================= bf16-split tensor-core GEMM =================
// C[M,N] = act( A[M,K] @ B[N,K]^T + bias ),  A,B pre-split bf16 hi/lo,
// fp32 accum; D = Ah*Bh + Ah*Bl + Al*Bh.
#define BM 128
#define BN 256
#define BK 32
#define PADB 80                  // smem row stride in bytes (40 bf16)
#define A_ARR (128*PADB)         // 10240
#define B_ARR (256*PADB)         // 20480
#define STAGE (2*A_ARR + 2*B_ARR)// 61440
#define SMEM_GEMM (3*STAGE)      // 184320

__device__ __forceinline__ uint32_t smem_u32(const void* p) {
    uint32_t a;
    asm("{ .reg .u64 t; cvta.to.shared.u64 t, %1; cvt.u32.u64 %0, t; }"
        : "=r"(a) : "l"(p));
    return a;
}
__device__ __forceinline__ void ldsm4(uint32_t* r, uint32_t addr) {
    asm volatile("ldmatrix.sync.aligned.m8n8.x4.shared.b16 {%0,%1,%2,%3}, [%4];"
        : "=r"(r[0]), "=r"(r[1]), "=r"(r[2]), "=r"(r[3]) : "r"(addr));
}
__device__ __forceinline__ void mma16816(float* c, const uint32_t* a, const uint32_t* b) {
    asm volatile(
        "mma.sync.aligned.m16n8k16.row.col.f32.bf16.bf16.f32 "
        "{%0,%1,%2,%3}, {%4,%5,%6,%7}, {%8,%9}, {%0,%1,%2,%3};"
        : "+f"(c[0]), "+f"(c[1]), "+f"(c[2]), "+f"(c[3])
        : "r"(a[0]), "r"(a[1]), "r"(a[2]), "r"(a[3]), "r"(b[0]), "r"(b[1]));
}
__device__ __forceinline__ void cpa16(uint32_t dst, const void* src, int srcsize) {
    asm volatile("cp.async.cg.shared.global [%0], [%1], 16, %2;"
                 :: "r"(dst), "l"(src), "r"(srcsize));
}

__device__ __forceinline__ void load_stage(
    uint32_t st,
    const __nv_bfloat16* __restrict__ Ah, const __nv_bfloat16* __restrict__ Al,
    const __nv_bfloat16* __restrict__ Bh, const __nv_bfloat16* __restrict__ Bl,
    int tile_m, int tile_n, int Mdim, int Kdim, int kc, int tid)
{
    const int k0 = kc * 32;
    #pragma unroll
    for (int i = 0; i < 4; i++) {           // A: 2 arrays x 128 rows x 4 chunks
        int id  = tid + 256*i;
        int arr = id >> 9, rem = id & 511;
        int row = rem >> 2, c = rem & 3;
        const __nv_bfloat16* src =
            (arr ? Al : Ah) + (size_t)(tile_m + row) * Kdim + k0 + c*8;
        cpa16(st + arr*A_ARR + row*PADB + c*16, src,
              (tile_m + row) < Mdim ? 16 : 0);
    }
    #pragma unroll
    for (int i = 0; i < 8; i++) {           // B: 2 arrays x 256 rows x 4 chunks
        int id  = tid + 256*i;
        int arr = id >> 10, rem = id & 1023;
        int row = rem >> 2, c = rem & 3;
        const __nv_bfloat16* src =
            (arr ? Bl : Bh) + (size_t)(tile_n + row) * Kdim + k0 + c*8;
        cpa16(st + 2*A_ARR + arr*B_ARR + row*PADB + c*16, src, 16);
    }
    asm volatile("cp.async.commit_group;" ::: "memory");
}

__device__ __forceinline__ void split2(float v0, float v1,
                                       __nv_bfloat162& h, __nv_bfloat162& l) {
    h.x = __float2bfloat16_rn(v0); h.y = __float2bfloat16_rn(v1);
    l.x = __float2bfloat16_rn(v0 - __bfloat162float(h.x));
    l.y = __float2bfloat16_rn(v1 - __bfloat162float(h.y));
}

__global__ __launch_bounds__(256)
void gemm_tc(const __nv_bfloat16* __restrict__ Ah, const __nv_bfloat16* __restrict__ Al,
             const __nv_bfloat16* __restrict__ Bh, const __nv_bfloat16* __restrict__ Bl,
             float* __restrict__ Cf,
             __nv_bfloat16* __restrict__ Ch, __nv_bfloat16* __restrict__ Cl,
             int Mdim, int Ndim, int Kdim,
             const float* __restrict__ bias, int act)
{
    extern __shared__ __align__(16) char smem[];
    const uint32_t sb = smem_u32(smem);
    const int tid    = threadIdx.x;
    const int tile_m = blockIdx.y * BM;
    const int tile_n = blockIdx.x * BN;
    const int warp = tid >> 5, lane = tid & 31;
    const int wm2 = warp >> 2, wn4 = warp & 3;    // 2(M) x 4(N) warp grid, 64x64 tiles

    float acc[4][8][4];
    #pragma unroll
    for (int a = 0; a < 4; a++)
        #pragma unroll
        for (int b = 0; b < 8; b++)
            #pragma unroll
            for (int q = 0; q < 4; q++) acc[a][b][q] = 0.0f;

    const int nst = Kdim >> 5;
    load_stage(sb,         Ah, Al, Bh, Bl, tile_m, tile_n, Mdim, Kdim, 0, tid);
    load_stage(sb + STAGE, Ah, Al, Bh, Bl, tile_m, tile_n, Mdim, Kdim, 1, tid);

    // ldmatrix lane offsets
    const uint32_t a_off = (uint32_t)(wm2*64 + (lane & 7) + ((lane >> 3) & 1) * 8) * PADB
                         + ((lane >> 4) * 16);
    const uint32_t b_off = (uint32_t)(wn4*64 + (lane & 7) + ((lane >> 4) & 1) * 8) * PADB
                         + (((lane >> 3) & 1) * 16);

    for (int s = 0; s < nst; s++) {
        if (s + 1 < nst) asm volatile("cp.async.wait_group 1;" ::: "memory");
        else             asm volatile("cp.async.wait_group 0;" ::: "memory");
        __syncthreads();
        if (s + 2 < nst)
            load_stage(sb + ((s + 2) % 3) * STAGE, Ah, Al, Bh, Bl,
                       tile_m, tile_n, Mdim, Kdim, s + 2, tid);
        const uint32_t st = sb + (s % 3) * STAGE;

        #pragma unroll
        for (int ks = 0; ks < 2; ks++) {
            uint32_t ah[4][4], al[4][4], bh[8][2], bl[8][2];
            #pragma unroll
            for (int mi = 0; mi < 4; mi++) {
                uint32_t ad = st + a_off + mi * (16 * PADB) + ks * 32;
                ldsm4(ah[mi], ad);
                ldsm4(al[mi], ad + A_ARR);
            }
            #pragma unroll
            for (int p = 0; p < 4; p++) {
                uint32_t bd = st + 2*A_ARR + b_off + p * (16 * PADB) + ks * 32;
                uint32_t r[4];
                ldsm4(r, bd);
                bh[2*p][0] = r[0]; bh[2*p][1] = r[1];
                bh[2*p+1][0] = r[2]; bh[2*p+1][1] = r[3];
                ldsm4(r, bd + B_ARR);
                bl[2*p][0] = r[0]; bl[2*p][1] = r[1];
                bl[2*p+1][0] = r[2]; bl[2*p+1][1] = r[3];
            }
            #pragma unroll
            for (int mi = 0; mi < 4; mi++)
                #pragma unroll
                for (int ni = 0; ni < 8; ni++) {
                    mma16816(acc[mi][ni], ah[mi], bh[ni]);
                    mma16816(acc[mi][ni], ah[mi], bl[ni]);
                    mma16816(acc[mi][ni], al[mi], bh[ni]);
                }
        }
    }

    // ---- epilogue ----
    const int er = lane >> 2;
    const int ec = (lane & 3) * 2;
    #pragma unroll
    for (int mi = 0; mi < 4; mi++) {
        const int gm0 = tile_m + wm2*64 + mi*16 + er;
        #pragma unroll
        for (int ni = 0; ni < 8; ni++) {
            const int gn = tile_n + wn4*64 + ni*8 + ec;
            float bx = 0.f, by = 0.f;
            if (bias) { float2 bb = *reinterpret_cast<const float2*>(bias + gn);
                        bx = bb.x; by = bb.y; }
            float v0 = acc[mi][ni][0] + bx, v1 = acc[mi][ni][1] + by;
            float v2 = acc[mi][ni][2] + bx, v3 = acc[mi][ni][3] + by;
            if (act == 1) {
                v0 = fmaxf(v0, 0.f); v1 = fmaxf(v1, 0.f);
                v2 = fmaxf(v2, 0.f); v3 = fmaxf(v3, 0.f);
            } else if (act == 2) {
                v0 = tanhf(v0); v1 = tanhf(v1); v2 = tanhf(v2); v3 = tanhf(v3);
            }
            if (Cf) {
                if (gm0 < Mdim)
                    *reinterpret_cast<float2*>(Cf + (size_t)gm0 * Ndim + gn) = make_float2(v0, v1);
                if (gm0 + 8 < Mdim)
                    *reinterpret_cast<float2*>(Cf + (size_t)(gm0+8) * Ndim + gn) = make_float2(v2, v3);
            } else {
                __nv_bfloat162 h, l;
                if (gm0 < Mdim) {
                    size_t off = (size_t)gm0 * Ndim + gn;
                    split2(v0, v1, h, l);
                    *reinterpret_cast<__nv_bfloat162*>(Ch + off) = h;
                    *reinterpret_cast<__nv_bfloat162*>(Cl + off) = l;
                }
                if (gm0 + 8 < Mdim) {
                    size_t off = (size_t)(gm0+8) * Ndim + gn;
                    split2(v2, v3, h, l);
                    *reinterpret_cast<__nv_bfloat162*>(Ch + off) = h;
                    *reinterpret_cast<__nv_bfloat162*>(Cl + off) = l;
                }
            }
        }
    }
}

// ---------------- fp32 -> bf16 hi/lo split (weights) ----------------
__global__ void split_kernel(const float* __restrict__ in,
                             __nv_bfloat16* __restrict__ oh,
                             __nv_bfloat16* __restrict__ ol, int n4) {
    int i = blockIdx.x * blockDim.x + threadIdx.x;
    if (i >= n4) return;
    float4 v = *reinterpret_cast<const float4*>(in + (size_t)i * 4);
    __nv_bfloat162 h0, l0, h1, l1;
    split2(v.x, v.y, h0, l0);
    split2(v.z, v.w, h1, l1);
    uint2 hh, ll;
    hh.x = *reinterpret_cast<uint32_t*>(&h0); hh.y = *reinterpret_cast<uint32_t*>(&h1);
    ll.x = *reinterpret_cast<uint32_t*>(&l0); ll.y = *reinterpret_cast<uint32_t*>(&l1);
    *reinterpret_cast<uint2*>(oh + (size_t)i * 4) = hh;
    *reinterpret_cast<uint2*>(ol + (size_t)i * 4) = ll;
}

// ---------------- PE table ----------------
__global__ void pe_kernel(float* pe) {
    int idx = blockIdx.x * blockDim.x + threadIdx.x;
    if (idx >= M_ * E_) return;
    int pos = idx / E_, i = idx % E_;
    double e2  = (double)((i / 2) * 2);
    double ang = (double)pos / pow(10000.0, e2 / (double)E_);
    pe[idx] = (float)((i % 2 == 0) ? sin(ang) : cos(ang));
}

// ---------------- span id ----------------
__global__ void span_kernel(const int* __restrict__ pos1, int* __restrict__ span) {
    int b = blockIdx.x;
    int j = threadIdx.x;
    __shared__ int firstZero;
    span[b*M_ + j] = -1;
    if (j == 0) firstZero = M_;
    __syncthreads();
    int endv = pos1[((size_t)b*M_ + j)*2 + 1];
    if (endv == 0) atomicMin(&firstZero, j);
    __syncthreads();
    if (j < firstZero) {
        int st = pos1[((size_t)b*M_ + j)*2];
        int en = endv; if (en > M_) en = M_;
        for (int k = st; k < en; k++)
            atomicMax(&span[b*M_ + k], j);
    }
}

// ---------------- build x [B,S,E] + split ----------------
__global__ void build_x_kernel(const int* __restrict__ pos2,
                               const float* __restrict__ fbase,
                               const float* __restrict__ emb,
                               const int* __restrict__ span,
                               const float* __restrict__ pe,
                               float* __restrict__ X,
                               __nv_bfloat16* __restrict__ Xh,
                               __nv_bfloat16* __restrict__ Xl) {
    int row = blockIdx.x;
    int b = row / S_, s = row % S_;
    size_t base = (size_t)row * E_;
    int e = threadIdx.x;                 // 512 threads = E
    float val;
    if (s == 0) {
        val = emb[(size_t)1*E_ + e];
    } else {
        int k = s - 1;
        int sid = span[b*M_ + k];
        if (sid >= 0) {
            int p = pos2[b*M_ + sid];
            val = (p == 0 ? 0.0f : emb[(size_t)p*E_ + e]) + pe[(size_t)sid*E_ + e];
        } else {
            val = fbase[((size_t)b*M_ + k)*E_ + e];
        }
    }
    X[base + e] = val;
    __nv_bfloat16 h = __float2bfloat16_rn(val);
    Xh[base + e] = h;
    Xl[base + e] = __float2bfloat16_rn(val - __bfloat162float(h));
}

// ---------------- fused attention over the B axis (split output) ----------------
__global__ void attn_kernel(const float* __restrict__ QKV,
                            __nv_bfloat16* __restrict__ CXh,
                            __nv_bfloat16* __restrict__ CXl) {
    int z = blockIdx.x;
    int s = z / NHEAD_, h = z % NHEAD_;
    __shared__ float q[B_][DH_];
    __shared__ float k[B_][DH_];
    __shared__ float v[B_][DH_];
    __shared__ float sc[B_][B_ + 1];

    const float* base = QKV + (size_t)s * 3*E_ + (size_t)h * DH_;
    int t = threadIdx.x;

    for (int i = t; i < B_*DH_; i += 256) {
        int b = i / DH_, d = i % DH_;
        size_t off = (size_t)b * S_ * 3*E_ + d;
        q[b][d] = base[off];
        k[b][d] = base[off + E_];
        v[b][d] = base[off + 2*E_];
    }
    __syncthreads();

    for (int i = t; i < B_*B_; i += 256) {
        int l = i / B_, m = i % B_;
        float acc = 0.0f;
        #pragma unroll
        for (int d = 0; d < DH_; d++) acc += q[l][d] * k[m][d];
        sc[l][m] = acc * 0.125f;
    }
    __syncthreads();

    int warp = t >> 5, lane = t & 31;
    for (int l = warp; l < B_; l += 8) {
        float val = sc[l][lane];
        float mx = val;
        #pragma unroll
        for (int o = 16; o; o >>= 1) mx = fmaxf(mx, __shfl_xor_sync(0xffffffffu, mx, o));
        float e = expf(val - mx);
        float sum = e;
        #pragma unroll
        for (int o = 16; o; o >>= 1) sum += __shfl_xor_sync(0xffffffffu, sum, o);
        sc[l][lane] = e / sum;
    }
    __syncthreads();

    for (int i = t; i < B_*DH_; i += 256) {
        int l = i / DH_, d = i % DH_;
        float acc = 0.0f;
        #pragma unroll
        for (int m = 0; m < B_; m++) acc += sc[l][m] * v[m][d];
        size_t off = ((size_t)l * S_ + s) * E_ + (size_t)h * DH_ + d;
        __nv_bfloat16 hh = __float2bfloat16_rn(acc);
        CXh[off] = hh;
        CXl[off] = __float2bfloat16_rn(acc - __bfloat162float(hh));
    }
}

// ---------------- residual add + layernorm (+ split) ----------------
__global__ void add_ln_kernel(float* __restrict__ x, const float* __restrict__ y,
                              const float* __restrict__ w, const float* __restrict__ b,
                              __nv_bfloat16* __restrict__ Xh,
                              __nv_bfloat16* __restrict__ Xl) {
    long long row = blockIdx.x;
    __shared__ float red[256];
    int t = threadIdx.x;
    float v0 = x[row*E_ + t]       + y[row*E_ + t];
    float v1 = x[row*E_ + 256 + t] + y[row*E_ + 256 + t];
    red[t] = v0 + v1;
    __syncthreads();
    #pragma unroll
    for (int s2 = 128; s2 > 0; s2 >>= 1) { if (t < s2) red[t] += red[t + s2]; __syncthreads(); }
    float mean = red[0] * (1.0f / E_);
    __syncthreads();
    float d0 = v0 - mean, d1 = v1 - mean;
    red[t] = d0*d0 + d1*d1;
    __syncthreads();
    #pragma unroll
    for (int s2 = 128; s2 > 0; s2 >>= 1) { if (t < s2) red[t] += red[t + s2]; __syncthreads(); }
    float rstd = rsqrtf(red[0] * (1.0f / E_) + 1e-5f);
    float o0 = d0 * rstd * w[t]       + b[t];
    float o1 = d1 * rstd * w[t + 256] + b[t + 256];
    x[row*E_ + t]       = o0;
    x[row*E_ + 256 + t] = o1;
    __nv_bfloat16 h0 = __float2bfloat16_rn(o0);
    __nv_bfloat16 h1 = __float2bfloat16_rn(o1);
    Xh[row*E_ + t]       = h0;
    Xh[row*E_ + 256 + t] = h1;
    Xl[row*E_ + t]       = __float2bfloat16_rn(o0 - __bfloat162float(h0));
    Xl[row*E_ + 256 + t] = __float2bfloat16_rn(o1 - __bfloat162float(h1));
}

// ---------------- discriminator head ----------------
__global__ void disc_kernel(const float* __restrict__ bert,
                            const float* __restrict__ posf,
                            const float* __restrict__ wd,
                            const float* __restrict__ bd,
                            float* __restrict__ out, int ntok) {
    int n = (blockIdx.x * blockDim.x + threadIdx.x) >> 5;
    int lane = threadIdx.x & 31;
    if (n >= ntok) return;
    float acc = 0.0f;
    const float* br = bert + (size_t)n * F_;
    const float* pr = posf + (size_t)n * F_;
    for (int i = lane; i < F_; i += 32) acc += br[i] * wd[i];
    for (int i = lane; i < F_; i += 32) acc += pr[i] * wd[F_ + i];
    #pragma unroll
    for (int o = 16; o; o >>= 1) acc += __shfl_xor_sync(0xffffffffu, acc, o);
    if (lane == 0) out[n] = 1.0f / (1.0f + expf(-(acc + bd[0])));
}

// ---------------- host orchestration ----------------
static inline int cdiv(int a, int b) { return (a + b - 1) / b; }

extern "C" void kernel_launch(void* const* d_in, const int* in_sizes, int n_in,
                              void* d_out, int out_size) {
    const int*   pos1  = (const int*)d_in[0];
    const int*   pos2  = (const int*)d_in[1];
    const float* bert  = (const float*)d_in[2];
    const float* fbase = (const float*)d_in[3];
    const float* emb   = (const float*)d_in[4];
    const float* wqkv  = (const float*)d_in[5];
    const float* bqkv  = (const float*)d_in[6];
    const float* wo    = (const float*)d_in[7];
    const float* bo    = (const float*)d_in[8];
    const float* ln1w  = (const float*)d_in[9];
    const float* ln1b  = (const float*)d_in[10];
    const float* ln2w  = (const float*)d_in[11];
    const float* ln2b  = (const float*)d_in[12];
    const float* w1    = (const float*)d_in[13];
    const float* b1    = (const float*)d_in[14];
    const float* w2    = (const float*)d_in[15];
    const float* b2    = (const float*)d_in[16];
    const float* wm    = (const float*)d_in[17];
    const float* wd    = (const float*)d_in[18];
    const float* bd    = (const float*)d_in[19];
    float* out = (float*)d_out;

    float *PE, *X, *Y, *QKV, *POSF; int* SPAN;
    __nv_bfloat16 *Xh, *Xl, *CXh, *CXl, *Hh, *Hl;
    __nv_bfloat16 *WQh, *WQl, *WOh, *WOl, *W1h, *W1l, *W2h, *W2l, *WMh, *WMl;
    cudaGetSymbolAddress((void**)&PE,   d_PE);
    cudaGetSymbolAddress((void**)&SPAN, d_SPAN);
    cudaGetSymbolAddress((void**)&X,    d_X);
    cudaGetSymbolAddress((void**)&Y,    d_Y);
    cudaGetSymbolAddress((void**)&QKV,  d_QKV);
    cudaGetSymbolAddress((void**)&POSF, d_POSF);
    cudaGetSymbolAddress((void**)&Xh,  d_Xh);  cudaGetSymbolAddress((void**)&Xl,  d_Xl);
    cudaGetSymbolAddress((void**)&CXh, d_CXh); cudaGetSymbolAddress((void**)&CXl, d_CXl);
    cudaGetSymbolAddress((void**)&Hh,  d_Hh);  cudaGetSymbolAddress((void**)&Hl,  d_Hl);
    cudaGetSymbolAddress((void**)&WQh, d_WQh); cudaGetSymbolAddress((void**)&WQl, d_WQl);
    cudaGetSymbolAddress((void**)&WOh, d_WOh); cudaGetSymbolAddress((void**)&WOl, d_WOl);
    cudaGetSymbolAddress((void**)&W1h, d_W1h); cudaGetSymbolAddress((void**)&W1l, d_W1l);
    cudaGetSymbolAddress((void**)&W2h, d_W2h); cudaGetSymbolAddress((void**)&W2l, d_W2l);
    cudaGetSymbolAddress((void**)&WMh, d_WMh); cudaGetSymbolAddress((void**)&WMl, d_WMl);

    cudaFuncSetAttribute(gemm_tc, cudaFuncAttributeMaxDynamicSharedMemorySize, SMEM_GEMM);

    // ---- preamble ----
    pe_kernel<<<cdiv(M_*E_, 256), 256>>>(PE);
    span_kernel<<<B_, M_>>>(pos1, SPAN);
    build_x_kernel<<<NTOK, 512>>>(pos2, fbase, emb, SPAN, PE, X, Xh, Xl);

    // ---- weight splits ----
    { int n4 = 2*3*E_*E_/4; split_kernel<<<cdiv(n4,256),256>>>(wqkv, WQh, WQl, n4); }
    { int n4 = 2*E_*E_/4;   split_kernel<<<cdiv(n4,256),256>>>(wo,   WOh, WOl, n4); }
    { int n4 = 2*DFF_*E_/4; split_kernel<<<cdiv(n4,256),256>>>(w1,   W1h, W1l, n4); }
    { int n4 = 2*E_*DFF_/4; split_kernel<<<cdiv(n4,256),256>>>(w2,   W2h, W2l, n4); }
    { int n4 = F_*E_/4;     split_kernel<<<cdiv(n4,256),256>>>(wm,   WMh, WMl, n4); }

    const int MY = cdiv(NTOK, BM);   // 129

    for (int l = 0; l < 2; l++) {
        const size_t oq = (size_t)l * 3*E_ * E_;
        const size_t oo = (size_t)l * E_ * E_;
        const size_t o1 = (size_t)l * DFF_ * E_;
        const size_t o2 = (size_t)l * E_ * DFF_;

        { dim3 g(3*E_/BN, MY);   // QKV
          gemm_tc<<<g, 256, SMEM_GEMM>>>(Xh, Xl, WQh+oq, WQl+oq,
              QKV, nullptr, nullptr, NTOK, 3*E_, E_, bqkv + l*3*E_, 0); }

        attn_kernel<<<S_*NHEAD_, 256>>>(QKV, CXh, CXl);

        { dim3 g(E_/BN, MY);     // Wo
          gemm_tc<<<g, 256, SMEM_GEMM>>>(CXh, CXl, WOh+oo, WOl+oo,
              Y, nullptr, nullptr, NTOK, E_, E_, bo + l*E_, 0); }

        add_ln_kernel<<<NTOK, 256>>>(X, Y, ln1w + l*E_, ln1b + l*E_, Xh, Xl);

        { dim3 g(DFF_/BN, MY);   // FFN1 -> split H
          gemm_tc<<<g, 256, SMEM_GEMM>>>(Xh, Xl, W1h+o1, W1l+o1,
              nullptr, Hh, Hl, NTOK, DFF_, E_, b1 + l*DFF_, 1); }

        { dim3 g(E_/BN, MY);     // FFN2
          gemm_tc<<<g, 256, SMEM_GEMM>>>(Hh, Hl, W2h+o2, W2l+o2,
              Y, nullptr, nullptr, NTOK, E_, DFF_, b2 + l*E_, 0); }

        add_ln_kernel<<<NTOK, 256>>>(X, Y, ln2w + l*E_, ln2b + l*E_, Xh, Xl);
    }

    { dim3 g(F_/BN, MY);         // pos_feature = tanh(X @ wm^T)
      gemm_tc<<<g, 256, SMEM_GEMM>>>(Xh, Xl, WMh, WMl,
          POSF, nullptr, nullptr, NTOK, F_, E_, nullptr, 2); }

    disc_kernel<<<cdiv(NTOK*32, 256), 256>>>(bert, POSF, wd, bd, out, NTOK);
}

// round 6
// speedup vs baseline: 4.4304x; 1.0002x over previous
#include <cuda_runtime.h>
#include <cuda_bf16.h>
#include <math.h>
#include <stdint.h>

// ---------------- problem constants ----------------
#define B_    32
#define M_    512
#define E_    512
#define S_    513
#define NTOK  (B_*S_)          // 16416
#define NHEAD_ 8
#define DH_   64
#define DFF_  2048
#define F_    768

// ---------------- fp32 scratch ----------------
__device__ float d_PE[M_*E_];
__device__ int   d_SPAN[B_*M_];
__device__ float d_X  [(size_t)NTOK*E_];
__device__ float d_Y  [(size_t)NTOK*E_];
__device__ float d_QKV[(size_t)NTOK*3*E_];
__device__ float d_POSF[(size_t)NTOK*F_];

// ---------------- bf16 hi/lo split operand buffers ----------------
__device__ __align__(16) __nv_bfloat16 d_Xh [(size_t)NTOK*E_];
__device__ __align__(16) __nv_bfloat16 d_Xl [(size_t)NTOK*E_];
__device__ __align__(16) __nv_bfloat16 d_CXh[(size_t)NTOK*E_];
__device__ __align__(16) __nv_bfloat16 d_CXl[(size_t)NTOK*E_];
__device__ __align__(16) __nv_bfloat16 d_Hh [(size_t)NTOK*DFF_];
__device__ __align__(16) __nv_bfloat16 d_Hl [(size_t)NTOK*DFF_];
__device__ __align__(16) __nv_bfloat16 d_WQh[(size_t)2*3*E_*E_];
__device__ __align__(16) __nv_bfloat16 d_WQl[(size_t)2*3*E_*E_];
__device__ __align__(16) __nv_bfloat16 d_WOh[(size_t)2*E_*E_];
__device__ __align__(16) __nv_bfloat16 d_WOl[(size_t)2*E_*E_];
__device__ __align__(16) __nv_bfloat16 d_W1h[(size_t)2*DFF_*E_];
__device__ __align__(16) __nv_bfloat16 d_W1l[(size_t)2*DFF_*E_];
__device__ __align__(16) __nv_bfloat16 d_W2h[(size_t)2*E_*DFF_];
__device__ __align__(16) __nv_bfloat16 d_W2l[(size_t)2*E_*DFF_];
__device__ __align__(16) __nv_bfloat16 d_WMh[(size_t)F_*E_];
__device__ __align__(16) __nv_bfloat16 d_WMl[(size_t)F_*E_];

// ================= bf16-split tensor-core GEMM =================
#define BM 128
#define BN 256
#define BK 32
#define PADB 80
#define A_ARR (128*PADB)
#define B_ARR (256*PADB)
#define STAGE (2*A_ARR + 2*B_ARR)
#define SMEM_GEMM (3*STAGE)

__device__ __forceinline__ uint32_t smem_u32(const void* p) {
    uint32_t a;
    asm("{ .reg .u64 t; cvta.to.shared.u64 t, %1; cvt.u32.u64 %0, t; }"
        : "=r"(a) : "l"(p));
    return a;
}
__device__ __forceinline__ void ldsm4(uint32_t* r, uint32_t addr) {
    asm volatile("ldmatrix.sync.aligned.m8n8.x4.shared.b16 {%0,%1,%2,%3}, [%4];"
        : "=r"(r[0]), "=r"(r[1]), "=r"(r[2]), "=r"(r[3]) : "r"(addr));
}
__device__ __forceinline__ void mma16816(float* c, const uint32_t* a, const uint32_t* b) {
    asm volatile(
        "mma.sync.aligned.m16n8k16.row.col.f32.bf16.bf16.f32 "
        "{%0,%1,%2,%3}, {%4,%5,%6,%7}, {%8,%9}, {%0,%1,%2,%3};"
        : "+f"(c[0]), "+f"(c[1]), "+f"(c[2]), "+f"(c[3])
        : "r"(a[0]), "r"(a[1]), "r"(a[2]), "r"(a[3]), "r"(b[0]), "r"(b[1]));
}
__device__ __forceinline__ void cpa16(uint32_t dst, const void* src, int srcsize) {
    asm volatile("cp.async.cg.shared.global [%0], [%1], 16, %2;"
                 :: "r"(dst), "l"(src), "r"(srcsize));
}

__device__ __forceinline__ void load_stage(
    uint32_t st,
    const __nv_bfloat16* __restrict__ Ah, const __nv_bfloat16* __restrict__ Al,
    const __nv_bfloat16* __restrict__ Bh, const __nv_bfloat16* __restrict__ Bl,
    int tile_m, int tile_n, int Mdim, int Kdim, int kc, int tid)
{
    const int k0 = kc * 32;
    #pragma unroll
    for (int i = 0; i < 4; i++) {           // A: 2 arrays x 128 rows x 4 chunks
        int id  = tid + 256*i;
        int arr = id >> 9, rem = id & 511;
        int row = rem >> 2, c = rem & 3;
        const __nv_bfloat16* src =
            (arr ? Al : Ah) + (size_t)(tile_m + row) * Kdim + k0 + c*8;
        cpa16(st + arr*A_ARR + row*PADB + c*16, src,
              (tile_m + row) < Mdim ? 16 : 0);
    }
    #pragma unroll
    for (int i = 0; i < 8; i++) {           // B: 2 arrays x 256 rows x 4 chunks
        int id  = tid + 256*i;
        int arr = id >> 10, rem = id & 1023;
        int row = rem >> 2, c = rem & 3;
        const __nv_bfloat16* src =
            (arr ? Bl : Bh) + (size_t)(tile_n + row) * Kdim + k0 + c*8;
        cpa16(st + 2*A_ARR + arr*B_ARR + row*PADB + c*16, src, 16);
    }
    asm volatile("cp.async.commit_group;" ::: "memory");
}

__device__ __forceinline__ void split2(float v0, float v1,
                                       __nv_bfloat162& h, __nv_bfloat162& l) {
    h.x = __float2bfloat16_rn(v0); h.y = __float2bfloat16_rn(v1);
    l.x = __float2bfloat16_rn(v0 - __bfloat162float(h.x));
    l.y = __float2bfloat16_rn(v1 - __bfloat162float(h.y));
}

__global__ __launch_bounds__(256)
void gemm_tc(const __nv_bfloat16* __restrict__ Ah, const __nv_bfloat16* __restrict__ Al,
             const __nv_bfloat16* __restrict__ Bh, const __nv_bfloat16* __restrict__ Bl,
             float* __restrict__ Cf,
             __nv_bfloat16* __restrict__ Ch, __nv_bfloat16* __restrict__ Cl,
             int Mdim, int Ndim, int Kdim,
             const float* __restrict__ bias, int act)
{
    extern __shared__ __align__(16) char smem[];
    const uint32_t sb = smem_u32(smem);
    const int tid    = threadIdx.x;
    const int tile_m = blockIdx.y * BM;
    const int tile_n = blockIdx.x * BN;
    const int warp = tid >> 5, lane = tid & 31;
    const int wm2 = warp >> 2, wn4 = warp & 3;    // 2(M) x 4(N), 64x64 warp tiles

    float acc[4][8][4];
    #pragma unroll
    for (int a = 0; a < 4; a++)
        #pragma unroll
        for (int b = 0; b < 8; b++)
            #pragma unroll
            for (int q = 0; q < 4; q++) acc[a][b][q] = 0.0f;

    const int nst = Kdim >> 5;
    load_stage(sb,         Ah, Al, Bh, Bl, tile_m, tile_n, Mdim, Kdim, 0, tid);
    load_stage(sb + STAGE, Ah, Al, Bh, Bl, tile_m, tile_n, Mdim, Kdim, 1, tid);

    const uint32_t a_off = (uint32_t)(wm2*64 + (lane & 7) + ((lane >> 3) & 1) * 8) * PADB
                         + ((lane >> 4) * 16);
    const uint32_t b_off = (uint32_t)(wn4*64 + (lane & 7) + ((lane >> 4) & 1) * 8) * PADB
                         + (((lane >> 3) & 1) * 16);

    for (int s = 0; s < nst; s++) {
        if (s + 1 < nst) asm volatile("cp.async.wait_group 1;" ::: "memory");
        else             asm volatile("cp.async.wait_group 0;" ::: "memory");
        __syncthreads();
        if (s + 2 < nst)
            load_stage(sb + ((s + 2) % 3) * STAGE, Ah, Al, Bh, Bl,
                       tile_m, tile_n, Mdim, Kdim, s + 2, tid);
        const uint32_t st = sb + (s % 3) * STAGE;

        #pragma unroll
        for (int ks = 0; ks < 2; ks++) {
            uint32_t ah[4][4], al[4][4], bh[8][2], bl[8][2];
            #pragma unroll
            for (int mi = 0; mi < 4; mi++) {
                uint32_t ad = st + a_off + mi * (16 * PADB) + ks * 32;
                ldsm4(ah[mi], ad);
                ldsm4(al[mi], ad + A_ARR);
            }
            #pragma unroll
            for (int p = 0; p < 4; p++) {
                uint32_t bd = st + 2*A_ARR + b_off + p * (16 * PADB) + ks * 32;
                uint32_t r[4];
                ldsm4(r, bd);
                bh[2*p][0] = r[0]; bh[2*p][1] = r[1];
                bh[2*p+1][0] = r[2]; bh[2*p+1][1] = r[3];
                ldsm4(r, bd + B_ARR);
                bl[2*p][0] = r[0]; bl[2*p][1] = r[1];
                bl[2*p+1][0] = r[2]; bl[2*p+1][1] = r[3];
            }
            // --- three independent passes: 32 distinct accumulators between
            //     successive writes to the same acc -> no RAW stalls ---
            #pragma unroll
            for (int mi = 0; mi < 4; mi++)
                #pragma unroll
                for (int ni = 0; ni < 8; ni++)
                    mma16816(acc[mi][ni], ah[mi], bh[ni]);
            #pragma unroll
            for (int mi = 0; mi < 4; mi++)
                #pragma unroll
                for (int ni = 0; ni < 8; ni++)
                    mma16816(acc[mi][ni], ah[mi], bl[ni]);
            #pragma unroll
            for (int mi = 0; mi < 4; mi++)
                #pragma unroll
                for (int ni = 0; ni < 8; ni++)
                    mma16816(acc[mi][ni], al[mi], bh[ni]);
        }
    }

    // ---- epilogue ----
    const int er = lane >> 2;
    const int ec = (lane & 3) * 2;
    #pragma unroll
    for (int mi = 0; mi < 4; mi++) {
        const int gm0 = tile_m + wm2*64 + mi*16 + er;
        #pragma unroll
        for (int ni = 0; ni < 8; ni++) {
            const int gn = tile_n + wn4*64 + ni*8 + ec;
            float bx = 0.f, by = 0.f;
            if (bias) { float2 bb = *reinterpret_cast<const float2*>(bias + gn);
                        bx = bb.x; by = bb.y; }
            float v0 = acc[mi][ni][0] + bx, v1 = acc[mi][ni][1] + by;
            float v2 = acc[mi][ni][2] + bx, v3 = acc[mi][ni][3] + by;
            if (act == 1) {
                v0 = fmaxf(v0, 0.f); v1 = fmaxf(v1, 0.f);
                v2 = fmaxf(v2, 0.f); v3 = fmaxf(v3, 0.f);
            } else if (act == 2) {
                v0 = tanhf(v0); v1 = tanhf(v1); v2 = tanhf(v2); v3 = tanhf(v3);
            }
            if (Cf) {
                if (gm0 < Mdim)
                    *reinterpret_cast<float2*>(Cf + (size_t)gm0 * Ndim + gn) = make_float2(v0, v1);
                if (gm0 + 8 < Mdim)
                    *reinterpret_cast<float2*>(Cf + (size_t)(gm0+8) * Ndim + gn) = make_float2(v2, v3);
            } else {
                __nv_bfloat162 h, l;
                if (gm0 < Mdim) {
                    size_t off = (size_t)gm0 * Ndim + gn;
                    split2(v0, v1, h, l);
                    *reinterpret_cast<__nv_bfloat162*>(Ch + off) = h;
                    *reinterpret_cast<__nv_bfloat162*>(Cl + off) = l;
                }
                if (gm0 + 8 < Mdim) {
                    size_t off = (size_t)(gm0+8) * Ndim + gn;
                    split2(v2, v3, h, l);
                    *reinterpret_cast<__nv_bfloat162*>(Ch + off) = h;
                    *reinterpret_cast<__nv_bfloat162*>(Cl + off) = l;
                }
            }
        }
    }
}

// ---------------- fp32 -> bf16 hi/lo split (weights) ----------------
__global__ void split_kernel(const float* __restrict__ in,
                             __nv_bfloat16* __restrict__ oh,
                             __nv_bfloat16* __restrict__ ol, int n4) {
    int i = blockIdx.x * blockDim.x + threadIdx.x;
    if (i >= n4) return;
    float4 v = *reinterpret_cast<const float4*>(in + (size_t)i * 4);
    __nv_bfloat162 h0, l0, h1, l1;
    split2(v.x, v.y, h0, l0);
    split2(v.z, v.w, h1, l1);
    uint2 hh, ll;
    hh.x = *reinterpret_cast<uint32_t*>(&h0); hh.y = *reinterpret_cast<uint32_t*>(&h1);
    ll.x = *reinterpret_cast<uint32_t*>(&l0); ll.y = *reinterpret_cast<uint32_t*>(&l1);
    *reinterpret_cast<uint2*>(oh + (size_t)i * 4) = hh;
    *reinterpret_cast<uint2*>(ol + (size_t)i * 4) = ll;
}

// ---------------- PE table ----------------
__global__ void pe_kernel(float* pe) {
    int idx = blockIdx.x * blockDim.x + threadIdx.x;
    if (idx >= M_ * E_) return;
    int pos = idx / E_, i = idx % E_;
    double e2  = (double)((i / 2) * 2);
    double ang = (double)pos / pow(10000.0, e2 / (double)E_);
    pe[idx] = (float)((i % 2 == 0) ? sin(ang) : cos(ang));
}

// ---------------- span id ----------------
__global__ void span_kernel(const int* __restrict__ pos1, int* __restrict__ span) {
    int b = blockIdx.x;
    int j = threadIdx.x;
    __shared__ int firstZero;
    span[b*M_ + j] = -1;
    if (j == 0) firstZero = M_;
    __syncthreads();
    int endv = pos1[((size_t)b*M_ + j)*2 + 1];
    if (endv == 0) atomicMin(&firstZero, j);
    __syncthreads();
    if (j < firstZero) {
        int st = pos1[((size_t)b*M_ + j)*2];
        int en = endv; if (en > M_) en = M_;
        for (int k = st; k < en; k++)
            atomicMax(&span[b*M_ + k], j);
    }
}

// ---------------- build x [B,S,E] + split ----------------
__global__ void build_x_kernel(const int* __restrict__ pos2,
                               const float* __restrict__ fbase,
                               const float* __restrict__ emb,
                               const int* __restrict__ span,
                               const float* __restrict__ pe,
                               float* __restrict__ X,
                               __nv_bfloat16* __restrict__ Xh,
                               __nv_bfloat16* __restrict__ Xl) {
    int row = blockIdx.x;
    int b = row / S_, s = row % S_;
    size_t base = (size_t)row * E_;
    int e = threadIdx.x;
    float val;
    if (s == 0) {
        val = emb[(size_t)1*E_ + e];
    } else {
        int k = s - 1;
        int sid = span[b*M_ + k];
        if (sid >= 0) {
            int p = pos2[b*M_ + sid];
            val = (p == 0 ? 0.0f : emb[(size_t)p*E_ + e]) + pe[(size_t)sid*E_ + e];
        } else {
            val = fbase[((size_t)b*M_ + k)*E_ + e];
        }
    }
    X[base + e] = val;
    __nv_bfloat16 h = __float2bfloat16_rn(val);
    Xh[base + e] = h;
    Xl[base + e] = __float2bfloat16_rn(val - __bfloat162float(h));
}

// ---------------- fused attention over the B axis (split output) ----------------
__global__ void attn_kernel(const float* __restrict__ QKV,
                            __nv_bfloat16* __restrict__ CXh,
                            __nv_bfloat16* __restrict__ CXl) {
    int z = blockIdx.x;
    int s = z / NHEAD_, h = z % NHEAD_;
    __shared__ float q[B_][DH_];
    __shared__ float k[B_][DH_];
    __shared__ float v[B_][DH_];
    __shared__ float sc[B_][B_ + 1];

    const float* base = QKV + (size_t)s * 3*E_ + (size_t)h * DH_;
    int t = threadIdx.x;

    for (int i = t; i < B_*DH_; i += 256) {
        int b = i / DH_, d = i % DH_;
        size_t off = (size_t)b * S_ * 3*E_ + d;
        q[b][d] = base[off];
        k[b][d] = base[off + E_];
        v[b][d] = base[off + 2*E_];
    }
    __syncthreads();

    for (int i = t; i < B_*B_; i += 256) {
        int l = i / B_, m = i % B_;
        float acc = 0.0f;
        #pragma unroll
        for (int d = 0; d < DH_; d++) acc += q[l][d] * k[m][d];
        sc[l][m] = acc * 0.125f;
    }
    __syncthreads();

    int warp = t >> 5, lane = t & 31;
    for (int l = warp; l < B_; l += 8) {
        float val = sc[l][lane];
        float mx = val;
        #pragma unroll
        for (int o = 16; o; o >>= 1) mx = fmaxf(mx, __shfl_xor_sync(0xffffffffu, mx, o));
        float e = expf(val - mx);
        float sum = e;
        #pragma unroll
        for (int o = 16; o; o >>= 1) sum += __shfl_xor_sync(0xffffffffu, sum, o);
        sc[l][lane] = e / sum;
    }
    __syncthreads();

    for (int i = t; i < B_*DH_; i += 256) {
        int l = i / DH_, d = i % DH_;
        float acc = 0.0f;
        #pragma unroll
        for (int m = 0; m < B_; m++) acc += sc[l][m] * v[m][d];
        size_t off = ((size_t)l * S_ + s) * E_ + (size_t)h * DH_ + d;
        __nv_bfloat16 hh = __float2bfloat16_rn(acc);
        CXh[off] = hh;
        CXl[off] = __float2bfloat16_rn(acc - __bfloat162float(hh));
    }
}

// ---------------- residual add + layernorm (+ split) ----------------
__global__ void add_ln_kernel(float* __restrict__ x, const float* __restrict__ y,
                              const float* __restrict__ w, const float* __restrict__ b,
                              __nv_bfloat16* __restrict__ Xh,
                              __nv_bfloat16* __restrict__ Xl) {
    long long row = blockIdx.x;
    __shared__ float red[256];
    int t = threadIdx.x;
    float v0 = x[row*E_ + t]       + y[row*E_ + t];
    float v1 = x[row*E_ + 256 + t] + y[row*E_ + 256 + t];
    red[t] = v0 + v1;
    __syncthreads();
    #pragma unroll
    for (int s2 = 128; s2 > 0; s2 >>= 1) { if (t < s2) red[t] += red[t + s2]; __syncthreads(); }
    float mean = red[0] * (1.0f / E_);
    __syncthreads();
    float d0 = v0 - mean, d1 = v1 - mean;
    red[t] = d0*d0 + d1*d1;
    __syncthreads();
    #pragma unroll
    for (int s2 = 128; s2 > 0; s2 >>= 1) { if (t < s2) red[t] += red[t + s2]; __syncthreads(); }
    float rstd = rsqrtf(red[0] * (1.0f / E_) + 1e-5f);
    float o0 = d0 * rstd * w[t]       + b[t];
    float o1 = d1 * rstd * w[t + 256] + b[t + 256];
    x[row*E_ + t]       = o0;
    x[row*E_ + 256 + t] = o1;
    __nv_bfloat16 h0 = __float2bfloat16_rn(o0);
    __nv_bfloat16 h1 = __float2bfloat16_rn(o1);
    Xh[row*E_ + t]       = h0;
    Xh[row*E_ + 256 + t] = h1;
    Xl[row*E_ + t]       = __float2bfloat16_rn(o0 - __bfloat162float(h0));
    Xl[row*E_ + 256 + t] = __float2bfloat16_rn(o1 - __bfloat162float(h1));
}

// ---------------- discriminator head ----------------
__global__ void disc_kernel(const float* __restrict__ bert,
                            const float* __restrict__ posf,
                            const float* __restrict__ wd,
                            const float* __restrict__ bd,
                            float* __restrict__ out, int ntok) {
    int n = (blockIdx.x * blockDim.x + threadIdx.x) >> 5;
    int lane = threadIdx.x & 31;
    if (n >= ntok) return;
    float acc = 0.0f;
    const float* br = bert + (size_t)n * F_;
    const float* pr = posf + (size_t)n * F_;
    for (int i = lane; i < F_; i += 32) acc += br[i] * wd[i];
    for (int i = lane; i < F_; i += 32) acc += pr[i] * wd[F_ + i];
    #pragma unroll
    for (int o = 16; o; o >>= 1) acc += __shfl_xor_sync(0xffffffffu, acc, o);
    if (lane == 0) out[n] = 1.0f / (1.0f + expf(-(acc + bd[0])));
}

// ---------------- host orchestration ----------------
static inline int cdiv(int a, int b) { return (a + b - 1) / b; }

extern "C" void kernel_launch(void* const* d_in, const int* in_sizes, int n_in,
                              void* d_out, int out_size) {
    const int*   pos1  = (const int*)d_in[0];
    const int*   pos2  = (const int*)d_in[1];
    const float* bert  = (const float*)d_in[2];
    const float* fbase = (const float*)d_in[3];
    const float* emb   = (const float*)d_in[4];
    const float* wqkv  = (const float*)d_in[5];
    const float* bqkv  = (const float*)d_in[6];
    const float* wo    = (const float*)d_in[7];
    const float* bo    = (const float*)d_in[8];
    const float* ln1w  = (const float*)d_in[9];
    const float* ln1b  = (const float*)d_in[10];
    const float* ln2w  = (const float*)d_in[11];
    const float* ln2b  = (const float*)d_in[12];
    const float* w1    = (const float*)d_in[13];
    const float* b1    = (const float*)d_in[14];
    const float* w2    = (const float*)d_in[15];
    const float* b2    = (const float*)d_in[16];
    const float* wm    = (const float*)d_in[17];
    const float* wd    = (const float*)d_in[18];
    const float* bd    = (const float*)d_in[19];
    float* out = (float*)d_out;

    float *PE, *X, *Y, *QKV, *POSF; int* SPAN;
    __nv_bfloat16 *Xh, *Xl, *CXh, *CXl, *Hh, *Hl;
    __nv_bfloat16 *WQh, *WQl, *WOh, *WOl, *W1h, *W1l, *W2h, *W2l, *WMh, *WMl;
    cudaGetSymbolAddress((void**)&PE,   d_PE);
    cudaGetSymbolAddress((void**)&SPAN, d_SPAN);
    cudaGetSymbolAddress((void**)&X,    d_X);
    cudaGetSymbolAddress((void**)&Y,    d_Y);
    cudaGetSymbolAddress((void**)&QKV,  d_QKV);
    cudaGetSymbolAddress((void**)&POSF, d_POSF);
    cudaGetSymbolAddress((void**)&Xh,  d_Xh);  cudaGetSymbolAddress((void**)&Xl,  d_Xl);
    cudaGetSymbolAddress((void**)&CXh, d_CXh); cudaGetSymbolAddress((void**)&CXl, d_CXl);
    cudaGetSymbolAddress((void**)&Hh,  d_Hh);  cudaGetSymbolAddress((void**)&Hl,  d_Hl);
    cudaGetSymbolAddress((void**)&WQh, d_WQh); cudaGetSymbolAddress((void**)&WQl, d_WQl);
    cudaGetSymbolAddress((void**)&WOh, d_WOh); cudaGetSymbolAddress((void**)&WOl, d_WOl);
    cudaGetSymbolAddress((void**)&W1h, d_W1h); cudaGetSymbolAddress((void**)&W1l, d_W1l);
    cudaGetSymbolAddress((void**)&W2h, d_W2h); cudaGetSymbolAddress((void**)&W2l, d_W2l);
    cudaGetSymbolAddress((void**)&WMh, d_WMh); cudaGetSymbolAddress((void**)&WMl, d_WMl);

    cudaFuncSetAttribute(gemm_tc, cudaFuncAttributeMaxDynamicSharedMemorySize, SMEM_GEMM);

    // ---- preamble ----
    pe_kernel<<<cdiv(M_*E_, 256), 256>>>(PE);
    span_kernel<<<B_, M_>>>(pos1, SPAN);
    build_x_kernel<<<NTOK, 512>>>(pos2, fbase, emb, SPAN, PE, X, Xh, Xl);

    // ---- weight splits ----
    { int n4 = 2*3*E_*E_/4; split_kernel<<<cdiv(n4,256),256>>>(wqkv, WQh, WQl, n4); }
    { int n4 = 2*E_*E_/4;   split_kernel<<<cdiv(n4,256),256>>>(wo,   WOh, WOl, n4); }
    { int n4 = 2*DFF_*E_/4; split_kernel<<<cdiv(n4,256),256>>>(w1,   W1h, W1l, n4); }
    { int n4 = 2*E_*DFF_/4; split_kernel<<<cdiv(n4,256),256>>>(w2,   W2h, W2l, n4); }
    { int n4 = F_*E_/4;     split_kernel<<<cdiv(n4,256),256>>>(wm,   WMh, WMl, n4); }

    const int MY = cdiv(NTOK, BM);   // 129

    for (int l = 0; l < 2; l++) {
        const size_t oq = (size_t)l * 3*E_ * E_;
        const size_t oo = (size_t)l * E_ * E_;
        const size_t o1 = (size_t)l * DFF_ * E_;
        const size_t o2 = (size_t)l * E_ * DFF_;

        { dim3 g(3*E_/BN, MY);   // QKV
          gemm_tc<<<g, 256, SMEM_GEMM>>>(Xh, Xl, WQh+oq, WQl+oq,
              QKV, nullptr, nullptr, NTOK, 3*E_, E_, bqkv + l*3*E_, 0); }

        attn_kernel<<<S_*NHEAD_, 256>>>(QKV, CXh, CXl);

        { dim3 g(E_/BN, MY);     // Wo
          gemm_tc<<<g, 256, SMEM_GEMM>>>(CXh, CXl, WOh+oo, WOl+oo,
              Y, nullptr, nullptr, NTOK, E_, E_, bo + l*E_, 0); }

        add_ln_kernel<<<NTOK, 256>>>(X, Y, ln1w + l*E_, ln1b + l*E_, Xh, Xl);

        { dim3 g(DFF_/BN, MY);   // FFN1 -> split H
          gemm_tc<<<g, 256, SMEM_GEMM>>>(Xh, Xl, W1h+o1, W1l+o1,
              nullptr, Hh, Hl, NTOK, DFF_, E_, b1 + l*DFF_, 1); }

        { dim3 g(E_/BN, MY);     // FFN2
          gemm_tc<<<g, 256, SMEM_GEMM>>>(Hh, Hl, W2h+o2, W2l+o2,
              Y, nullptr, nullptr, NTOK, E_, DFF_, b2 + l*E_, 0); }

        add_ln_kernel<<<NTOK, 256>>>(X, Y, ln2w + l*E_, ln2b + l*E_, Xh, Xl);
    }

    { dim3 g(F_/BN, MY);         // pos_feature = tanh(X @ wm^T)
      gemm_tc<<<g, 256, SMEM_GEMM>>>(Xh, Xl, WMh, WMl,
          POSF, nullptr, nullptr, NTOK, F_, E_, nullptr, 2); }

    disc_kernel<<<cdiv(NTOK*32, 256), 256>>>(bert, POSF, wd, bd, out, NTOK);
}

// round 7
// speedup vs baseline: 4.5343x; 1.0234x over previous
#include <cuda_runtime.h>
#include <cuda_bf16.h>
#include <math.h>
#include <stdint.h>

// ---------------- problem constants ----------------
#define B_    32
#define M_    512
#define E_    512
#define S_    513
#define NTOK  (B_*S_)          // 16416
#define NHEAD_ 8
#define DH_   64
#define DFF_  2048
#define F_    768

// ---------------- fp32 scratch ----------------
__device__ float d_PE[M_*E_];
__device__ int   d_SPAN[B_*M_];
__device__ float d_X  [(size_t)NTOK*E_];
__device__ float d_Y  [(size_t)NTOK*E_];
__device__ float d_QKV[(size_t)NTOK*3*E_];
__device__ float d_POSF[(size_t)NTOK*F_];

// ---------------- bf16 hi/lo split operand buffers ----------------
__device__ __align__(16) __nv_bfloat16 d_Xh [(size_t)NTOK*E_];
__device__ __align__(16) __nv_bfloat16 d_Xl [(size_t)NTOK*E_];
__device__ __align__(16) __nv_bfloat16 d_CXh[(size_t)NTOK*E_];
__device__ __align__(16) __nv_bfloat16 d_CXl[(size_t)NTOK*E_];
__device__ __align__(16) __nv_bfloat16 d_Hh [(size_t)NTOK*DFF_];
__device__ __align__(16) __nv_bfloat16 d_Hl [(size_t)NTOK*DFF_];
__device__ __align__(16) __nv_bfloat16 d_WQh[(size_t)2*3*E_*E_];
__device__ __align__(16) __nv_bfloat16 d_WQl[(size_t)2*3*E_*E_];
__device__ __align__(16) __nv_bfloat16 d_WOh[(size_t)2*E_*E_];
__device__ __align__(16) __nv_bfloat16 d_WOl[(size_t)2*E_*E_];
__device__ __align__(16) __nv_bfloat16 d_W1h[(size_t)2*DFF_*E_];
__device__ __align__(16) __nv_bfloat16 d_W1l[(size_t)2*DFF_*E_];
__device__ __align__(16) __nv_bfloat16 d_W2h[(size_t)2*E_*DFF_];
__device__ __align__(16) __nv_bfloat16 d_W2l[(size_t)2*E_*DFF_];
__device__ __align__(16) __nv_bfloat16 d_WMh[(size_t)F_*E_];
__device__ __align__(16) __nv_bfloat16 d_WMl[(size_t)F_*E_];

// ================= bf16-split tensor-core GEMM =================
#define BM 128
#define BN 256
#define BK 32
#define PADB 80
#define A_ARR (128*PADB)
#define B_ARR (256*PADB)
#define STAGE (2*A_ARR + 2*B_ARR)
#define SMEM_GEMM (3*STAGE)
#define NTHR_G 512

__device__ __forceinline__ uint32_t smem_u32(const void* p) {
    uint32_t a;
    asm("{ .reg .u64 t; cvta.to.shared.u64 t, %1; cvt.u32.u64 %0, t; }"
        : "=r"(a) : "l"(p));
    return a;
}
__device__ __forceinline__ void ldsm4(uint32_t* r, uint32_t addr) {
    asm volatile("ldmatrix.sync.aligned.m8n8.x4.shared.b16 {%0,%1,%2,%3}, [%4];"
        : "=r"(r[0]), "=r"(r[1]), "=r"(r[2]), "=r"(r[3]) : "r"(addr));
}
__device__ __forceinline__ void mma16816(float* c, const uint32_t* a, const uint32_t* b) {
    asm volatile(
        "mma.sync.aligned.m16n8k16.row.col.f32.bf16.bf16.f32 "
        "{%0,%1,%2,%3}, {%4,%5,%6,%7}, {%8,%9}, {%0,%1,%2,%3};"
        : "+f"(c[0]), "+f"(c[1]), "+f"(c[2]), "+f"(c[3])
        : "r"(a[0]), "r"(a[1]), "r"(a[2]), "r"(a[3]), "r"(b[0]), "r"(b[1]));
}
__device__ __forceinline__ void cpa16(uint32_t dst, const void* src, int srcsize) {
    asm volatile("cp.async.cg.shared.global [%0], [%1], 16, %2;"
                 :: "r"(dst), "l"(src), "r"(srcsize));
}

__device__ __forceinline__ void load_stage(
    uint32_t st,
    const __nv_bfloat16* __restrict__ Ah, const __nv_bfloat16* __restrict__ Al,
    const __nv_bfloat16* __restrict__ Bh, const __nv_bfloat16* __restrict__ Bl,
    int tile_m, int tile_n, int Mdim, int Kdim, int kc, int tid)
{
    const int k0 = kc * 32;
    #pragma unroll
    for (int i = 0; i < 2; i++) {           // A: 2 arrays x 128 rows x 4 chunks = 1024
        int id  = tid + NTHR_G*i;
        int arr = id >> 9, rem = id & 511;
        int row = rem >> 2, c = rem & 3;
        const __nv_bfloat16* src =
            (arr ? Al : Ah) + (size_t)(tile_m + row) * Kdim + k0 + c*8;
        cpa16(st + arr*A_ARR + row*PADB + c*16, src,
              (tile_m + row) < Mdim ? 16 : 0);
    }
    #pragma unroll
    for (int i = 0; i < 4; i++) {           // B: 2 arrays x 256 rows x 4 chunks = 2048
        int id  = tid + NTHR_G*i;
        int arr = id >> 10, rem = id & 1023;
        int row = rem >> 2, c = rem & 3;
        const __nv_bfloat16* src =
            (arr ? Bl : Bh) + (size_t)(tile_n + row) * Kdim + k0 + c*8;
        cpa16(st + 2*A_ARR + arr*B_ARR + row*PADB + c*16, src, 16);
    }
    asm volatile("cp.async.commit_group;" ::: "memory");
}

__device__ __forceinline__ void split2(float v0, float v1,
                                       __nv_bfloat162& h, __nv_bfloat162& l) {
    h.x = __float2bfloat16_rn(v0); h.y = __float2bfloat16_rn(v1);
    l.x = __float2bfloat16_rn(v0 - __bfloat162float(h.x));
    l.y = __float2bfloat16_rn(v1 - __bfloat162float(h.y));
}

__global__ __launch_bounds__(NTHR_G, 1)
void gemm_tc(const __nv_bfloat16* __restrict__ Ah, const __nv_bfloat16* __restrict__ Al,
             const __nv_bfloat16* __restrict__ Bh, const __nv_bfloat16* __restrict__ Bl,
             float* __restrict__ Cf,
             __nv_bfloat16* __restrict__ Ch, __nv_bfloat16* __restrict__ Cl,
             int Mdim, int Ndim, int Kdim,
             const float* __restrict__ bias, int act)
{
    extern __shared__ __align__(16) char smem[];
    const uint32_t sb = smem_u32(smem);
    const int tid    = threadIdx.x;
    const int tile_m = blockIdx.y * BM;
    const int tile_n = blockIdx.x * BN;
    const int warp = tid >> 5, lane = tid & 31;
    const int wm4 = warp >> 2, wn4 = warp & 3;    // 4(M) x 4(N), 32x64 warp tiles

    float acc[2][8][4];
    #pragma unroll
    for (int a = 0; a < 2; a++)
        #pragma unroll
        for (int b = 0; b < 8; b++)
            #pragma unroll
            for (int q = 0; q < 4; q++) acc[a][b][q] = 0.0f;

    const int nst = Kdim >> 5;
    load_stage(sb,         Ah, Al, Bh, Bl, tile_m, tile_n, Mdim, Kdim, 0, tid);
    load_stage(sb + STAGE, Ah, Al, Bh, Bl, tile_m, tile_n, Mdim, Kdim, 1, tid);

    const uint32_t a_off = (uint32_t)(wm4*32 + (lane & 7) + ((lane >> 3) & 1) * 8) * PADB
                         + ((lane >> 4) * 16);
    const uint32_t b_off = (uint32_t)(wn4*64 + (lane & 7) + ((lane >> 4) & 1) * 8) * PADB
                         + (((lane >> 3) & 1) * 16);

    for (int s = 0; s < nst; s++) {
        if (s + 1 < nst) asm volatile("cp.async.wait_group 1;" ::: "memory");
        else             asm volatile("cp.async.wait_group 0;" ::: "memory");
        __syncthreads();
        if (s + 2 < nst)
            load_stage(sb + ((s + 2) % 3) * STAGE, Ah, Al, Bh, Bl,
                       tile_m, tile_n, Mdim, Kdim, s + 2, tid);
        const uint32_t st = sb + (s % 3) * STAGE;

        #pragma unroll
        for (int ks = 0; ks < 2; ks++) {
            uint32_t ah[2][4], al[2][4];
            #pragma unroll
            for (int mi = 0; mi < 2; mi++) {
                uint32_t ad = st + a_off + mi * (16 * PADB) + ks * 32;
                ldsm4(ah[mi], ad);
                ldsm4(al[mi], ad + A_ARR);
            }
            #pragma unroll
            for (int half = 0; half < 2; half++) {
                uint32_t bh[4][2], bl[4][2];
                #pragma unroll
                for (int p = 0; p < 2; p++) {
                    uint32_t bd = st + 2*A_ARR + b_off
                                + (half*2 + p) * (16 * PADB) + ks * 32;
                    uint32_t r[4];
                    ldsm4(r, bd);
                    bh[2*p][0] = r[0]; bh[2*p][1] = r[1];
                    bh[2*p+1][0] = r[2]; bh[2*p+1][1] = r[3];
                    ldsm4(r, bd + B_ARR);
                    bl[2*p][0] = r[0]; bl[2*p][1] = r[1];
                    bl[2*p+1][0] = r[2]; bl[2*p+1][1] = r[3];
                }
                #pragma unroll
                for (int mi = 0; mi < 2; mi++)
                    #pragma unroll
                    for (int ni = 0; ni < 4; ni++)
                        mma16816(acc[mi][half*4+ni], ah[mi], bh[ni]);
                #pragma unroll
                for (int mi = 0; mi < 2; mi++)
                    #pragma unroll
                    for (int ni = 0; ni < 4; ni++)
                        mma16816(acc[mi][half*4+ni], ah[mi], bl[ni]);
                #pragma unroll
                for (int mi = 0; mi < 2; mi++)
                    #pragma unroll
                    for (int ni = 0; ni < 4; ni++)
                        mma16816(acc[mi][half*4+ni], al[mi], bh[ni]);
            }
        }
    }

    // ---- epilogue ----
    const int er = lane >> 2;
    const int ec = (lane & 3) * 2;
    #pragma unroll
    for (int mi = 0; mi < 2; mi++) {
        const int gm0 = tile_m + wm4*32 + mi*16 + er;
        #pragma unroll
        for (int ni = 0; ni < 8; ni++) {
            const int gn = tile_n + wn4*64 + ni*8 + ec;
            float bx = 0.f, by = 0.f;
            if (bias) { float2 bb = *reinterpret_cast<const float2*>(bias + gn);
                        bx = bb.x; by = bb.y; }
            float v0 = acc[mi][ni][0] + bx, v1 = acc[mi][ni][1] + by;
            float v2 = acc[mi][ni][2] + bx, v3 = acc[mi][ni][3] + by;
            if (act == 1) {
                v0 = fmaxf(v0, 0.f); v1 = fmaxf(v1, 0.f);
                v2 = fmaxf(v2, 0.f); v3 = fmaxf(v3, 0.f);
            } else if (act == 2) {
                v0 = tanhf(v0); v1 = tanhf(v1); v2 = tanhf(v2); v3 = tanhf(v3);
            }
            if (Cf) {
                if (gm0 < Mdim)
                    *reinterpret_cast<float2*>(Cf + (size_t)gm0 * Ndim + gn) = make_float2(v0, v1);
                if (gm0 + 8 < Mdim)
                    *reinterpret_cast<float2*>(Cf + (size_t)(gm0+8) * Ndim + gn) = make_float2(v2, v3);
            } else {
                __nv_bfloat162 h, l;
                if (gm0 < Mdim) {
                    size_t off = (size_t)gm0 * Ndim + gn;
                    split2(v0, v1, h, l);
                    *reinterpret_cast<__nv_bfloat162*>(Ch + off) = h;
                    *reinterpret_cast<__nv_bfloat162*>(Cl + off) = l;
                }
                if (gm0 + 8 < Mdim) {
                    size_t off = (size_t)(gm0+8) * Ndim + gn;
                    split2(v2, v3, h, l);
                    *reinterpret_cast<__nv_bfloat162*>(Ch + off) = h;
                    *reinterpret_cast<__nv_bfloat162*>(Cl + off) = l;
                }
            }
        }
    }
}

// ---------------- fp32 -> bf16 hi/lo splits (multi-tensor, fewer launches) -----
__device__ __forceinline__ void split_one(const float* in, __nv_bfloat16* oh,
                                          __nv_bfloat16* ol, int i) {
    float4 v = *reinterpret_cast<const float4*>(in + (size_t)i * 4);
    __nv_bfloat162 h0, l0, h1, l1;
    split2(v.x, v.y, h0, l0);
    split2(v.z, v.w, h1, l1);
    uint2 hh, ll;
    hh.x = *reinterpret_cast<uint32_t*>(&h0); hh.y = *reinterpret_cast<uint32_t*>(&h1);
    ll.x = *reinterpret_cast<uint32_t*>(&l0); ll.y = *reinterpret_cast<uint32_t*>(&l1);
    *reinterpret_cast<uint2*>(oh + (size_t)i * 4) = hh;
    *reinterpret_cast<uint2*>(ol + (size_t)i * 4) = ll;
}
__global__ void split3_kernel(const float* i1, __nv_bfloat16* h1, __nv_bfloat16* l1, int n1,
                              const float* i2, __nv_bfloat16* h2, __nv_bfloat16* l2, int n2,
                              const float* i3, __nv_bfloat16* h3, __nv_bfloat16* l3, int n3) {
    int i = blockIdx.x * blockDim.x + threadIdx.x;
    if (i < n1) { split_one(i1, h1, l1, i); return; }
    i -= n1;
    if (i < n2) { split_one(i2, h2, l2, i); return; }
    i -= n2;
    if (i < n3) split_one(i3, h3, l3, i);
}
__global__ void split2_kernel(const float* i1, __nv_bfloat16* h1, __nv_bfloat16* l1, int n1,
                              const float* i2, __nv_bfloat16* h2, __nv_bfloat16* l2, int n2) {
    int i = blockIdx.x * blockDim.x + threadIdx.x;
    if (i < n1) { split_one(i1, h1, l1, i); return; }
    i -= n1;
    if (i < n2) split_one(i2, h2, l2, i);
}

// ---------------- PE table ----------------
__global__ void pe_kernel(float* pe) {
    int idx = blockIdx.x * blockDim.x + threadIdx.x;
    if (idx >= M_ * E_) return;
    int pos = idx / E_, i = idx % E_;
    double e2  = (double)((i / 2) * 2);
    double ang = (double)pos / pow(10000.0, e2 / (double)E_);
    pe[idx] = (float)((i % 2 == 0) ? sin(ang) : cos(ang));
}

// ---------------- span id ----------------
__global__ void span_kernel(const int* __restrict__ pos1, int* __restrict__ span) {
    int b = blockIdx.x;
    int j = threadIdx.x;
    __shared__ int firstZero;
    span[b*M_ + j] = -1;
    if (j == 0) firstZero = M_;
    __syncthreads();
    int endv = pos1[((size_t)b*M_ + j)*2 + 1];
    if (endv == 0) atomicMin(&firstZero, j);
    __syncthreads();
    if (j < firstZero) {
        int st = pos1[((size_t)b*M_ + j)*2];
        int en = endv; if (en > M_) en = M_;
        for (int k = st; k < en; k++)
            atomicMax(&span[b*M_ + k], j);
    }
}

// ---------------- build x [B,S,E] + split ----------------
__global__ void build_x_kernel(const int* __restrict__ pos2,
                               const float* __restrict__ fbase,
                               const float* __restrict__ emb,
                               const int* __restrict__ span,
                               const float* __restrict__ pe,
                               float* __restrict__ X,
                               __nv_bfloat16* __restrict__ Xh,
                               __nv_bfloat16* __restrict__ Xl) {
    int row = blockIdx.x;
    int b = row / S_, s = row % S_;
    size_t base = (size_t)row * E_;
    int e = threadIdx.x;
    float val;
    if (s == 0) {
        val = emb[(size_t)1*E_ + e];
    } else {
        int k = s - 1;
        int sid = span[b*M_ + k];
        if (sid >= 0) {
            int p = pos2[b*M_ + sid];
            val = (p == 0 ? 0.0f : emb[(size_t)p*E_ + e]) + pe[(size_t)sid*E_ + e];
        } else {
            val = fbase[((size_t)b*M_ + k)*E_ + e];
        }
    }
    X[base + e] = val;
    __nv_bfloat16 h = __float2bfloat16_rn(val);
    Xh[base + e] = h;
    Xl[base + e] = __float2bfloat16_rn(val - __bfloat162float(h));
}

// ---------------- fused attention over the B axis (split output) ----------------
__global__ void attn_kernel(const float* __restrict__ QKV,
                            __nv_bfloat16* __restrict__ CXh,
                            __nv_bfloat16* __restrict__ CXl) {
    int z = blockIdx.x;
    int s = z / NHEAD_, h = z % NHEAD_;
    __shared__ float q[B_][DH_];
    __shared__ float k[B_][DH_];
    __shared__ float v[B_][DH_];
    __shared__ float sc[B_][B_ + 1];

    const float* base = QKV + (size_t)s * 3*E_ + (size_t)h * DH_;
    int t = threadIdx.x;

    for (int i = t; i < B_*DH_; i += 256) {
        int b = i / DH_, d = i % DH_;
        size_t off = (size_t)b * S_ * 3*E_ + d;
        q[b][d] = base[off];
        k[b][d] = base[off + E_];
        v[b][d] = base[off + 2*E_];
    }
    __syncthreads();

    for (int i = t; i < B_*B_; i += 256) {
        int l = i / B_, m = i % B_;
        float acc = 0.0f;
        #pragma unroll
        for (int d = 0; d < DH_; d++) acc += q[l][d] * k[m][d];
        sc[l][m] = acc * 0.125f;
    }
    __syncthreads();

    int warp = t >> 5, lane = t & 31;
    for (int l = warp; l < B_; l += 8) {
        float val = sc[l][lane];
        float mx = val;
        #pragma unroll
        for (int o = 16; o; o >>= 1) mx = fmaxf(mx, __shfl_xor_sync(0xffffffffu, mx, o));
        float e = expf(val - mx);
        float sum = e;
        #pragma unroll
        for (int o = 16; o; o >>= 1) sum += __shfl_xor_sync(0xffffffffu, sum, o);
        sc[l][lane] = e / sum;
    }
    __syncthreads();

    for (int i = t; i < B_*DH_; i += 256) {
        int l = i / DH_, d = i % DH_;
        float acc = 0.0f;
        #pragma unroll
        for (int m = 0; m < B_; m++) acc += sc[l][m] * v[m][d];
        size_t off = ((size_t)l * S_ + s) * E_ + (size_t)h * DH_ + d;
        __nv_bfloat16 hh = __float2bfloat16_rn(acc);
        CXh[off] = hh;
        CXl[off] = __float2bfloat16_rn(acc - __bfloat162float(hh));
    }
}

// ---------------- residual add + layernorm (+ split) ----------------
__global__ void add_ln_kernel(float* __restrict__ x, const float* __restrict__ y,
                              const float* __restrict__ w, const float* __restrict__ b,
                              __nv_bfloat16* __restrict__ Xh,
                              __nv_bfloat16* __restrict__ Xl) {
    long long row = blockIdx.x;
    __shared__ float red[256];
    int t = threadIdx.x;
    float v0 = x[row*E_ + t]       + y[row*E_ + t];
    float v1 = x[row*E_ + 256 + t] + y[row*E_ + 256 + t];
    red[t] = v0 + v1;
    __syncthreads();
    #pragma unroll
    for (int s2 = 128; s2 > 0; s2 >>= 1) { if (t < s2) red[t] += red[t + s2]; __syncthreads(); }
    float mean = red[0] * (1.0f / E_);
    __syncthreads();
    float d0 = v0 - mean, d1 = v1 - mean;
    red[t] = d0*d0 + d1*d1;
    __syncthreads();
    #pragma unroll
    for (int s2 = 128; s2 > 0; s2 >>= 1) { if (t < s2) red[t] += red[t + s2]; __syncthreads(); }
    float rstd = rsqrtf(red[0] * (1.0f / E_) + 1e-5f);
    float o0 = d0 * rstd * w[t]       + b[t];
    float o1 = d1 * rstd * w[t + 256] + b[t + 256];
    x[row*E_ + t]       = o0;
    x[row*E_ + 256 + t] = o1;
    __nv_bfloat16 h0 = __float2bfloat16_rn(o0);
    __nv_bfloat16 h1 = __float2bfloat16_rn(o1);
    Xh[row*E_ + t]       = h0;
    Xh[row*E_ + 256 + t] = h1;
    Xl[row*E_ + t]       = __float2bfloat16_rn(o0 - __bfloat162float(h0));
    Xl[row*E_ + 256 + t] = __float2bfloat16_rn(o1 - __bfloat162float(h1));
}

// ---------------- discriminator head ----------------
__global__ void disc_kernel(const float* __restrict__ bert,
                            const float* __restrict__ posf,
                            const float* __restrict__ wd,
                            const float* __restrict__ bd,
                            float* __restrict__ out, int ntok) {
    int n = (blockIdx.x * blockDim.x + threadIdx.x) >> 5;
    int lane = threadIdx.x & 31;
    if (n >= ntok) return;
    float acc = 0.0f;
    const float* br = bert + (size_t)n * F_;
    const float* pr = posf + (size_t)n * F_;
    for (int i = lane; i < F_; i += 32) acc += br[i] * wd[i];
    for (int i = lane; i < F_; i += 32) acc += pr[i] * wd[F_ + i];
    #pragma unroll
    for (int o = 16; o; o >>= 1) acc += __shfl_xor_sync(0xffffffffu, acc, o);
    if (lane == 0) out[n] = 1.0f / (1.0f + expf(-(acc + bd[0])));
}

// ---------------- host orchestration ----------------
static inline int cdiv(int a, int b) { return (a + b - 1) / b; }

extern "C" void kernel_launch(void* const* d_in, const int* in_sizes, int n_in,
                              void* d_out, int out_size) {
    const int*   pos1  = (const int*)d_in[0];
    const int*   pos2  = (const int*)d_in[1];
    const float* bert  = (const float*)d_in[2];
    const float* fbase = (const float*)d_in[3];
    const float* emb   = (const float*)d_in[4];
    const float* wqkv  = (const float*)d_in[5];
    const float* bqkv  = (const float*)d_in[6];
    const float* wo    = (const float*)d_in[7];
    const float* bo    = (const float*)d_in[8];
    const float* ln1w  = (const float*)d_in[9];
    const float* ln1b  = (const float*)d_in[10];
    const float* ln2w  = (const float*)d_in[11];
    const float* ln2b  = (const float*)d_in[12];
    const float* w1    = (const float*)d_in[13];
    const float* b1    = (const float*)d_in[14];
    const float* w2    = (const float*)d_in[15];
    const float* b2    = (const float*)d_in[16];
    const float* wm    = (const float*)d_in[17];
    const float* wd    = (const float*)d_in[18];
    const float* bd    = (const float*)d_in[19];
    float* out = (float*)d_out;

    float *PE, *X, *Y, *QKV, *POSF; int* SPAN;
    __nv_bfloat16 *Xh, *Xl, *CXh, *CXl, *Hh, *Hl;
    __nv_bfloat16 *WQh, *WQl, *WOh, *WOl, *W1h, *W1l, *W2h, *W2l, *WMh, *WMl;
    cudaGetSymbolAddress((void**)&PE,   d_PE);
    cudaGetSymbolAddress((void**)&SPAN, d_SPAN);
    cudaGetSymbolAddress((void**)&X,    d_X);
    cudaGetSymbolAddress((void**)&Y,    d_Y);
    cudaGetSymbolAddress((void**)&QKV,  d_QKV);
    cudaGetSymbolAddress((void**)&POSF, d_POSF);
    cudaGetSymbolAddress((void**)&Xh,  d_Xh);  cudaGetSymbolAddress((void**)&Xl,  d_Xl);
    cudaGetSymbolAddress((void**)&CXh, d_CXh); cudaGetSymbolAddress((void**)&CXl, d_CXl);
    cudaGetSymbolAddress((void**)&Hh,  d_Hh);  cudaGetSymbolAddress((void**)&Hl,  d_Hl);
    cudaGetSymbolAddress((void**)&WQh, d_WQh); cudaGetSymbolAddress((void**)&WQl, d_WQl);
    cudaGetSymbolAddress((void**)&WOh, d_WOh); cudaGetSymbolAddress((void**)&WOl, d_WOl);
    cudaGetSymbolAddress((void**)&W1h, d_W1h); cudaGetSymbolAddress((void**)&W1l, d_W1l);
    cudaGetSymbolAddress((void**)&W2h, d_W2h); cudaGetSymbolAddress((void**)&W2l, d_W2l);
    cudaGetSymbolAddress((void**)&WMh, d_WMh); cudaGetSymbolAddress((void**)&WMl, d_WMl);

    cudaFuncSetAttribute(gemm_tc, cudaFuncAttributeMaxDynamicSharedMemorySize, SMEM_GEMM);

    // ---- weight splits first (2 launches) so ncu idx 5 = QKV GEMM ----
    {   // launch 0: w1 + w2 + wm
        int n1 = 2*DFF_*E_/4, n2 = 2*E_*DFF_/4, n3 = F_*E_/4;
        split3_kernel<<<cdiv(n1+n2+n3,256),256>>>(w1, W1h, W1l, n1,
                                                  w2, W2h, W2l, n2,
                                                  wm, WMh, WMl, n3);
    }
    {   // launch 1: wqkv + wo
        int n1 = 2*3*E_*E_/4, n2 = 2*E_*E_/4;
        split2_kernel<<<cdiv(n1+n2,256),256>>>(wqkv, WQh, WQl, n1,
                                               wo,   WOh, WOl, n2);
    }
    // launches 2-4: preamble
    pe_kernel<<<cdiv(M_*E_, 256), 256>>>(PE);
    span_kernel<<<B_, M_>>>(pos1, SPAN);
    build_x_kernel<<<NTOK, 512>>>(pos2, fbase, emb, SPAN, PE, X, Xh, Xl);

    const int MY = cdiv(NTOK, BM);   // 129

    for (int l = 0; l < 2; l++) {
        const size_t oq = (size_t)l * 3*E_ * E_;
        const size_t oo = (size_t)l * E_ * E_;
        const size_t o1 = (size_t)l * DFF_ * E_;
        const size_t o2 = (size_t)l * E_ * DFF_;

        { dim3 g(3*E_/BN, MY);   // QKV  (launch idx 5 on first iter)
          gemm_tc<<<g, NTHR_G, SMEM_GEMM>>>(Xh, Xl, WQh+oq, WQl+oq,
              QKV, nullptr, nullptr, NTOK, 3*E_, E_, bqkv + l*3*E_, 0); }

        attn_kernel<<<S_*NHEAD_, 256>>>(QKV, CXh, CXl);

        { dim3 g(E_/BN, MY);     // Wo
          gemm_tc<<<g, NTHR_G, SMEM_GEMM>>>(CXh, CXl, WOh+oo, WOl+oo,
              Y, nullptr, nullptr, NTOK, E_, E_, bo + l*E_, 0); }

        add_ln_kernel<<<NTOK, 256>>>(X, Y, ln1w + l*E_, ln1b + l*E_, Xh, Xl);

        { dim3 g(DFF_/BN, MY);   // FFN1 -> split H
          gemm_tc<<<g, NTHR_G, SMEM_GEMM>>>(Xh, Xl, W1h+o1, W1l+o1,
              nullptr, Hh, Hl, NTOK, DFF_, E_, b1 + l*DFF_, 1); }

        { dim3 g(E_/BN, MY);     // FFN2
          gemm_tc<<<g, NTHR_G, SMEM_GEMM>>>(Hh, Hl, W2h+o2, W2l+o2,
              Y, nullptr, nullptr, NTOK, E_, DFF_, b2 + l*E_, 0); }

        add_ln_kernel<<<NTOK, 256>>>(X, Y, ln2w + l*E_, ln2b + l*E_, Xh, Xl);
    }

    { dim3 g(F_/BN, MY);         // pos_feature = tanh(X @ wm^T)
      gemm_tc<<<g, NTHR_G, SMEM_GEMM>>>(Xh, Xl, WMh, WMl,
          POSF, nullptr, nullptr, NTOK, F_, E_, nullptr, 2); }

    disc_kernel<<<cdiv(NTOK*32, 256), 256>>>(bert, POSF, wd, bd, out, NTOK);
}

// round 8
// speedup vs baseline: 7.8584x; 1.7331x over previous
#include <cuda_runtime.h>
#include <cuda_fp16.h>
#include <math.h>
#include <stdint.h>

// ---------------- problem constants ----------------
#define B_    32
#define M_    512
#define E_    512
#define S_    513
#define NTOK  (B_*S_)          // 16416
#define NHEAD_ 8
#define DH_   64
#define DFF_  2048
#define F_    768

// ---------------- fp32 scratch ----------------
__device__ float d_PE[M_*E_];
__device__ int   d_SPAN[B_*M_];
__device__ float d_X  [(size_t)NTOK*E_];
__device__ float d_Y  [(size_t)NTOK*E_];
__device__ float d_QKV[(size_t)NTOK*3*E_];
__device__ float d_POSF[(size_t)NTOK*F_];

// ---------------- fp16 operand buffers ----------------
__device__ __align__(16) __half d_Xf [(size_t)NTOK*E_];
__device__ __align__(16) __half d_CXf[(size_t)NTOK*E_];
__device__ __align__(16) __half d_Hf [(size_t)NTOK*DFF_];
__device__ __align__(16) __half d_WQf[(size_t)2*3*E_*E_];
__device__ __align__(16) __half d_WOf[(size_t)2*E_*E_];
__device__ __align__(16) __half d_W1f[(size_t)2*DFF_*E_];
__device__ __align__(16) __half d_W2f[(size_t)2*E_*DFF_];
__device__ __align__(16) __half d_WMf[(size_t)F_*E_];

// ================= fp16 tensor-core GEMM (single pass, fp32 accum) ========
#define BM 128
#define BN 256
#define BK 32
#define PADB 80                  // 64B data + 16B pad per row
#define A_ARR (128*PADB)         // 10240
#define B_ARR (256*PADB)         // 20480
#define STAGE (A_ARR + B_ARR)    // 30720
#define SMEM_GEMM (3*STAGE)      // 92160
#define NTHR_G 512

__device__ __forceinline__ uint32_t smem_u32(const void* p) {
    uint32_t a;
    asm("{ .reg .u64 t; cvta.to.shared.u64 t, %1; cvt.u32.u64 %0, t; }"
        : "=r"(a) : "l"(p));
    return a;
}
__device__ __forceinline__ void ldsm4(uint32_t* r, uint32_t addr) {
    asm volatile("ldmatrix.sync.aligned.m8n8.x4.shared.b16 {%0,%1,%2,%3}, [%4];"
        : "=r"(r[0]), "=r"(r[1]), "=r"(r[2]), "=r"(r[3]) : "r"(addr));
}
__device__ __forceinline__ void mma16816(float* c, const uint32_t* a, const uint32_t* b) {
    asm volatile(
        "mma.sync.aligned.m16n8k16.row.col.f32.f16.f16.f32 "
        "{%0,%1,%2,%3}, {%4,%5,%6,%7}, {%8,%9}, {%0,%1,%2,%3};"
        : "+f"(c[0]), "+f"(c[1]), "+f"(c[2]), "+f"(c[3])
        : "r"(a[0]), "r"(a[1]), "r"(a[2]), "r"(a[3]), "r"(b[0]), "r"(b[1]));
}
__device__ __forceinline__ void cpa16(uint32_t dst, const void* src, int srcsize) {
    asm volatile("cp.async.cg.shared.global [%0], [%1], 16, %2;"
                 :: "r"(dst), "l"(src), "r"(srcsize));
}

__device__ __forceinline__ void load_stage(
    uint32_t st,
    const __half* __restrict__ Af, const __half* __restrict__ Bf,
    int tile_m, int tile_n, int Mdim, int Kdim, int kc, int tid)
{
    const int k0 = kc * 32;
    {   // A: 128 rows x 4 x 16B  = 512 cp.asyncs
        int row = tid >> 2, c = tid & 3;
        const __half* src = Af + (size_t)(tile_m + row) * Kdim + k0 + c*8;
        cpa16(st + row*PADB + c*16, src, (tile_m + row) < Mdim ? 16 : 0);
    }
    #pragma unroll
    for (int i = 0; i < 2; i++) {   // B: 256 rows x 4 x 16B = 1024
        int id  = tid + NTHR_G*i;
        int row = id >> 2, c = id & 3;
        const __half* src = Bf + (size_t)(tile_n + row) * Kdim + k0 + c*8;
        cpa16(st + A_ARR + row*PADB + c*16, src, 16);
    }
    asm volatile("cp.async.commit_group;" ::: "memory");
}

__global__ __launch_bounds__(NTHR_G, 1)
void gemm_tc(const __half* __restrict__ Af, const __half* __restrict__ Bf,
             float* __restrict__ Cf, __half* __restrict__ Chalf,
             int Mdim, int Ndim, int Kdim,
             const float* __restrict__ bias, int act)
{
    extern __shared__ __align__(16) char smem[];
    const uint32_t sb = smem_u32(smem);
    const int tid    = threadIdx.x;
    const int tile_m = blockIdx.y * BM;
    const int tile_n = blockIdx.x * BN;
    const int warp = tid >> 5, lane = tid & 31;
    const int wm4 = warp >> 2, wn4 = warp & 3;    // 4(M) x 4(N), 32x64 warp tiles

    float acc[2][8][4];
    #pragma unroll
    for (int a = 0; a < 2; a++)
        #pragma unroll
        for (int b = 0; b < 8; b++)
            #pragma unroll
            for (int q = 0; q < 4; q++) acc[a][b][q] = 0.0f;

    const int nst = Kdim >> 5;
    load_stage(sb,         Af, Bf, tile_m, tile_n, Mdim, Kdim, 0, tid);
    load_stage(sb + STAGE, Af, Bf, tile_m, tile_n, Mdim, Kdim, 1, tid);

    const uint32_t a_off = (uint32_t)(wm4*32 + (lane & 7) + ((lane >> 3) & 1) * 8) * PADB
                         + ((lane >> 4) * 16);
    const uint32_t b_off = (uint32_t)(wn4*64 + (lane & 7) + ((lane >> 4) & 1) * 8) * PADB
                         + (((lane >> 3) & 1) * 16);

    for (int s = 0; s < nst; s++) {
        if (s + 1 < nst) asm volatile("cp.async.wait_group 1;" ::: "memory");
        else             asm volatile("cp.async.wait_group 0;" ::: "memory");
        __syncthreads();
        if (s + 2 < nst)
            load_stage(sb + ((s + 2) % 3) * STAGE, Af, Bf,
                       tile_m, tile_n, Mdim, Kdim, s + 2, tid);
        const uint32_t st = sb + (s % 3) * STAGE;

        #pragma unroll
        for (int ks = 0; ks < 2; ks++) {
            uint32_t ah[2][4];
            #pragma unroll
            for (int mi = 0; mi < 2; mi++)
                ldsm4(ah[mi], st + a_off + mi * (16 * PADB) + ks * 32);
            #pragma unroll
            for (int half = 0; half < 2; half++) {
                uint32_t bh[4][2];
                #pragma unroll
                for (int p = 0; p < 2; p++) {
                    uint32_t r[4];
                    ldsm4(r, st + A_ARR + b_off + (half*2 + p) * (16 * PADB) + ks * 32);
                    bh[2*p][0] = r[0]; bh[2*p][1] = r[1];
                    bh[2*p+1][0] = r[2]; bh[2*p+1][1] = r[3];
                }
                #pragma unroll
                for (int mi = 0; mi < 2; mi++)
                    #pragma unroll
                    for (int ni = 0; ni < 4; ni++)
                        mma16816(acc[mi][half*4+ni], ah[mi], bh[ni]);
            }
        }
    }

    // ---- epilogue ----
    const int er = lane >> 2;
    const int ec = (lane & 3) * 2;
    #pragma unroll
    for (int mi = 0; mi < 2; mi++) {
        const int gm0 = tile_m + wm4*32 + mi*16 + er;
        #pragma unroll
        for (int ni = 0; ni < 8; ni++) {
            const int gn = tile_n + wn4*64 + ni*8 + ec;
            float bx = 0.f, by = 0.f;
            if (bias) { float2 bb = *reinterpret_cast<const float2*>(bias + gn);
                        bx = bb.x; by = bb.y; }
            float v0 = acc[mi][ni][0] + bx, v1 = acc[mi][ni][1] + by;
            float v2 = acc[mi][ni][2] + bx, v3 = acc[mi][ni][3] + by;
            if (act == 1) {
                v0 = fmaxf(v0, 0.f); v1 = fmaxf(v1, 0.f);
                v2 = fmaxf(v2, 0.f); v3 = fmaxf(v3, 0.f);
            } else if (act == 2) {
                v0 = tanhf(v0); v1 = tanhf(v1); v2 = tanhf(v2); v3 = tanhf(v3);
            }
            if (Cf) {
                if (gm0 < Mdim)
                    *reinterpret_cast<float2*>(Cf + (size_t)gm0 * Ndim + gn) = make_float2(v0, v1);
                if (gm0 + 8 < Mdim)
                    *reinterpret_cast<float2*>(Cf + (size_t)(gm0+8) * Ndim + gn) = make_float2(v2, v3);
            } else {
                if (gm0 < Mdim) {
                    __half2 h; h.x = __float2half_rn(v0); h.y = __float2half_rn(v1);
                    *reinterpret_cast<__half2*>(Chalf + (size_t)gm0 * Ndim + gn) = h;
                }
                if (gm0 + 8 < Mdim) {
                    __half2 h; h.x = __float2half_rn(v2); h.y = __float2half_rn(v3);
                    *reinterpret_cast<__half2*>(Chalf + (size_t)(gm0+8) * Ndim + gn) = h;
                }
            }
        }
    }
}

// ---------------- fp32 -> fp16 convert (multi-tensor) ----------------
__device__ __forceinline__ void cvt_one(const float* in, __half* o, int i) {
    float4 v = *reinterpret_cast<const float4*>(in + (size_t)i * 4);
    __half2 h0, h1;
    h0.x = __float2half_rn(v.x); h0.y = __float2half_rn(v.y);
    h1.x = __float2half_rn(v.z); h1.y = __float2half_rn(v.w);
    uint2 u;
    u.x = *reinterpret_cast<uint32_t*>(&h0);
    u.y = *reinterpret_cast<uint32_t*>(&h1);
    *reinterpret_cast<uint2*>(o + (size_t)i * 4) = u;
}
__global__ void cvt3_kernel(const float* i1, __half* o1, int n1,
                            const float* i2, __half* o2, int n2,
                            const float* i3, __half* o3, int n3) {
    int i = blockIdx.x * blockDim.x + threadIdx.x;
    if (i < n1) { cvt_one(i1, o1, i); return; }
    i -= n1;
    if (i < n2) { cvt_one(i2, o2, i); return; }
    i -= n2;
    if (i < n3) cvt_one(i3, o3, i);
}
__global__ void cvt2_kernel(const float* i1, __half* o1, int n1,
                            const float* i2, __half* o2, int n2) {
    int i = blockIdx.x * blockDim.x + threadIdx.x;
    if (i < n1) { cvt_one(i1, o1, i); return; }
    i -= n1;
    if (i < n2) cvt_one(i2, o2, i);
}

// ---------------- fused span-id + PE table (one launch) ----------------
__global__ void spanpe_kernel(const int* __restrict__ pos1, int* __restrict__ span,
                              float* __restrict__ pe) {
    if (blockIdx.x < 32) {
        int b = blockIdx.x;
        int j = threadIdx.x;
        __shared__ int firstZero;
        span[b*M_ + j] = -1;
        if (j == 0) firstZero = M_;
        __syncthreads();
        int endv = pos1[((size_t)b*M_ + j)*2 + 1];
        if (endv == 0) atomicMin(&firstZero, j);
        __syncthreads();
        if (j < firstZero) {
            int st = pos1[((size_t)b*M_ + j)*2];
            int en = endv; if (en > M_) en = M_;
            for (int k = st; k < en; k++)
                atomicMax(&span[b*M_ + k], j);
        }
    } else {
        int idx = (blockIdx.x - 32) * 512 + threadIdx.x;   // 512 blocks cover M*E
        if (idx >= M_ * E_) return;
        int pos = idx / E_, i = idx % E_;
        double e2  = (double)((i / 2) * 2);
        double ang = (double)pos / pow(10000.0, e2 / (double)E_);
        pe[idx] = (float)((i % 2 == 0) ? sin(ang) : cos(ang));
    }
}

// ---------------- build x [B,S,E] + f16 copy ----------------
__global__ void build_x_kernel(const int* __restrict__ pos2,
                               const float* __restrict__ fbase,
                               const float* __restrict__ emb,
                               const int* __restrict__ span,
                               const float* __restrict__ pe,
                               float* __restrict__ X,
                               __half* __restrict__ Xf) {
    int row = blockIdx.x;
    int b = row / S_, s = row % S_;
    size_t base = (size_t)row * E_;
    int e = threadIdx.x;
    float val;
    if (s == 0) {
        val = emb[(size_t)1*E_ + e];
    } else {
        int k = s - 1;
        int sid = span[b*M_ + k];
        if (sid >= 0) {
            int p = pos2[b*M_ + sid];
            val = (p == 0 ? 0.0f : emb[(size_t)p*E_ + e]) + pe[(size_t)sid*E_ + e];
        } else {
            val = fbase[((size_t)b*M_ + k)*E_ + e];
        }
    }
    X[base + e] = val;
    Xf[base + e] = __float2half_rn(val);
}

// ---------------- fused attention over the B axis (f16 output) ----------------
__global__ void attn_kernel(const float* __restrict__ QKV,
                            __half* __restrict__ CXf) {
    int z = blockIdx.x;
    int s = z / NHEAD_, h = z % NHEAD_;
    __shared__ float q[B_][DH_];
    __shared__ float k[B_][DH_];
    __shared__ float v[B_][DH_];
    __shared__ float sc[B_][B_ + 1];

    const float* base = QKV + (size_t)s * 3*E_ + (size_t)h * DH_;
    int t = threadIdx.x;

    for (int i = t; i < B_*DH_; i += 256) {
        int b = i / DH_, d = i % DH_;
        size_t off = (size_t)b * S_ * 3*E_ + d;
        q[b][d] = base[off];
        k[b][d] = base[off + E_];
        v[b][d] = base[off + 2*E_];
    }
    __syncthreads();

    for (int i = t; i < B_*B_; i += 256) {
        int l = i / B_, m = i % B_;
        float acc = 0.0f;
        #pragma unroll
        for (int d = 0; d < DH_; d++) acc += q[l][d] * k[m][d];
        sc[l][m] = acc * 0.125f;
    }
    __syncthreads();

    int warp = t >> 5, lane = t & 31;
    for (int l = warp; l < B_; l += 8) {
        float val = sc[l][lane];
        float mx = val;
        #pragma unroll
        for (int o = 16; o; o >>= 1) mx = fmaxf(mx, __shfl_xor_sync(0xffffffffu, mx, o));
        float e = expf(val - mx);
        float sum = e;
        #pragma unroll
        for (int o = 16; o; o >>= 1) sum += __shfl_xor_sync(0xffffffffu, sum, o);
        sc[l][lane] = e / sum;
    }
    __syncthreads();

    for (int i = t; i < B_*DH_; i += 256) {
        int l = i / DH_, d = i % DH_;
        float acc = 0.0f;
        #pragma unroll
        for (int m = 0; m < B_; m++) acc += sc[l][m] * v[m][d];
        CXf[((size_t)l * S_ + s) * E_ + (size_t)h * DH_ + d] = __float2half_rn(acc);
    }
}

// ---------------- residual add + layernorm (+ f16 copy) ----------------
__global__ void add_ln_kernel(float* __restrict__ x, const float* __restrict__ y,
                              const float* __restrict__ w, const float* __restrict__ b,
                              __half* __restrict__ Xf) {
    long long row = blockIdx.x;
    __shared__ float red[256];
    int t = threadIdx.x;
    float v0 = x[row*E_ + t]       + y[row*E_ + t];
    float v1 = x[row*E_ + 256 + t] + y[row*E_ + 256 + t];
    red[t] = v0 + v1;
    __syncthreads();
    #pragma unroll
    for (int s2 = 128; s2 > 0; s2 >>= 1) { if (t < s2) red[t] += red[t + s2]; __syncthreads(); }
    float mean = red[0] * (1.0f / E_);
    __syncthreads();
    float d0 = v0 - mean, d1 = v1 - mean;
    red[t] = d0*d0 + d1*d1;
    __syncthreads();
    #pragma unroll
    for (int s2 = 128; s2 > 0; s2 >>= 1) { if (t < s2) red[t] += red[t + s2]; __syncthreads(); }
    float rstd = rsqrtf(red[0] * (1.0f / E_) + 1e-5f);
    float o0 = d0 * rstd * w[t]       + b[t];
    float o1 = d1 * rstd * w[t + 256] + b[t + 256];
    x[row*E_ + t]       = o0;
    x[row*E_ + 256 + t] = o1;
    Xf[row*E_ + t]       = __float2half_rn(o0);
    Xf[row*E_ + 256 + t] = __float2half_rn(o1);
}

// ---------------- discriminator head ----------------
__global__ void disc_kernel(const float* __restrict__ bert,
                            const float* __restrict__ posf,
                            const float* __restrict__ wd,
                            const float* __restrict__ bd,
                            float* __restrict__ out, int ntok) {
    int n = (blockIdx.x * blockDim.x + threadIdx.x) >> 5;
    int lane = threadIdx.x & 31;
    if (n >= ntok) return;
    float acc = 0.0f;
    const float* br = bert + (size_t)n * F_;
    const float* pr = posf + (size_t)n * F_;
    for (int i = lane; i < F_; i += 32) acc += br[i] * wd[i];
    for (int i = lane; i < F_; i += 32) acc += pr[i] * wd[F_ + i];
    #pragma unroll
    for (int o = 16; o; o >>= 1) acc += __shfl_xor_sync(0xffffffffu, acc, o);
    if (lane == 0) out[n] = 1.0f / (1.0f + expf(-(acc + bd[0])));
}

// ---------------- host orchestration ----------------
static inline int cdiv(int a, int b) { return (a + b - 1) / b; }

extern "C" void kernel_launch(void* const* d_in, const int* in_sizes, int n_in,
                              void* d_out, int out_size) {
    const int*   pos1  = (const int*)d_in[0];
    const int*   pos2  = (const int*)d_in[1];
    const float* bert  = (const float*)d_in[2];
    const float* fbase = (const float*)d_in[3];
    const float* emb   = (const float*)d_in[4];
    const float* wqkv  = (const float*)d_in[5];
    const float* bqkv  = (const float*)d_in[6];
    const float* wo    = (const float*)d_in[7];
    const float* bo    = (const float*)d_in[8];
    const float* ln1w  = (const float*)d_in[9];
    const float* ln1b  = (const float*)d_in[10];
    const float* ln2w  = (const float*)d_in[11];
    const float* ln2b  = (const float*)d_in[12];
    const float* w1    = (const float*)d_in[13];
    const float* b1    = (const float*)d_in[14];
    const float* w2    = (const float*)d_in[15];
    const float* b2    = (const float*)d_in[16];
    const float* wm    = (const float*)d_in[17];
    const float* wd    = (const float*)d_in[18];
    const float* bd    = (const float*)d_in[19];
    float* out = (float*)d_out;

    float *PE, *X, *Y, *QKV, *POSF; int* SPAN;
    __half *Xf, *CXf, *Hf, *WQf, *WOf, *W1f, *W2f, *WMf;
    cudaGetSymbolAddress((void**)&PE,   d_PE);
    cudaGetSymbolAddress((void**)&SPAN, d_SPAN);
    cudaGetSymbolAddress((void**)&X,    d_X);
    cudaGetSymbolAddress((void**)&Y,    d_Y);
    cudaGetSymbolAddress((void**)&QKV,  d_QKV);
    cudaGetSymbolAddress((void**)&POSF, d_POSF);
    cudaGetSymbolAddress((void**)&Xf,  d_Xf);
    cudaGetSymbolAddress((void**)&CXf, d_CXf);
    cudaGetSymbolAddress((void**)&Hf,  d_Hf);
    cudaGetSymbolAddress((void**)&WQf, d_WQf);
    cudaGetSymbolAddress((void**)&WOf, d_WOf);
    cudaGetSymbolAddress((void**)&W1f, d_W1f);
    cudaGetSymbolAddress((void**)&W2f, d_W2f);
    cudaGetSymbolAddress((void**)&WMf, d_WMf);

    cudaFuncSetAttribute(gemm_tc, cudaFuncAttributeMaxDynamicSharedMemorySize, SMEM_GEMM);

    // launch 0: convert wqkv + wo (needed by launch 3)
    {
        int n1 = 2*3*E_*E_/4, n2 = 2*E_*E_/4;
        cvt2_kernel<<<cdiv(n1+n2,256),256>>>(wqkv, WQf, n1, wo, WOf, n2);
    }
    // launch 1: fused span + PE
    spanpe_kernel<<<32 + cdiv(M_*E_, 512), 512>>>(pos1, SPAN, PE);
    // launch 2: build x
    build_x_kernel<<<NTOK, 512>>>(pos2, fbase, emb, SPAN, PE, X, Xf);

    const int MY = cdiv(NTOK, BM);   // 129
    bool cvt3_done = false;

    for (int l = 0; l < 2; l++) {
        const size_t oq = (size_t)l * 3*E_ * E_;
        const size_t oo = (size_t)l * E_ * E_;
        const size_t o1 = (size_t)l * DFF_ * E_;
        const size_t o2 = (size_t)l * E_ * DFF_;

        { dim3 g(3*E_/BN, MY);   // QKV  (launch 3 on layer 0 -> ncu target)
          gemm_tc<<<g, NTHR_G, SMEM_GEMM>>>(Xf, WQf+oq,
              QKV, nullptr, NTOK, 3*E_, E_, bqkv + l*3*E_, 0); }

        if (!cvt3_done) {        // launch 4: convert w1 + w2 + wm
            int n1 = 2*DFF_*E_/4, n2 = 2*E_*DFF_/4, n3 = F_*E_/4;
            cvt3_kernel<<<cdiv(n1+n2+n3,256),256>>>(w1, W1f, n1,
                                                    w2, W2f, n2,
                                                    wm, WMf, n3);
            cvt3_done = true;
        }

        attn_kernel<<<S_*NHEAD_, 256>>>(QKV, CXf);

        { dim3 g(E_/BN, MY);     // Wo
          gemm_tc<<<g, NTHR_G, SMEM_GEMM>>>(CXf, WOf+oo,
              Y, nullptr, NTOK, E_, E_, bo + l*E_, 0); }

        add_ln_kernel<<<NTOK, 256>>>(X, Y, ln1w + l*E_, ln1b + l*E_, Xf);

        { dim3 g(DFF_/BN, MY);   // FFN1 -> f16 H
          gemm_tc<<<g, NTHR_G, SMEM_GEMM>>>(Xf, W1f+o1,
              nullptr, Hf, NTOK, DFF_, E_, b1 + l*DFF_, 1); }

        { dim3 g(E_/BN, MY);     // FFN2
          gemm_tc<<<g, NTHR_G, SMEM_GEMM>>>(Hf, W2f+o2,
              Y, nullptr, NTOK, E_, DFF_, b2 + l*E_, 0); }

        add_ln_kernel<<<NTOK, 256>>>(X, Y, ln2w + l*E_, ln2b + l*E_, Xf);
    }

    { dim3 g(F_/BN, MY);         // pos_feature = tanh(X @ wm^T)
      gemm_tc<<<g, NTHR_G, SMEM_GEMM>>>(Xf, WMf,
          POSF, nullptr, NTOK, F_, E_, nullptr, 2); }

    disc_kernel<<<cdiv(NTOK*32, 256), 256>>>(bert, POSF, wd, bd, out, NTOK);
}

// round 9
// speedup vs baseline: 8.3586x; 1.0636x over previous
#include <cuda_runtime.h>
#include <cuda_fp16.h>
#include <math.h>
#include <stdint.h>

// ---------------- problem constants ----------------
#define B_    32
#define M_    512
#define E_    512
#define S_    513
#define NTOK  (B_*S_)          // 16416
#define NHEAD_ 8
#define DH_   64
#define DFF_  2048
#define F_    768

// ---------------- fp32 scratch ----------------
__device__ float d_PE[M_*E_];
__device__ int   d_SPAN[B_*M_];
__device__ float d_X  [(size_t)NTOK*E_];
__device__ float d_Y  [(size_t)NTOK*E_];
__device__ float d_QKV[(size_t)NTOK*3*E_];
__device__ float d_POSF[(size_t)NTOK*F_];

// ---------------- fp16 operand buffers ----------------
__device__ __align__(16) __half d_Xf [(size_t)NTOK*E_];
__device__ __align__(16) __half d_CXf[(size_t)NTOK*E_];
__device__ __align__(16) __half d_Hf [(size_t)NTOK*DFF_];
__device__ __align__(16) __half d_WQf[(size_t)2*3*E_*E_];
__device__ __align__(16) __half d_WOf[(size_t)2*E_*E_];
__device__ __align__(16) __half d_W1f[(size_t)2*DFF_*E_];
__device__ __align__(16) __half d_W2f[(size_t)2*E_*DFF_];
__device__ __align__(16) __half d_WMf[(size_t)F_*E_];

// ================= fp16 tensor-core GEMM (2 CTAs/SM) ========
#define BM 128
#define BN 128
#define BK 32
#define PADB 80                  // 64B data + 16B pad per row
#define A_ARR (128*PADB)         // 10240
#define B_ARR (128*PADB)         // 10240
#define STAGE (A_ARR + B_ARR)    // 20480
#define NSTAGE 4
#define SMEM_GEMM (NSTAGE*STAGE) // 81920
#define NTHR_G 256

__device__ __forceinline__ uint32_t smem_u32(const void* p) {
    uint32_t a;
    asm("{ .reg .u64 t; cvta.to.shared.u64 t, %1; cvt.u32.u64 %0, t; }"
        : "=r"(a) : "l"(p));
    return a;
}
__device__ __forceinline__ void ldsm4(uint32_t* r, uint32_t addr) {
    asm volatile("ldmatrix.sync.aligned.m8n8.x4.shared.b16 {%0,%1,%2,%3}, [%4];"
        : "=r"(r[0]), "=r"(r[1]), "=r"(r[2]), "=r"(r[3]) : "r"(addr));
}
__device__ __forceinline__ void mma16816(float* c, const uint32_t* a, const uint32_t* b) {
    asm volatile(
        "mma.sync.aligned.m16n8k16.row.col.f32.f16.f16.f32 "
        "{%0,%1,%2,%3}, {%4,%5,%6,%7}, {%8,%9}, {%0,%1,%2,%3};"
        : "+f"(c[0]), "+f"(c[1]), "+f"(c[2]), "+f"(c[3])
        : "r"(a[0]), "r"(a[1]), "r"(a[2]), "r"(a[3]), "r"(b[0]), "r"(b[1]));
}
__device__ __forceinline__ void cpa16(uint32_t dst, const void* src, int srcsize) {
    asm volatile("cp.async.cg.shared.global [%0], [%1], 16, %2;"
                 :: "r"(dst), "l"(src), "r"(srcsize));
}

__device__ __forceinline__ void load_stage(
    uint32_t st,
    const __half* __restrict__ Af, const __half* __restrict__ Bf,
    int tile_m, int tile_n, int Mdim, int Kdim, int kc, int tid)
{
    const int k0 = kc * 32;
    #pragma unroll
    for (int i = 0; i < 2; i++) {   // A: 128 rows x 4 x 16B = 512 cp
        int id = tid + NTHR_G*i;
        int row = id >> 2, c = id & 3;
        const __half* src = Af + (size_t)(tile_m + row) * Kdim + k0 + c*8;
        cpa16(st + row*PADB + c*16, src, (tile_m + row) < Mdim ? 16 : 0);
    }
    #pragma unroll
    for (int i = 0; i < 2; i++) {   // B: 128 rows x 4 x 16B = 512 cp
        int id = tid + NTHR_G*i;
        int row = id >> 2, c = id & 3;
        const __half* src = Bf + (size_t)(tile_n + row) * Kdim + k0 + c*8;
        cpa16(st + A_ARR + row*PADB + c*16, src, 16);
    }
    asm volatile("cp.async.commit_group;" ::: "memory");
}

__global__ __launch_bounds__(NTHR_G, 2)
void gemm_tc(const __half* __restrict__ Af, const __half* __restrict__ Bf,
             float* __restrict__ Cf, __half* __restrict__ Chalf,
             int Mdim, int Ndim, int Kdim,
             const float* __restrict__ bias, int act)
{
    extern __shared__ __align__(16) char smem[];
    const uint32_t sb = smem_u32(smem);
    const int tid    = threadIdx.x;
    const int tile_m = blockIdx.y * BM;
    const int tile_n = blockIdx.x * BN;
    const int warp = tid >> 5, lane = tid & 31;
    const int wm2 = warp >> 2, wn4 = warp & 3;    // 2(M) x 4(N), 64x32 warp tiles

    float acc[4][4][4];
    #pragma unroll
    for (int a = 0; a < 4; a++)
        #pragma unroll
        for (int b = 0; b < 4; b++)
            #pragma unroll
            for (int q = 0; q < 4; q++) acc[a][b][q] = 0.0f;

    const int nst = Kdim >> 5;
    load_stage(sb,           Af, Bf, tile_m, tile_n, Mdim, Kdim, 0, tid);
    load_stage(sb +   STAGE, Af, Bf, tile_m, tile_n, Mdim, Kdim, 1, tid);
    load_stage(sb + 2*STAGE, Af, Bf, tile_m, tile_n, Mdim, Kdim, 2, tid);

    const uint32_t a_off = (uint32_t)(wm2*64 + (lane & 7) + ((lane >> 3) & 1) * 8) * PADB
                         + ((lane >> 4) * 16);
    const uint32_t b_off = (uint32_t)(wn4*32 + (lane & 7) + ((lane >> 4) & 1) * 8) * PADB
                         + (((lane >> 3) & 1) * 16);

    for (int s = 0; s < nst; s++) {
        if (s + 3 < nst)      asm volatile("cp.async.wait_group 2;" ::: "memory");
        else if (s + 2 < nst) asm volatile("cp.async.wait_group 1;" ::: "memory");
        else                  asm volatile("cp.async.wait_group 0;" ::: "memory");
        __syncthreads();
        if (s + 3 < nst)
            load_stage(sb + ((s + 3) % NSTAGE) * STAGE, Af, Bf,
                       tile_m, tile_n, Mdim, Kdim, s + 3, tid);
        const uint32_t st = sb + (s % NSTAGE) * STAGE;

        #pragma unroll
        for (int ks = 0; ks < 2; ks++) {
            uint32_t ah[4][4], bh[4][2];
            #pragma unroll
            for (int mi = 0; mi < 4; mi++)
                ldsm4(ah[mi], st + a_off + mi * (16 * PADB) + ks * 32);
            #pragma unroll
            for (int p = 0; p < 2; p++) {
                uint32_t r[4];
                ldsm4(r, st + A_ARR + b_off + p * (16 * PADB) + ks * 32);
                bh[2*p][0] = r[0]; bh[2*p][1] = r[1];
                bh[2*p+1][0] = r[2]; bh[2*p+1][1] = r[3];
            }
            #pragma unroll
            for (int mi = 0; mi < 4; mi++)
                #pragma unroll
                for (int ni = 0; ni < 4; ni++)
                    mma16816(acc[mi][ni], ah[mi], bh[ni]);
        }
    }

    // ---- epilogue ----
    const int er = lane >> 2;
    const int ec = (lane & 3) * 2;
    #pragma unroll
    for (int mi = 0; mi < 4; mi++) {
        const int gm0 = tile_m + wm2*64 + mi*16 + er;
        #pragma unroll
        for (int ni = 0; ni < 4; ni++) {
            const int gn = tile_n + wn4*32 + ni*8 + ec;
            float bx = 0.f, by = 0.f;
            if (bias) { float2 bb = *reinterpret_cast<const float2*>(bias + gn);
                        bx = bb.x; by = bb.y; }
            float v0 = acc[mi][ni][0] + bx, v1 = acc[mi][ni][1] + by;
            float v2 = acc[mi][ni][2] + bx, v3 = acc[mi][ni][3] + by;
            if (act == 1) {
                v0 = fmaxf(v0, 0.f); v1 = fmaxf(v1, 0.f);
                v2 = fmaxf(v2, 0.f); v3 = fmaxf(v3, 0.f);
            } else if (act == 2) {
                v0 = tanhf(v0); v1 = tanhf(v1); v2 = tanhf(v2); v3 = tanhf(v3);
            }
            if (Cf) {
                if (gm0 < Mdim)
                    *reinterpret_cast<float2*>(Cf + (size_t)gm0 * Ndim + gn) = make_float2(v0, v1);
                if (gm0 + 8 < Mdim)
                    *reinterpret_cast<float2*>(Cf + (size_t)(gm0+8) * Ndim + gn) = make_float2(v2, v3);
            } else {
                if (gm0 < Mdim) {
                    __half2 h; h.x = __float2half_rn(v0); h.y = __float2half_rn(v1);
                    *reinterpret_cast<__half2*>(Chalf + (size_t)gm0 * Ndim + gn) = h;
                }
                if (gm0 + 8 < Mdim) {
                    __half2 h; h.x = __float2half_rn(v2); h.y = __float2half_rn(v3);
                    *reinterpret_cast<__half2*>(Chalf + (size_t)(gm0+8) * Ndim + gn) = h;
                }
            }
        }
    }
}

// ---------------- fp32 -> fp16 convert (multi-tensor) ----------------
__device__ __forceinline__ void cvt_one(const float* in, __half* o, int i) {
    float4 v = *reinterpret_cast<const float4*>(in + (size_t)i * 4);
    __half2 h0, h1;
    h0.x = __float2half_rn(v.x); h0.y = __float2half_rn(v.y);
    h1.x = __float2half_rn(v.z); h1.y = __float2half_rn(v.w);
    uint2 u;
    u.x = *reinterpret_cast<uint32_t*>(&h0);
    u.y = *reinterpret_cast<uint32_t*>(&h1);
    *reinterpret_cast<uint2*>(o + (size_t)i * 4) = u;
}
__global__ void cvt3_kernel(const float* i1, __half* o1, int n1,
                            const float* i2, __half* o2, int n2,
                            const float* i3, __half* o3, int n3) {
    int i = blockIdx.x * blockDim.x + threadIdx.x;
    if (i < n1) { cvt_one(i1, o1, i); return; }
    i -= n1;
    if (i < n2) { cvt_one(i2, o2, i); return; }
    i -= n2;
    if (i < n3) cvt_one(i3, o3, i);
}
__global__ void cvt2_kernel(const float* i1, __half* o1, int n1,
                            const float* i2, __half* o2, int n2) {
    int i = blockIdx.x * blockDim.x + threadIdx.x;
    if (i < n1) { cvt_one(i1, o1, i); return; }
    i -= n1;
    if (i < n2) cvt_one(i2, o2, i);
}

// ---------------- fused span-id + PE table (one launch) ----------------
__global__ void spanpe_kernel(const int* __restrict__ pos1, int* __restrict__ span,
                              float* __restrict__ pe) {
    if (blockIdx.x < 32) {
        int b = blockIdx.x;
        int j = threadIdx.x;
        __shared__ int firstZero;
        span[b*M_ + j] = -1;
        if (j == 0) firstZero = M_;
        __syncthreads();
        int endv = pos1[((size_t)b*M_ + j)*2 + 1];
        if (endv == 0) atomicMin(&firstZero, j);
        __syncthreads();
        if (j < firstZero) {
            int st = pos1[((size_t)b*M_ + j)*2];
            int en = endv; if (en > M_) en = M_;
            for (int k = st; k < en; k++)
                atomicMax(&span[b*M_ + k], j);
        }
    } else {
        int idx = (blockIdx.x - 32) * 512 + threadIdx.x;
        if (idx >= M_ * E_) return;
        int pos = idx / E_, i = idx % E_;
        double e2  = (double)((i / 2) * 2);
        double ang = (double)pos / pow(10000.0, e2 / (double)E_);
        pe[idx] = (float)((i % 2 == 0) ? sin(ang) : cos(ang));
    }
}

// ---------------- build x [B,S,E] + f16 copy ----------------
__global__ void build_x_kernel(const int* __restrict__ pos2,
                               const float* __restrict__ fbase,
                               const float* __restrict__ emb,
                               const int* __restrict__ span,
                               const float* __restrict__ pe,
                               float* __restrict__ X,
                               __half* __restrict__ Xf) {
    int row = blockIdx.x;
    int b = row / S_, s = row % S_;
    size_t base = (size_t)row * E_;
    int e = threadIdx.x;
    float val;
    if (s == 0) {
        val = emb[(size_t)1*E_ + e];
    } else {
        int k = s - 1;
        int sid = span[b*M_ + k];
        if (sid >= 0) {
            int p = pos2[b*M_ + sid];
            val = (p == 0 ? 0.0f : emb[(size_t)p*E_ + e]) + pe[(size_t)sid*E_ + e];
        } else {
            val = fbase[((size_t)b*M_ + k)*E_ + e];
        }
    }
    X[base + e] = val;
    Xf[base + e] = __float2half_rn(val);
}

// ---------------- fused attention over the B axis (f16 output) ----------------
__global__ void attn_kernel(const float* __restrict__ QKV,
                            __half* __restrict__ CXf) {
    int z = blockIdx.x;
    int s = z / NHEAD_, h = z % NHEAD_;
    __shared__ float q[B_][DH_];
    __shared__ float k[B_][DH_];
    __shared__ float v[B_][DH_];
    __shared__ float sc[B_][B_ + 1];

    const float* base = QKV + (size_t)s * 3*E_ + (size_t)h * DH_;
    int t = threadIdx.x;

    for (int i = t; i < B_*DH_; i += 256) {
        int b = i / DH_, d = i % DH_;
        size_t off = (size_t)b * S_ * 3*E_ + d;
        q[b][d] = base[off];
        k[b][d] = base[off + E_];
        v[b][d] = base[off + 2*E_];
    }
    __syncthreads();

    for (int i = t; i < B_*B_; i += 256) {
        int l = i / B_, m = i % B_;
        float acc = 0.0f;
        #pragma unroll
        for (int d = 0; d < DH_; d++) acc += q[l][d] * k[m][d];
        sc[l][m] = acc * 0.125f;
    }
    __syncthreads();

    int warp = t >> 5, lane = t & 31;
    for (int l = warp; l < B_; l += 8) {
        float val = sc[l][lane];
        float mx = val;
        #pragma unroll
        for (int o = 16; o; o >>= 1) mx = fmaxf(mx, __shfl_xor_sync(0xffffffffu, mx, o));
        float e = expf(val - mx);
        float sum = e;
        #pragma unroll
        for (int o = 16; o; o >>= 1) sum += __shfl_xor_sync(0xffffffffu, sum, o);
        sc[l][lane] = e / sum;
    }
    __syncthreads();

    for (int i = t; i < B_*DH_; i += 256) {
        int l = i / DH_, d = i % DH_;
        float acc = 0.0f;
        #pragma unroll
        for (int m = 0; m < B_; m++) acc += sc[l][m] * v[m][d];
        CXf[((size_t)l * S_ + s) * E_ + (size_t)h * DH_ + d] = __float2half_rn(acc);
    }
}

// ---------------- residual add + layernorm (+ f16 copy) ----------------
__global__ void add_ln_kernel(float* __restrict__ x, const float* __restrict__ y,
                              const float* __restrict__ w, const float* __restrict__ b,
                              __half* __restrict__ Xf) {
    long long row = blockIdx.x;
    __shared__ float red[256];
    int t = threadIdx.x;
    float v0 = x[row*E_ + t]       + y[row*E_ + t];
    float v1 = x[row*E_ + 256 + t] + y[row*E_ + 256 + t];
    red[t] = v0 + v1;
    __syncthreads();
    #pragma unroll
    for (int s2 = 128; s2 > 0; s2 >>= 1) { if (t < s2) red[t] += red[t + s2]; __syncthreads(); }
    float mean = red[0] * (1.0f / E_);
    __syncthreads();
    float d0 = v0 - mean, d1 = v1 - mean;
    red[t] = d0*d0 + d1*d1;
    __syncthreads();
    #pragma unroll
    for (int s2 = 128; s2 > 0; s2 >>= 1) { if (t < s2) red[t] += red[t + s2]; __syncthreads(); }
    float rstd = rsqrtf(red[0] * (1.0f / E_) + 1e-5f);
    float o0 = d0 * rstd * w[t]       + b[t];
    float o1 = d1 * rstd * w[t + 256] + b[t + 256];
    x[row*E_ + t]       = o0;
    x[row*E_ + 256 + t] = o1;
    Xf[row*E_ + t]       = __float2half_rn(o0);
    Xf[row*E_ + 256 + t] = __float2half_rn(o1);
}

// ---------------- discriminator head ----------------
__global__ void disc_kernel(const float* __restrict__ bert,
                            const float* __restrict__ posf,
                            const float* __restrict__ wd,
                            const float* __restrict__ bd,
                            float* __restrict__ out, int ntok) {
    int n = (blockIdx.x * blockDim.x + threadIdx.x) >> 5;
    int lane = threadIdx.x & 31;
    if (n >= ntok) return;
    float acc = 0.0f;
    const float* br = bert + (size_t)n * F_;
    const float* pr = posf + (size_t)n * F_;
    for (int i = lane; i < F_; i += 32) acc += br[i] * wd[i];
    for (int i = lane; i < F_; i += 32) acc += pr[i] * wd[F_ + i];
    #pragma unroll
    for (int o = 16; o; o >>= 1) acc += __shfl_xor_sync(0xffffffffu, acc, o);
    if (lane == 0) out[n] = 1.0f / (1.0f + expf(-(acc + bd[0])));
}

// ---------------- host orchestration ----------------
static inline int cdiv(int a, int b) { return (a + b - 1) / b; }

extern "C" void kernel_launch(void* const* d_in, const int* in_sizes, int n_in,
                              void* d_out, int out_size) {
    const int*   pos1  = (const int*)d_in[0];
    const int*   pos2  = (const int*)d_in[1];
    const float* bert  = (const float*)d_in[2];
    const float* fbase = (const float*)d_in[3];
    const float* emb   = (const float*)d_in[4];
    const float* wqkv  = (const float*)d_in[5];
    const float* bqkv  = (const float*)d_in[6];
    const float* wo    = (const float*)d_in[7];
    const float* bo    = (const float*)d_in[8];
    const float* ln1w  = (const float*)d_in[9];
    const float* ln1b  = (const float*)d_in[10];
    const float* ln2w  = (const float*)d_in[11];
    const float* ln2b  = (const float*)d_in[12];
    const float* w1    = (const float*)d_in[13];
    const float* b1    = (const float*)d_in[14];
    const float* w2    = (const float*)d_in[15];
    const float* b2    = (const float*)d_in[16];
    const float* wm    = (const float*)d_in[17];
    const float* wd    = (const float*)d_in[18];
    const float* bd    = (const float*)d_in[19];
    float* out = (float*)d_out;

    float *PE, *X, *Y, *QKV, *POSF; int* SPAN;
    __half *Xf, *CXf, *Hf, *WQf, *WOf, *W1f, *W2f, *WMf;
    cudaGetSymbolAddress((void**)&PE,   d_PE);
    cudaGetSymbolAddress((void**)&SPAN, d_SPAN);
    cudaGetSymbolAddress((void**)&X,    d_X);
    cudaGetSymbolAddress((void**)&Y,    d_Y);
    cudaGetSymbolAddress((void**)&QKV,  d_QKV);
    cudaGetSymbolAddress((void**)&POSF, d_POSF);
    cudaGetSymbolAddress((void**)&Xf,  d_Xf);
    cudaGetSymbolAddress((void**)&CXf, d_CXf);
    cudaGetSymbolAddress((void**)&Hf,  d_Hf);
    cudaGetSymbolAddress((void**)&WQf, d_WQf);
    cudaGetSymbolAddress((void**)&WOf, d_WOf);
    cudaGetSymbolAddress((void**)&W1f, d_W1f);
    cudaGetSymbolAddress((void**)&W2f, d_W2f);
    cudaGetSymbolAddress((void**)&WMf, d_WMf);

    cudaFuncSetAttribute(gemm_tc, cudaFuncAttributeMaxDynamicSharedMemorySize, SMEM_GEMM);

    // launch 0: convert wqkv + wo
    {
        int n1 = 2*3*E_*E_/4, n2 = 2*E_*E_/4;
        cvt2_kernel<<<cdiv(n1+n2,256),256>>>(wqkv, WQf, n1, wo, WOf, n2);
    }
    // launch 1: fused span + PE
    spanpe_kernel<<<32 + cdiv(M_*E_, 512), 512>>>(pos1, SPAN, PE);
    // launch 2: build x
    build_x_kernel<<<NTOK, 512>>>(pos2, fbase, emb, SPAN, PE, X, Xf);

    const int MY = cdiv(NTOK, BM);   // 129
    bool cvt3_done = false;

    for (int l = 0; l < 2; l++) {
        const size_t oq = (size_t)l * 3*E_ * E_;
        const size_t oo = (size_t)l * E_ * E_;
        const size_t o1 = (size_t)l * DFF_ * E_;
        const size_t o2 = (size_t)l * E_ * DFF_;

        { dim3 g(3*E_/BN, MY);   // QKV  (launch 3, layer 0 -> ncu target)
          gemm_tc<<<g, NTHR_G, SMEM_GEMM>>>(Xf, WQf+oq,
              QKV, nullptr, NTOK, 3*E_, E_, bqkv + l*3*E_, 0); }

        if (!cvt3_done) {        // launch 4: convert w1 + w2 + wm
            int n1 = 2*DFF_*E_/4, n2 = 2*E_*DFF_/4, n3 = F_*E_/4;
            cvt3_kernel<<<cdiv(n1+n2+n3,256),256>>>(w1, W1f, n1,
                                                    w2, W2f, n2,
                                                    wm, WMf, n3);
            cvt3_done = true;
        }

        attn_kernel<<<S_*NHEAD_, 256>>>(QKV, CXf);

        { dim3 g(E_/BN, MY);     // Wo
          gemm_tc<<<g, NTHR_G, SMEM_GEMM>>>(CXf, WOf+oo,
              Y, nullptr, NTOK, E_, E_, bo + l*E_, 0); }

        add_ln_kernel<<<NTOK, 256>>>(X, Y, ln1w + l*E_, ln1b + l*E_, Xf);

        { dim3 g(DFF_/BN, MY);   // FFN1 -> f16 H
          gemm_tc<<<g, NTHR_G, SMEM_GEMM>>>(Xf, W1f+o1,
              nullptr, Hf, NTOK, DFF_, E_, b1 + l*DFF_, 1); }

        { dim3 g(E_/BN, MY);     // FFN2
          gemm_tc<<<g, NTHR_G, SMEM_GEMM>>>(Hf, W2f+o2,
              Y, nullptr, NTOK, E_, DFF_, b2 + l*E_, 0); }

        add_ln_kernel<<<NTOK, 256>>>(X, Y, ln2w + l*E_, ln2b + l*E_, Xf);
    }

    { dim3 g(F_/BN, MY);         // pos_feature = tanh(X @ wm^T)
      gemm_tc<<<g, NTHR_G, SMEM_GEMM>>>(Xf, WMf,
          POSF, nullptr, NTOK, F_, E_, nullptr, 2); }

    disc_kernel<<<cdiv(NTOK*32, 256), 256>>>(bert, POSF, wd, bd, out, NTOK);
}

// round 10
// speedup vs baseline: 9.1182x; 1.0909x over previous
#include <cuda_runtime.h>
#include <cuda_fp16.h>
#include <math.h>
#include <stdint.h>

// ---------------- problem constants ----------------
#define B_    32
#define M_    512
#define E_    512
#define S_    513
#define NTOK  (B_*S_)          // 16416
#define NHEAD_ 8
#define DH_   64
#define DFF_  2048
#define F_    768

// ---------------- fp32 scratch ----------------
__device__ float d_PE[M_*E_];
__device__ int   d_SPAN[B_*M_];
__device__ float d_X  [(size_t)NTOK*E_];
__device__ float d_Y  [(size_t)NTOK*E_];
__device__ float d_POSF[(size_t)NTOK*F_];

// ---------------- fp16 operand buffers ----------------
__device__ __align__(16) __half d_Xf  [(size_t)NTOK*E_];
__device__ __align__(16) __half d_QKVf[(size_t)NTOK*3*E_];
__device__ __align__(16) __half d_CXf [(size_t)NTOK*E_];
__device__ __align__(16) __half d_Hf  [(size_t)NTOK*DFF_];
__device__ __align__(16) __half d_WQf [(size_t)2*3*E_*E_];
__device__ __align__(16) __half d_WOf [(size_t)2*E_*E_];
__device__ __align__(16) __half d_W1f [(size_t)2*DFF_*E_];
__device__ __align__(16) __half d_W2f [(size_t)2*E_*DFF_];
__device__ __align__(16) __half d_WMf [(size_t)F_*E_];

// ================= fp16 tensor-core GEMM (BK=64, 2 CTAs/SM) ========
#define BM 128
#define BN 128
#define BK 64
#define PADB 144                 // 128B data + 16B pad per row
#define A_ARR (128*PADB)         // 18432
#define B_ARR (128*PADB)         // 18432
#define STAGE (A_ARR + B_ARR)    // 36864
#define NSTAGE 3
#define SMEM_GEMM (NSTAGE*STAGE) // 110592
#define NTHR_G 256

__device__ __forceinline__ uint32_t smem_u32(const void* p) {
    uint32_t a;
    asm("{ .reg .u64 t; cvta.to.shared.u64 t, %1; cvt.u32.u64 %0, t; }"
        : "=r"(a) : "l"(p));
    return a;
}
__device__ __forceinline__ void ldsm4(uint32_t* r, uint32_t addr) {
    asm volatile("ldmatrix.sync.aligned.m8n8.x4.shared.b16 {%0,%1,%2,%3}, [%4];"
        : "=r"(r[0]), "=r"(r[1]), "=r"(r[2]), "=r"(r[3]) : "r"(addr));
}
__device__ __forceinline__ void mma16816(float* c, const uint32_t* a, const uint32_t* b) {
    asm volatile(
        "mma.sync.aligned.m16n8k16.row.col.f32.f16.f16.f32 "
        "{%0,%1,%2,%3}, {%4,%5,%6,%7}, {%8,%9}, {%0,%1,%2,%3};"
        : "+f"(c[0]), "+f"(c[1]), "+f"(c[2]), "+f"(c[3])
        : "r"(a[0]), "r"(a[1]), "r"(a[2]), "r"(a[3]), "r"(b[0]), "r"(b[1]));
}
__device__ __forceinline__ void cpa16(uint32_t dst, const void* src, int srcsize) {
    asm volatile("cp.async.cg.shared.global [%0], [%1], 16, %2;"
                 :: "r"(dst), "l"(src), "r"(srcsize));
}

__device__ __forceinline__ void load_stage(
    uint32_t st,
    const __half* __restrict__ Af, const __half* __restrict__ Bf,
    int tile_m, int tile_n, int Mdim, int Kdim, int kc, int tid)
{
    const int k0 = kc * BK;
    #pragma unroll
    for (int i = 0; i < 4; i++) {   // A: 128 rows x 8 x 16B = 1024 cp
        int id = tid + NTHR_G*i;
        int row = id >> 3, c = id & 7;
        const __half* src = Af + (size_t)(tile_m + row) * Kdim + k0 + c*8;
        cpa16(st + row*PADB + c*16, src, (tile_m + row) < Mdim ? 16 : 0);
    }
    #pragma unroll
    for (int i = 0; i < 4; i++) {   // B: 128 rows x 8 x 16B = 1024 cp
        int id = tid + NTHR_G*i;
        int row = id >> 3, c = id & 7;
        const __half* src = Bf + (size_t)(tile_n + row) * Kdim + k0 + c*8;
        cpa16(st + A_ARR + row*PADB + c*16, src, 16);
    }
    asm volatile("cp.async.commit_group;" ::: "memory");
}

__global__ __launch_bounds__(NTHR_G, 2)
void gemm_tc(const __half* __restrict__ Af, const __half* __restrict__ Bf,
             float* __restrict__ Cf, __half* __restrict__ Chalf,
             int Mdim, int Ndim, int Kdim,
             const float* __restrict__ bias, int act)
{
    extern __shared__ __align__(16) char smem[];
    const uint32_t sb = smem_u32(smem);
    const int tid    = threadIdx.x;
    const int tile_m = blockIdx.y * BM;
    const int tile_n = blockIdx.x * BN;
    const int warp = tid >> 5, lane = tid & 31;
    const int wm2 = warp >> 2, wn4 = warp & 3;    // 2(M) x 4(N), 64x32 warp tiles

    float acc[4][4][4];
    #pragma unroll
    for (int a = 0; a < 4; a++)
        #pragma unroll
        for (int b = 0; b < 4; b++)
            #pragma unroll
            for (int q = 0; q < 4; q++) acc[a][b][q] = 0.0f;

    const int nst = Kdim / BK;
    load_stage(sb,         Af, Bf, tile_m, tile_n, Mdim, Kdim, 0, tid);
    load_stage(sb + STAGE, Af, Bf, tile_m, tile_n, Mdim, Kdim, 1, tid);

    const uint32_t a_off = (uint32_t)(wm2*64 + (lane & 7) + ((lane >> 3) & 1) * 8) * PADB
                         + ((lane >> 4) * 16);
    const uint32_t b_off = (uint32_t)(wn4*32 + (lane & 7) + ((lane >> 4) & 1) * 8) * PADB
                         + (((lane >> 3) & 1) * 16);

    for (int s = 0; s < nst; s++) {
        if (s + 1 < nst) asm volatile("cp.async.wait_group 1;" ::: "memory");
        else             asm volatile("cp.async.wait_group 0;" ::: "memory");
        __syncthreads();
        if (s + 2 < nst)
            load_stage(sb + ((s + 2) % NSTAGE) * STAGE, Af, Bf,
                       tile_m, tile_n, Mdim, Kdim, s + 2, tid);
        const uint32_t st = sb + (s % NSTAGE) * STAGE;

        #pragma unroll
        for (int ks = 0; ks < 4; ks++) {
            uint32_t ah[4][4], bh[4][2];
            #pragma unroll
            for (int mi = 0; mi < 4; mi++)
                ldsm4(ah[mi], st + a_off + mi * (16 * PADB) + ks * 32);
            #pragma unroll
            for (int p = 0; p < 2; p++) {
                uint32_t r[4];
                ldsm4(r, st + A_ARR + b_off + p * (16 * PADB) + ks * 32);
                bh[2*p][0] = r[0]; bh[2*p][1] = r[1];
                bh[2*p+1][0] = r[2]; bh[2*p+1][1] = r[3];
            }
            #pragma unroll
            for (int mi = 0; mi < 4; mi++)
                #pragma unroll
                for (int ni = 0; ni < 4; ni++)
                    mma16816(acc[mi][ni], ah[mi], bh[ni]);
        }
    }

    // ---- epilogue ----
    const int er = lane >> 2;
    const int ec = (lane & 3) * 2;
    #pragma unroll
    for (int mi = 0; mi < 4; mi++) {
        const int gm0 = tile_m + wm2*64 + mi*16 + er;
        #pragma unroll
        for (int ni = 0; ni < 4; ni++) {
            const int gn = tile_n + wn4*32 + ni*8 + ec;
            float bx = 0.f, by = 0.f;
            if (bias) { float2 bb = *reinterpret_cast<const float2*>(bias + gn);
                        bx = bb.x; by = bb.y; }
            float v0 = acc[mi][ni][0] + bx, v1 = acc[mi][ni][1] + by;
            float v2 = acc[mi][ni][2] + bx, v3 = acc[mi][ni][3] + by;
            if (act == 1) {
                v0 = fmaxf(v0, 0.f); v1 = fmaxf(v1, 0.f);
                v2 = fmaxf(v2, 0.f); v3 = fmaxf(v3, 0.f);
            } else if (act == 2) {
                v0 = tanhf(v0); v1 = tanhf(v1); v2 = tanhf(v2); v3 = tanhf(v3);
            }
            if (Cf) {
                if (gm0 < Mdim)
                    *reinterpret_cast<float2*>(Cf + (size_t)gm0 * Ndim + gn) = make_float2(v0, v1);
                if (gm0 + 8 < Mdim)
                    *reinterpret_cast<float2*>(Cf + (size_t)(gm0+8) * Ndim + gn) = make_float2(v2, v3);
            }
            if (Chalf) {
                if (gm0 < Mdim) {
                    __half2 h; h.x = __float2half_rn(v0); h.y = __float2half_rn(v1);
                    *reinterpret_cast<__half2*>(Chalf + (size_t)gm0 * Ndim + gn) = h;
                }
                if (gm0 + 8 < Mdim) {
                    __half2 h; h.x = __float2half_rn(v2); h.y = __float2half_rn(v3);
                    *reinterpret_cast<__half2*>(Chalf + (size_t)(gm0+8) * Ndim + gn) = h;
                }
            }
        }
    }
}

// ---------------- fp32 -> fp16 convert (multi-tensor) ----------------
__device__ __forceinline__ void cvt_one(const float* in, __half* o, int i) {
    float4 v = *reinterpret_cast<const float4*>(in + (size_t)i * 4);
    __half2 h0, h1;
    h0.x = __float2half_rn(v.x); h0.y = __float2half_rn(v.y);
    h1.x = __float2half_rn(v.z); h1.y = __float2half_rn(v.w);
    uint2 u;
    u.x = *reinterpret_cast<uint32_t*>(&h0);
    u.y = *reinterpret_cast<uint32_t*>(&h1);
    *reinterpret_cast<uint2*>(o + (size_t)i * 4) = u;
}
__global__ void cvt3_kernel(const float* i1, __half* o1, int n1,
                            const float* i2, __half* o2, int n2,
                            const float* i3, __half* o3, int n3) {
    int i = blockIdx.x * blockDim.x + threadIdx.x;
    if (i < n1) { cvt_one(i1, o1, i); return; }
    i -= n1;
    if (i < n2) { cvt_one(i2, o2, i); return; }
    i -= n2;
    if (i < n3) cvt_one(i3, o3, i);
}
__global__ void cvt2_kernel(const float* i1, __half* o1, int n1,
                            const float* i2, __half* o2, int n2) {
    int i = blockIdx.x * blockDim.x + threadIdx.x;
    if (i < n1) { cvt_one(i1, o1, i); return; }
    i -= n1;
    if (i < n2) cvt_one(i2, o2, i);
}

// ---------------- fused span-id + PE table (one launch) ----------------
__global__ void spanpe_kernel(const int* __restrict__ pos1, int* __restrict__ span,
                              float* __restrict__ pe) {
    if (blockIdx.x < 32) {
        int b = blockIdx.x;
        int j = threadIdx.x;
        __shared__ int firstZero;
        span[b*M_ + j] = -1;
        if (j == 0) firstZero = M_;
        __syncthreads();
        int endv = pos1[((size_t)b*M_ + j)*2 + 1];
        if (endv == 0) atomicMin(&firstZero, j);
        __syncthreads();
        if (j < firstZero) {
            int st = pos1[((size_t)b*M_ + j)*2];
            int en = endv; if (en > M_) en = M_;
            for (int k = st; k < en; k++)
                atomicMax(&span[b*M_ + k], j);
        }
    } else {
        int idx = (blockIdx.x - 32) * 512 + threadIdx.x;
        if (idx >= M_ * E_) return;
        int pos = idx / E_, i = idx % E_;
        double e2  = (double)((i / 2) * 2);
        double ang = (double)pos / pow(10000.0, e2 / (double)E_);
        pe[idx] = (float)((i % 2 == 0) ? sin(ang) : cos(ang));
    }
}

// ---------------- build x [B,S,E] + f16 copy ----------------
__global__ void build_x_kernel(const int* __restrict__ pos2,
                               const float* __restrict__ fbase,
                               const float* __restrict__ emb,
                               const int* __restrict__ span,
                               const float* __restrict__ pe,
                               float* __restrict__ X,
                               __half* __restrict__ Xf) {
    int row = blockIdx.x;
    int b = row / S_, s = row % S_;
    size_t base = (size_t)row * E_;
    int e = threadIdx.x;
    float val;
    if (s == 0) {
        val = emb[(size_t)1*E_ + e];
    } else {
        int k = s - 1;
        int sid = span[b*M_ + k];
        if (sid >= 0) {
            int p = pos2[b*M_ + sid];
            val = (p == 0 ? 0.0f : emb[(size_t)p*E_ + e]) + pe[(size_t)sid*E_ + e];
        } else {
            val = fbase[((size_t)b*M_ + k)*E_ + e];
        }
    }
    X[base + e] = val;
    Xf[base + e] = __float2half_rn(val);
}

// ---------------- fused attention over the B axis (f16 in/out) ----------------
__global__ void attn_kernel(const __half* __restrict__ QKV,
                            __half* __restrict__ CXf) {
    int z = blockIdx.x;
    int s = z / NHEAD_, h = z % NHEAD_;
    __shared__ float q[B_][DH_];
    __shared__ float k[B_][DH_];
    __shared__ float v[B_][DH_];
    __shared__ float sc[B_][B_ + 1];

    const __half* base = QKV + (size_t)s * 3*E_ + (size_t)h * DH_;
    int t = threadIdx.x;

    // 32 rows x 32 half2 per matrix
    for (int i = t; i < B_*(DH_/2); i += 256) {
        int b = i / (DH_/2), d2 = i % (DH_/2);
        size_t off = (size_t)b * S_ * 3*E_ + 2*d2;
        __half2 hq = *reinterpret_cast<const __half2*>(base + off);
        __half2 hk = *reinterpret_cast<const __half2*>(base + off + E_);
        __half2 hv = *reinterpret_cast<const __half2*>(base + off + 2*E_);
        q[b][2*d2] = __half2float(hq.x); q[b][2*d2+1] = __half2float(hq.y);
        k[b][2*d2] = __half2float(hk.x); k[b][2*d2+1] = __half2float(hk.y);
        v[b][2*d2] = __half2float(hv.x); v[b][2*d2+1] = __half2float(hv.y);
    }
    __syncthreads();

    for (int i = t; i < B_*B_; i += 256) {
        int l = i / B_, m = i % B_;
        float acc = 0.0f;
        #pragma unroll
        for (int d = 0; d < DH_; d++) acc += q[l][d] * k[m][d];
        sc[l][m] = acc * 0.125f;
    }
    __syncthreads();

    int warp = t >> 5, lane = t & 31;
    for (int l = warp; l < B_; l += 8) {
        float val = sc[l][lane];
        float mx = val;
        #pragma unroll
        for (int o = 16; o; o >>= 1) mx = fmaxf(mx, __shfl_xor_sync(0xffffffffu, mx, o));
        float e = expf(val - mx);
        float sum = e;
        #pragma unroll
        for (int o = 16; o; o >>= 1) sum += __shfl_xor_sync(0xffffffffu, sum, o);
        sc[l][lane] = e / sum;
    }
    __syncthreads();

    for (int i = t; i < B_*DH_; i += 256) {
        int l = i / DH_, d = i % DH_;
        float acc = 0.0f;
        #pragma unroll
        for (int m = 0; m < B_; m++) acc += sc[l][m] * v[m][d];
        CXf[((size_t)l * S_ + s) * E_ + (size_t)h * DH_ + d] = __float2half_rn(acc);
    }
}

// ---------------- residual add + layernorm (+ f16 copy) ----------------
__global__ void add_ln_kernel(float* __restrict__ x, const float* __restrict__ y,
                              const float* __restrict__ w, const float* __restrict__ b,
                              __half* __restrict__ Xf) {
    long long row = blockIdx.x;
    __shared__ float red[256];
    int t = threadIdx.x;
    float v0 = x[row*E_ + t]       + y[row*E_ + t];
    float v1 = x[row*E_ + 256 + t] + y[row*E_ + 256 + t];
    red[t] = v0 + v1;
    __syncthreads();
    #pragma unroll
    for (int s2 = 128; s2 > 0; s2 >>= 1) { if (t < s2) red[t] += red[t + s2]; __syncthreads(); }
    float mean = red[0] * (1.0f / E_);
    __syncthreads();
    float d0 = v0 - mean, d1 = v1 - mean;
    red[t] = d0*d0 + d1*d1;
    __syncthreads();
    #pragma unroll
    for (int s2 = 128; s2 > 0; s2 >>= 1) { if (t < s2) red[t] += red[t + s2]; __syncthreads(); }
    float rstd = rsqrtf(red[0] * (1.0f / E_) + 1e-5f);
    float o0 = d0 * rstd * w[t]       + b[t];
    float o1 = d1 * rstd * w[t + 256] + b[t + 256];
    x[row*E_ + t]       = o0;
    x[row*E_ + 256 + t] = o1;
    Xf[row*E_ + t]       = __float2half_rn(o0);
    Xf[row*E_ + 256 + t] = __float2half_rn(o1);
}

// ---------------- discriminator head ----------------
__global__ void disc_kernel(const float* __restrict__ bert,
                            const float* __restrict__ posf,
                            const float* __restrict__ wd,
                            const float* __restrict__ bd,
                            float* __restrict__ out, int ntok) {
    int n = (blockIdx.x * blockDim.x + threadIdx.x) >> 5;
    int lane = threadIdx.x & 31;
    if (n >= ntok) return;
    float acc = 0.0f;
    const float* br = bert + (size_t)n * F_;
    const float* pr = posf + (size_t)n * F_;
    for (int i = lane; i < F_; i += 32) acc += br[i] * wd[i];
    for (int i = lane; i < F_; i += 32) acc += pr[i] * wd[F_ + i];
    #pragma unroll
    for (int o = 16; o; o >>= 1) acc += __shfl_xor_sync(0xffffffffu, acc, o);
    if (lane == 0) out[n] = 1.0f / (1.0f + expf(-(acc + bd[0])));
}

// ---------------- host orchestration ----------------
static inline int cdiv(int a, int b) { return (a + b - 1) / b; }

extern "C" void kernel_launch(void* const* d_in, const int* in_sizes, int n_in,
                              void* d_out, int out_size) {
    const int*   pos1  = (const int*)d_in[0];
    const int*   pos2  = (const int*)d_in[1];
    const float* bert  = (const float*)d_in[2];
    const float* fbase = (const float*)d_in[3];
    const float* emb   = (const float*)d_in[4];
    const float* wqkv  = (const float*)d_in[5];
    const float* bqkv  = (const float*)d_in[6];
    const float* wo    = (const float*)d_in[7];
    const float* bo    = (const float*)d_in[8];
    const float* ln1w  = (const float*)d_in[9];
    const float* ln1b  = (const float*)d_in[10];
    const float* ln2w  = (const float*)d_in[11];
    const float* ln2b  = (const float*)d_in[12];
    const float* w1    = (const float*)d_in[13];
    const float* b1    = (const float*)d_in[14];
    const float* w2    = (const float*)d_in[15];
    const float* b2    = (const float*)d_in[16];
    const float* wm    = (const float*)d_in[17];
    const float* wd    = (const float*)d_in[18];
    const float* bd    = (const float*)d_in[19];
    float* out = (float*)d_out;

    float *PE, *X, *Y, *POSF; int* SPAN;
    __half *Xf, *QKVf, *CXf, *Hf, *WQf, *WOf, *W1f, *W2f, *WMf;
    cudaGetSymbolAddress((void**)&PE,   d_PE);
    cudaGetSymbolAddress((void**)&SPAN, d_SPAN);
    cudaGetSymbolAddress((void**)&X,    d_X);
    cudaGetSymbolAddress((void**)&Y,    d_Y);
    cudaGetSymbolAddress((void**)&POSF, d_POSF);
    cudaGetSymbolAddress((void**)&Xf,   d_Xf);
    cudaGetSymbolAddress((void**)&QKVf, d_QKVf);
    cudaGetSymbolAddress((void**)&CXf,  d_CXf);
    cudaGetSymbolAddress((void**)&Hf,   d_Hf);
    cudaGetSymbolAddress((void**)&WQf,  d_WQf);
    cudaGetSymbolAddress((void**)&WOf,  d_WOf);
    cudaGetSymbolAddress((void**)&W1f,  d_W1f);
    cudaGetSymbolAddress((void**)&W2f,  d_W2f);
    cudaGetSymbolAddress((void**)&WMf,  d_WMf);

    cudaFuncSetAttribute(gemm_tc, cudaFuncAttributeMaxDynamicSharedMemorySize, SMEM_GEMM);

    // launch 0: convert wqkv + wo
    {
        int n1 = 2*3*E_*E_/4, n2 = 2*E_*E_/4;
        cvt2_kernel<<<cdiv(n1+n2,256),256>>>(wqkv, WQf, n1, wo, WOf, n2);
    }
    // launch 1: fused span + PE
    spanpe_kernel<<<32 + cdiv(M_*E_, 512), 512>>>(pos1, SPAN, PE);
    // launch 2: build x
    build_x_kernel<<<NTOK, 512>>>(pos2, fbase, emb, SPAN, PE, X, Xf);

    const int MY = cdiv(NTOK, BM);   // 129
    bool cvt3_done = false;

    for (int l = 0; l < 2; l++) {
        const size_t oq = (size_t)l * 3*E_ * E_;
        const size_t oo = (size_t)l * E_ * E_;
        const size_t o1 = (size_t)l * DFF_ * E_;
        const size_t o2 = (size_t)l * E_ * DFF_;

        { dim3 g(3*E_/BN, MY);   // QKV (fp16 out)  — launch 3, layer 0
          gemm_tc<<<g, NTHR_G, SMEM_GEMM>>>(Xf, WQf+oq,
              nullptr, QKVf, NTOK, 3*E_, E_, bqkv + l*3*E_, 0); }

        if (!cvt3_done) {        // launch 4: convert w1 + w2 + wm
            int n1 = 2*DFF_*E_/4, n2 = 2*E_*DFF_/4, n3 = F_*E_/4;
            cvt3_kernel<<<cdiv(n1+n2+n3,256),256>>>(w1, W1f, n1,
                                                    w2, W2f, n2,
                                                    wm, WMf, n3);
            cvt3_done = true;
        }

        attn_kernel<<<S_*NHEAD_, 256>>>(QKVf, CXf);

        { dim3 g(E_/BN, MY);     // Wo
          gemm_tc<<<g, NTHR_G, SMEM_GEMM>>>(CXf, WOf+oo,
              Y, nullptr, NTOK, E_, E_, bo + l*E_, 0); }

        add_ln_kernel<<<NTOK, 256>>>(X, Y, ln1w + l*E_, ln1b + l*E_, Xf);

        { dim3 g(DFF_/BN, MY);   // FFN1 -> f16 H
          gemm_tc<<<g, NTHR_G, SMEM_GEMM>>>(Xf, W1f+o1,
              nullptr, Hf, NTOK, DFF_, E_, b1 + l*DFF_, 1); }

        { dim3 g(E_/BN, MY);     // FFN2
          gemm_tc<<<g, NTHR_G, SMEM_GEMM>>>(Hf, W2f+o2,
              Y, nullptr, NTOK, E_, DFF_, b2 + l*E_, 0); }

        add_ln_kernel<<<NTOK, 256>>>(X, Y, ln2w + l*E_, ln2b + l*E_, Xf);
    }

    { dim3 g(F_/BN, MY);         // pos_feature = tanh(X @ wm^T)
      gemm_tc<<<g, NTHR_G, SMEM_GEMM>>>(Xf, WMf,
          POSF, nullptr, NTOK, F_, E_, nullptr, 2); }

    disc_kernel<<<cdiv(NTOK*32, 256), 256>>>(bert, POSF, wd, bd, out, NTOK);
}

// round 11
// speedup vs baseline: 10.5459x; 1.1566x over previous
#include <cuda_runtime.h>
#include <cuda_fp16.h>
#include <math.h>
#include <stdint.h>

// ---------------- problem constants ----------------
#define B_    32
#define M_    512
#define E_    512
#define S_    513
#define NTOK  (B_*S_)          // 16416
#define NHEAD_ 8
#define DH_   64
#define DFF_  2048
#define F_    768

// ---------------- fp32 scratch ----------------
__device__ float d_PE[M_*E_];
__device__ int   d_SPAN[B_*M_];
__device__ float d_X  [(size_t)NTOK*E_];
__device__ float d_Y  [(size_t)NTOK*E_];
__device__ float d_POSF[(size_t)NTOK*F_];

// ---------------- fp16 operand buffers ----------------
__device__ __align__(16) __half d_Xf  [(size_t)NTOK*E_];
__device__ __align__(16) __half d_QKVf[(size_t)NTOK*3*E_];
__device__ __align__(16) __half d_CXf [(size_t)NTOK*E_];
__device__ __align__(16) __half d_Hf  [(size_t)NTOK*DFF_];
__device__ __align__(16) __half d_WQf [(size_t)2*3*E_*E_];
__device__ __align__(16) __half d_WOf [(size_t)2*E_*E_];
__device__ __align__(16) __half d_W1f [(size_t)2*DFF_*E_];
__device__ __align__(16) __half d_W2f [(size_t)2*E_*DFF_];
__device__ __align__(16) __half d_WMf [(size_t)F_*E_];

// ================= fp16 tensor-core GEMM (BK=64, 2 CTAs/SM) ========
#define BM 128
#define BN 128
#define BK 64
#define PADB 144
#define A_ARR (128*PADB)
#define B_ARR (128*PADB)
#define STAGE (A_ARR + B_ARR)
#define NSTAGE 3
#define SMEM_GEMM (NSTAGE*STAGE)
#define NTHR_G 256

__device__ __forceinline__ uint32_t smem_u32(const void* p) {
    uint32_t a;
    asm("{ .reg .u64 t; cvta.to.shared.u64 t, %1; cvt.u32.u64 %0, t; }"
        : "=r"(a) : "l"(p));
    return a;
}
__device__ __forceinline__ void ldsm4(uint32_t* r, uint32_t addr) {
    asm volatile("ldmatrix.sync.aligned.m8n8.x4.shared.b16 {%0,%1,%2,%3}, [%4];"
        : "=r"(r[0]), "=r"(r[1]), "=r"(r[2]), "=r"(r[3]) : "r"(addr));
}
__device__ __forceinline__ void mma16816(float* c, const uint32_t* a, const uint32_t* b) {
    asm volatile(
        "mma.sync.aligned.m16n8k16.row.col.f32.f16.f16.f32 "
        "{%0,%1,%2,%3}, {%4,%5,%6,%7}, {%8,%9}, {%0,%1,%2,%3};"
        : "+f"(c[0]), "+f"(c[1]), "+f"(c[2]), "+f"(c[3])
        : "r"(a[0]), "r"(a[1]), "r"(a[2]), "r"(a[3]), "r"(b[0]), "r"(b[1]));
}
__device__ __forceinline__ void cpa16(uint32_t dst, const void* src, int srcsize) {
    asm volatile("cp.async.cg.shared.global [%0], [%1], 16, %2;"
                 :: "r"(dst), "l"(src), "r"(srcsize));
}

__device__ __forceinline__ void load_stage(
    uint32_t st,
    const __half* __restrict__ Af, const __half* __restrict__ Bf,
    int tile_m, int tile_n, int Mdim, int Kdim, int kc, int tid)
{
    const int k0 = kc * BK;
    #pragma unroll
    for (int i = 0; i < 4; i++) {
        int id = tid + NTHR_G*i;
        int row = id >> 3, c = id & 7;
        const __half* src = Af + (size_t)(tile_m + row) * Kdim + k0 + c*8;
        cpa16(st + row*PADB + c*16, src, (tile_m + row) < Mdim ? 16 : 0);
    }
    #pragma unroll
    for (int i = 0; i < 4; i++) {
        int id = tid + NTHR_G*i;
        int row = id >> 3, c = id & 7;
        const __half* src = Bf + (size_t)(tile_n + row) * Kdim + k0 + c*8;
        cpa16(st + A_ARR + row*PADB + c*16, src, 16);
    }
    asm volatile("cp.async.commit_group;" ::: "memory");
}

__global__ __launch_bounds__(NTHR_G, 2)
void gemm_tc(const __half* __restrict__ Af, const __half* __restrict__ Bf,
             float* __restrict__ Cf, __half* __restrict__ Chalf,
             int Mdim, int Ndim, int Kdim,
             const float* __restrict__ bias, int act)
{
    extern __shared__ __align__(16) char smem[];
    const uint32_t sb = smem_u32(smem);
    const int tid    = threadIdx.x;
    const int tile_m = blockIdx.y * BM;
    const int tile_n = blockIdx.x * BN;
    const int warp = tid >> 5, lane = tid & 31;
    const int wm2 = warp >> 2, wn4 = warp & 3;

    float acc[4][4][4];
    #pragma unroll
    for (int a = 0; a < 4; a++)
        #pragma unroll
        for (int b = 0; b < 4; b++)
            #pragma unroll
            for (int q = 0; q < 4; q++) acc[a][b][q] = 0.0f;

    const int nst = Kdim / BK;
    load_stage(sb,         Af, Bf, tile_m, tile_n, Mdim, Kdim, 0, tid);
    load_stage(sb + STAGE, Af, Bf, tile_m, tile_n, Mdim, Kdim, 1, tid);

    const uint32_t a_off = (uint32_t)(wm2*64 + (lane & 7) + ((lane >> 3) & 1) * 8) * PADB
                         + ((lane >> 4) * 16);
    const uint32_t b_off = (uint32_t)(wn4*32 + (lane & 7) + ((lane >> 4) & 1) * 8) * PADB
                         + (((lane >> 3) & 1) * 16);

    for (int s = 0; s < nst; s++) {
        if (s + 1 < nst) asm volatile("cp.async.wait_group 1;" ::: "memory");
        else             asm volatile("cp.async.wait_group 0;" ::: "memory");
        __syncthreads();
        if (s + 2 < nst)
            load_stage(sb + ((s + 2) % NSTAGE) * STAGE, Af, Bf,
                       tile_m, tile_n, Mdim, Kdim, s + 2, tid);
        const uint32_t st = sb + (s % NSTAGE) * STAGE;

        #pragma unroll
        for (int ks = 0; ks < 4; ks++) {
            uint32_t ah[4][4], bh[4][2];
            #pragma unroll
            for (int mi = 0; mi < 4; mi++)
                ldsm4(ah[mi], st + a_off + mi * (16 * PADB) + ks * 32);
            #pragma unroll
            for (int p = 0; p < 2; p++) {
                uint32_t r[4];
                ldsm4(r, st + A_ARR + b_off + p * (16 * PADB) + ks * 32);
                bh[2*p][0] = r[0]; bh[2*p][1] = r[1];
                bh[2*p+1][0] = r[2]; bh[2*p+1][1] = r[3];
            }
            #pragma unroll
            for (int mi = 0; mi < 4; mi++)
                #pragma unroll
                for (int ni = 0; ni < 4; ni++)
                    mma16816(acc[mi][ni], ah[mi], bh[ni]);
        }
    }

    // ---- epilogue ----
    const int er = lane >> 2;
    const int ec = (lane & 3) * 2;
    #pragma unroll
    for (int mi = 0; mi < 4; mi++) {
        const int gm0 = tile_m + wm2*64 + mi*16 + er;
        #pragma unroll
        for (int ni = 0; ni < 4; ni++) {
            const int gn = tile_n + wn4*32 + ni*8 + ec;
            float bx = 0.f, by = 0.f;
            if (bias) { float2 bb = *reinterpret_cast<const float2*>(bias + gn);
                        bx = bb.x; by = bb.y; }
            float v0 = acc[mi][ni][0] + bx, v1 = acc[mi][ni][1] + by;
            float v2 = acc[mi][ni][2] + bx, v3 = acc[mi][ni][3] + by;
            if (act == 1) {
                v0 = fmaxf(v0, 0.f); v1 = fmaxf(v1, 0.f);
                v2 = fmaxf(v2, 0.f); v3 = fmaxf(v3, 0.f);
            } else if (act == 2) {
                v0 = tanhf(v0); v1 = tanhf(v1); v2 = tanhf(v2); v3 = tanhf(v3);
            }
            if (Cf) {
                if (gm0 < Mdim)
                    *reinterpret_cast<float2*>(Cf + (size_t)gm0 * Ndim + gn) = make_float2(v0, v1);
                if (gm0 + 8 < Mdim)
                    *reinterpret_cast<float2*>(Cf + (size_t)(gm0+8) * Ndim + gn) = make_float2(v2, v3);
            }
            if (Chalf) {
                if (gm0 < Mdim) {
                    __half2 h; h.x = __float2half_rn(v0); h.y = __float2half_rn(v1);
                    *reinterpret_cast<__half2*>(Chalf + (size_t)gm0 * Ndim + gn) = h;
                }
                if (gm0 + 8 < Mdim) {
                    __half2 h; h.x = __float2half_rn(v2); h.y = __float2half_rn(v3);
                    *reinterpret_cast<__half2*>(Chalf + (size_t)(gm0+8) * Ndim + gn) = h;
                }
            }
        }
    }
}

// ---------------- fp32 -> fp16 convert (multi-tensor) ----------------
__device__ __forceinline__ void cvt_one(const float* in, __half* o, int i) {
    float4 v = *reinterpret_cast<const float4*>(in + (size_t)i * 4);
    __half2 h0, h1;
    h0.x = __float2half_rn(v.x); h0.y = __float2half_rn(v.y);
    h1.x = __float2half_rn(v.z); h1.y = __float2half_rn(v.w);
    uint2 u;
    u.x = *reinterpret_cast<uint32_t*>(&h0);
    u.y = *reinterpret_cast<uint32_t*>(&h1);
    *reinterpret_cast<uint2*>(o + (size_t)i * 4) = u;
}
__global__ void cvt3_kernel(const float* i1, __half* o1, int n1,
                            const float* i2, __half* o2, int n2,
                            const float* i3, __half* o3, int n3) {
    int i = blockIdx.x * blockDim.x + threadIdx.x;
    if (i < n1) { cvt_one(i1, o1, i); return; }
    i -= n1;
    if (i < n2) { cvt_one(i2, o2, i); return; }
    i -= n2;
    if (i < n3) cvt_one(i3, o3, i);
}
__global__ void cvt2_kernel(const float* i1, __half* o1, int n1,
                            const float* i2, __half* o2, int n2) {
    int i = blockIdx.x * blockDim.x + threadIdx.x;
    if (i < n1) { cvt_one(i1, o1, i); return; }
    i -= n1;
    if (i < n2) cvt_one(i2, o2, i);
}

// ---------------- fused span-id + PE table ----------------
__global__ void spanpe_kernel(const int* __restrict__ pos1, int* __restrict__ span,
                              float* __restrict__ pe) {
    if (blockIdx.x < 32) {
        int b = blockIdx.x;
        int j = threadIdx.x;
        __shared__ int firstZero;
        span[b*M_ + j] = -1;
        if (j == 0) firstZero = M_;
        __syncthreads();
        int endv = pos1[((size_t)b*M_ + j)*2 + 1];
        if (endv == 0) atomicMin(&firstZero, j);
        __syncthreads();
        if (j < firstZero) {
            int st = pos1[((size_t)b*M_ + j)*2];
            int en = endv; if (en > M_) en = M_;
            for (int k = st; k < en; k++)
                atomicMax(&span[b*M_ + k], j);
        }
    } else {
        int idx = (blockIdx.x - 32) * 512 + threadIdx.x;
        if (idx >= M_ * E_) return;
        int pos = idx / E_, i = idx % E_;
        double e2  = (double)((i / 2) * 2);
        double ang = (double)pos / pow(10000.0, e2 / (double)E_);
        pe[idx] = (float)((i % 2 == 0) ? sin(ang) : cos(ang));
    }
}

// ---------------- build x [B,S,E] + f16 copy ----------------
__global__ void build_x_kernel(const int* __restrict__ pos2,
                               const float* __restrict__ fbase,
                               const float* __restrict__ emb,
                               const int* __restrict__ span,
                               const float* __restrict__ pe,
                               float* __restrict__ X,
                               __half* __restrict__ Xf) {
    int row = blockIdx.x;
    int b = row / S_, s = row % S_;
    size_t base = (size_t)row * E_;
    int e = threadIdx.x;
    float val;
    if (s == 0) {
        val = emb[(size_t)1*E_ + e];
    } else {
        int k = s - 1;
        int sid = span[b*M_ + k];
        if (sid >= 0) {
            int p = pos2[b*M_ + sid];
            val = (p == 0 ? 0.0f : emb[(size_t)p*E_ + e]) + pe[(size_t)sid*E_ + e];
        } else {
            val = fbase[((size_t)b*M_ + k)*E_ + e];
        }
    }
    X[base + e] = val;
    Xf[base + e] = __float2half_rn(val);
}

// ---------------- fused attention over the B axis (conflict-free k) ----------------
__global__ void attn_kernel(const __half* __restrict__ QKV,
                            __half* __restrict__ CXf) {
    int z = blockIdx.x;
    int s = z / NHEAD_, h = z % NHEAD_;
    __shared__ float q[B_][DH_];
    __shared__ float k[B_][DH_ + 1];   // +1 pad: row stride 65 words -> no bank conflicts
    __shared__ float v[B_][DH_];
    __shared__ float sc[B_][B_ + 1];

    const __half* base = QKV + (size_t)s * 3*E_ + (size_t)h * DH_;
    int t = threadIdx.x;

    for (int i = t; i < B_*(DH_/2); i += 256) {
        int b = i / (DH_/2), d2 = i % (DH_/2);
        size_t off = (size_t)b * S_ * 3*E_ + 2*d2;
        __half2 hq = *reinterpret_cast<const __half2*>(base + off);
        __half2 hk = *reinterpret_cast<const __half2*>(base + off + E_);
        __half2 hv = *reinterpret_cast<const __half2*>(base + off + 2*E_);
        q[b][2*d2] = __half2float(hq.x); q[b][2*d2+1] = __half2float(hq.y);
        k[b][2*d2] = __half2float(hk.x); k[b][2*d2+1] = __half2float(hk.y);
        v[b][2*d2] = __half2float(hv.x); v[b][2*d2+1] = __half2float(hv.y);
    }
    __syncthreads();

    // scores: warp handles 4 l-rows; lane = m. q broadcast, k stride-65 (conflict-free)
    for (int i = t; i < B_*B_; i += 256) {
        int l = i / B_, m = i % B_;
        float acc = 0.0f;
        #pragma unroll
        for (int d = 0; d < DH_; d++) acc += q[l][d] * k[m][d];
        sc[l][m] = acc * 0.125f;
    }
    __syncthreads();

    int warp = t >> 5, lane = t & 31;
    for (int l = warp; l < B_; l += 8) {
        float val = sc[l][lane];
        float mx = val;
        #pragma unroll
        for (int o = 16; o; o >>= 1) mx = fmaxf(mx, __shfl_xor_sync(0xffffffffu, mx, o));
        float e = expf(val - mx);
        float sum = e;
        #pragma unroll
        for (int o = 16; o; o >>= 1) sum += __shfl_xor_sync(0xffffffffu, sum, o);
        sc[l][lane] = e / sum;
    }
    __syncthreads();

    for (int i = t; i < B_*DH_; i += 256) {
        int l = i / DH_, d = i % DH_;
        float acc = 0.0f;
        #pragma unroll
        for (int m = 0; m < B_; m++) acc += sc[l][m] * v[m][d];
        CXf[((size_t)l * S_ + s) * E_ + (size_t)h * DH_ + d] = __float2half_rn(acc);
    }
}

// ---------------- residual add + layernorm: one-pass, shuffle reductions ------
__global__ void add_ln_kernel(float* __restrict__ x, const float* __restrict__ y,
                              const float* __restrict__ w, const float* __restrict__ b,
                              __half* __restrict__ Xf) {
    long long row = blockIdx.x;
    int t = threadIdx.x;                // 256 threads, 2 elems each
    int warp = t >> 5, lane = t & 31;
    __shared__ float ps[8], ps2[8];
    __shared__ float s_mean, s_rstd;

    float v0 = x[row*E_ + t]       + y[row*E_ + t];
    float v1 = x[row*E_ + 256 + t] + y[row*E_ + 256 + t];
    float s  = v0 + v1;
    float s2 = v0*v0 + v1*v1;
    #pragma unroll
    for (int o = 16; o; o >>= 1) {
        s  += __shfl_xor_sync(0xffffffffu, s,  o);
        s2 += __shfl_xor_sync(0xffffffffu, s2, o);
    }
    if (lane == 0) { ps[warp] = s; ps2[warp] = s2; }
    __syncthreads();
    if (t == 0) {
        float ts = 0.f, ts2 = 0.f;
        #pragma unroll
        for (int i = 0; i < 8; i++) { ts += ps[i]; ts2 += ps2[i]; }
        float mean = ts * (1.0f / E_);
        float var  = ts2 * (1.0f / E_) - mean * mean;
        s_mean = mean;
        s_rstd = rsqrtf(var + 1e-5f);
    }
    __syncthreads();
    float mean = s_mean, rstd = s_rstd;
    float o0 = (v0 - mean) * rstd * w[t]       + b[t];
    float o1 = (v1 - mean) * rstd * w[t + 256] + b[t + 256];
    x[row*E_ + t]       = o0;
    x[row*E_ + 256 + t] = o1;
    Xf[row*E_ + t]       = __float2half_rn(o0);
    Xf[row*E_ + 256 + t] = __float2half_rn(o1);
}

// ---------------- discriminator head ----------------
__global__ void disc_kernel(const float* __restrict__ bert,
                            const float* __restrict__ posf,
                            const float* __restrict__ wd,
                            const float* __restrict__ bd,
                            float* __restrict__ out, int ntok) {
    int n = (blockIdx.x * blockDim.x + threadIdx.x) >> 5;
    int lane = threadIdx.x & 31;
    if (n >= ntok) return;
    float acc = 0.0f;
    const float* br = bert + (size_t)n * F_;
    const float* pr = posf + (size_t)n * F_;
    for (int i = lane; i < F_; i += 32) acc += br[i] * wd[i];
    for (int i = lane; i < F_; i += 32) acc += pr[i] * wd[F_ + i];
    #pragma unroll
    for (int o = 16; o; o >>= 1) acc += __shfl_xor_sync(0xffffffffu, acc, o);
    if (lane == 0) out[n] = 1.0f / (1.0f + expf(-(acc + bd[0])));
}

// ---------------- host orchestration ----------------
static inline int cdiv(int a, int b) { return (a + b - 1) / b; }

extern "C" void kernel_launch(void* const* d_in, const int* in_sizes, int n_in,
                              void* d_out, int out_size) {
    const int*   pos1  = (const int*)d_in[0];
    const int*   pos2  = (const int*)d_in[1];
    const float* bert  = (const float*)d_in[2];
    const float* fbase = (const float*)d_in[3];
    const float* emb   = (const float*)d_in[4];
    const float* wqkv  = (const float*)d_in[5];
    const float* bqkv  = (const float*)d_in[6];
    const float* wo    = (const float*)d_in[7];
    const float* bo    = (const float*)d_in[8];
    const float* ln1w  = (const float*)d_in[9];
    const float* ln1b  = (const float*)d_in[10];
    const float* ln2w  = (const float*)d_in[11];
    const float* ln2b  = (const float*)d_in[12];
    const float* w1    = (const float*)d_in[13];
    const float* b1    = (const float*)d_in[14];
    const float* w2    = (const float*)d_in[15];
    const float* b2    = (const float*)d_in[16];
    const float* wm    = (const float*)d_in[17];
    const float* wd    = (const float*)d_in[18];
    const float* bd    = (const float*)d_in[19];
    float* out = (float*)d_out;

    float *PE, *X, *Y, *POSF; int* SPAN;
    __half *Xf, *QKVf, *CXf, *Hf, *WQf, *WOf, *W1f, *W2f, *WMf;
    cudaGetSymbolAddress((void**)&PE,   d_PE);
    cudaGetSymbolAddress((void**)&SPAN, d_SPAN);
    cudaGetSymbolAddress((void**)&X,    d_X);
    cudaGetSymbolAddress((void**)&Y,    d_Y);
    cudaGetSymbolAddress((void**)&POSF, d_POSF);
    cudaGetSymbolAddress((void**)&Xf,   d_Xf);
    cudaGetSymbolAddress((void**)&QKVf, d_QKVf);
    cudaGetSymbolAddress((void**)&CXf,  d_CXf);
    cudaGetSymbolAddress((void**)&Hf,   d_Hf);
    cudaGetSymbolAddress((void**)&WQf,  d_WQf);
    cudaGetSymbolAddress((void**)&WOf,  d_WOf);
    cudaGetSymbolAddress((void**)&W1f,  d_W1f);
    cudaGetSymbolAddress((void**)&W2f,  d_W2f);
    cudaGetSymbolAddress((void**)&WMf,  d_WMf);

    cudaFuncSetAttribute(gemm_tc, cudaFuncAttributeMaxDynamicSharedMemorySize, SMEM_GEMM);

    // launch 0: convert wqkv + wo
    {
        int n1 = 2*3*E_*E_/4, n2 = 2*E_*E_/4;
        cvt2_kernel<<<cdiv(n1+n2,256),256>>>(wqkv, WQf, n1, wo, WOf, n2);
    }
    // launch 1: fused span + PE
    spanpe_kernel<<<32 + cdiv(M_*E_, 512), 512>>>(pos1, SPAN, PE);
    // launch 2: build x
    build_x_kernel<<<NTOK, 512>>>(pos2, fbase, emb, SPAN, PE, X, Xf);

    const int MY = cdiv(NTOK, BM);   // 129
    bool cvt3_done = false;

    for (int l = 0; l < 2; l++) {
        const size_t oq = (size_t)l * 3*E_ * E_;
        const size_t oo = (size_t)l * E_ * E_;
        const size_t o1 = (size_t)l * DFF_ * E_;
        const size_t o2 = (size_t)l * E_ * DFF_;

        { dim3 g(3*E_/BN, MY);   // QKV (fp16 out) — launch 3, layer 0
          gemm_tc<<<g, NTHR_G, SMEM_GEMM>>>(Xf, WQf+oq,
              nullptr, QKVf, NTOK, 3*E_, E_, bqkv + l*3*E_, 0); }

        if (!cvt3_done) {
            int n1 = 2*DFF_*E_/4, n2 = 2*E_*DFF_/4, n3 = F_*E_/4;
            cvt3_kernel<<<cdiv(n1+n2+n3,256),256>>>(w1, W1f, n1,
                                                    w2, W2f, n2,
                                                    wm, WMf, n3);
            cvt3_done = true;
        }

        attn_kernel<<<S_*NHEAD_, 256>>>(QKVf, CXf);

        { dim3 g(E_/BN, MY);     // Wo
          gemm_tc<<<g, NTHR_G, SMEM_GEMM>>>(CXf, WOf+oo,
              Y, nullptr, NTOK, E_, E_, bo + l*E_, 0); }

        add_ln_kernel<<<NTOK, 256>>>(X, Y, ln1w + l*E_, ln1b + l*E_, Xf);

        { dim3 g(DFF_/BN, MY);   // FFN1 -> f16 H
          gemm_tc<<<g, NTHR_G, SMEM_GEMM>>>(Xf, W1f+o1,
              nullptr, Hf, NTOK, DFF_, E_, b1 + l*DFF_, 1); }

        { dim3 g(E_/BN, MY);     // FFN2
          gemm_tc<<<g, NTHR_G, SMEM_GEMM>>>(Hf, W2f+o2,
              Y, nullptr, NTOK, E_, DFF_, b2 + l*E_, 0); }

        add_ln_kernel<<<NTOK, 256>>>(X, Y, ln2w + l*E_, ln2b + l*E_, Xf);
    }

    { dim3 g(F_/BN, MY);         // pos_feature = tanh(X @ wm^T)
      gemm_tc<<<g, NTHR_G, SMEM_GEMM>>>(Xf, WMf,
          POSF, nullptr, NTOK, F_, E_, nullptr, 2); }

    disc_kernel<<<cdiv(NTOK*32, 256), 256>>>(bert, POSF, wd, bd, out, NTOK);
}

// round 12
// speedup vs baseline: 10.8895x; 1.0326x over previous
#include <cuda_runtime.h>
#include <cuda_fp16.h>
#include <math.h>
#include <stdint.h>

// ---------------- problem constants ----------------
#define B_    32
#define M_    512
#define E_    512
#define S_    513
#define NTOK  (B_*S_)          // 16416
#define NHEAD_ 8
#define DH_   64
#define DFF_  2048
#define F_    768

// ---------------- fp32 scratch ----------------
__device__ float d_PE[M_*E_];
__device__ int   d_SPAN[B_*M_];
__device__ float d_X  [(size_t)NTOK*E_];
__device__ float d_Y  [(size_t)NTOK*E_];

// ---------------- fp16 operand buffers ----------------
__device__ __align__(16) __half d_Xf   [(size_t)NTOK*E_];
__device__ __align__(16) __half d_QKVf [(size_t)NTOK*3*E_];
__device__ __align__(16) __half d_CXf  [(size_t)NTOK*E_];
__device__ __align__(16) __half d_Hf   [(size_t)NTOK*DFF_];
__device__ __align__(16) __half d_POSFh[(size_t)NTOK*F_];
__device__ __align__(16) __half d_WQf  [(size_t)2*3*E_*E_];
__device__ __align__(16) __half d_WOf  [(size_t)2*E_*E_];
__device__ __align__(16) __half d_W1f  [(size_t)2*DFF_*E_];
__device__ __align__(16) __half d_W2f  [(size_t)2*E_*DFF_];
__device__ __align__(16) __half d_WMf  [(size_t)F_*E_];

// ================= fp16 tensor-core GEMM (BK=64, 2 CTAs/SM) ========
#define BM 128
#define BN 128
#define BK 64
#define PADB 144
#define A_ARR (128*PADB)
#define B_ARR (128*PADB)
#define STAGE (A_ARR + B_ARR)
#define NSTAGE 3
#define SMEM_GEMM (NSTAGE*STAGE)
#define NTHR_G 256

__device__ __forceinline__ uint32_t smem_u32(const void* p) {
    uint32_t a;
    asm("{ .reg .u64 t; cvta.to.shared.u64 t, %1; cvt.u32.u64 %0, t; }"
        : "=r"(a) : "l"(p));
    return a;
}
__device__ __forceinline__ void ldsm4(uint32_t* r, uint32_t addr) {
    asm volatile("ldmatrix.sync.aligned.m8n8.x4.shared.b16 {%0,%1,%2,%3}, [%4];"
        : "=r"(r[0]), "=r"(r[1]), "=r"(r[2]), "=r"(r[3]) : "r"(addr));
}
__device__ __forceinline__ void mma16816(float* c, const uint32_t* a, const uint32_t* b) {
    asm volatile(
        "mma.sync.aligned.m16n8k16.row.col.f32.f16.f16.f32 "
        "{%0,%1,%2,%3}, {%4,%5,%6,%7}, {%8,%9}, {%0,%1,%2,%3};"
        : "+f"(c[0]), "+f"(c[1]), "+f"(c[2]), "+f"(c[3])
        : "r"(a[0]), "r"(a[1]), "r"(a[2]), "r"(a[3]), "r"(b[0]), "r"(b[1]));
}
__device__ __forceinline__ void cpa16(uint32_t dst, const void* src, int srcsize) {
    asm volatile("cp.async.cg.shared.global [%0], [%1], 16, %2;"
                 :: "r"(dst), "l"(src), "r"(srcsize));
}

__device__ __forceinline__ void load_stage(
    uint32_t st,
    const __half* __restrict__ Af, const __half* __restrict__ Bf,
    int tile_m, int tile_n, int Mdim, int Kdim, int kc, int tid)
{
    const int k0 = kc * BK;
    #pragma unroll
    for (int i = 0; i < 4; i++) {
        int id = tid + NTHR_G*i;
        int row = id >> 3, c = id & 7;
        const __half* src = Af + (size_t)(tile_m + row) * Kdim + k0 + c*8;
        cpa16(st + row*PADB + c*16, src, (tile_m + row) < Mdim ? 16 : 0);
    }
    #pragma unroll
    for (int i = 0; i < 4; i++) {
        int id = tid + NTHR_G*i;
        int row = id >> 3, c = id & 7;
        const __half* src = Bf + (size_t)(tile_n + row) * Kdim + k0 + c*8;
        cpa16(st + A_ARR + row*PADB + c*16, src, 16);
    }
    asm volatile("cp.async.commit_group;" ::: "memory");
}

__global__ __launch_bounds__(NTHR_G, 2)
void gemm_tc(const __half* __restrict__ Af, const __half* __restrict__ Bf,
             float* __restrict__ Cf, __half* __restrict__ Chalf,
             int Mdim, int Ndim, int Kdim,
             const float* __restrict__ bias, int act)
{
    extern __shared__ __align__(16) char smem[];
    const uint32_t sb = smem_u32(smem);
    const int tid    = threadIdx.x;
    const int tile_m = blockIdx.y * BM;
    const int tile_n = blockIdx.x * BN;
    const int warp = tid >> 5, lane = tid & 31;
    const int wm2 = warp >> 2, wn4 = warp & 3;

    float acc[4][4][4];
    #pragma unroll
    for (int a = 0; a < 4; a++)
        #pragma unroll
        for (int b = 0; b < 4; b++)
            #pragma unroll
            for (int q = 0; q < 4; q++) acc[a][b][q] = 0.0f;

    const int nst = Kdim / BK;
    load_stage(sb,         Af, Bf, tile_m, tile_n, Mdim, Kdim, 0, tid);
    load_stage(sb + STAGE, Af, Bf, tile_m, tile_n, Mdim, Kdim, 1, tid);

    const uint32_t a_off = (uint32_t)(wm2*64 + (lane & 7) + ((lane >> 3) & 1) * 8) * PADB
                         + ((lane >> 4) * 16);
    const uint32_t b_off = (uint32_t)(wn4*32 + (lane & 7) + ((lane >> 4) & 1) * 8) * PADB
                         + (((lane >> 3) & 1) * 16);

    for (int s = 0; s < nst; s++) {
        if (s + 1 < nst) asm volatile("cp.async.wait_group 1;" ::: "memory");
        else             asm volatile("cp.async.wait_group 0;" ::: "memory");
        __syncthreads();
        if (s + 2 < nst)
            load_stage(sb + ((s + 2) % NSTAGE) * STAGE, Af, Bf,
                       tile_m, tile_n, Mdim, Kdim, s + 2, tid);
        const uint32_t st = sb + (s % NSTAGE) * STAGE;

        #pragma unroll
        for (int ks = 0; ks < 4; ks++) {
            uint32_t ah[4][4], bh[4][2];
            #pragma unroll
            for (int mi = 0; mi < 4; mi++)
                ldsm4(ah[mi], st + a_off + mi * (16 * PADB) + ks * 32);
            #pragma unroll
            for (int p = 0; p < 2; p++) {
                uint32_t r[4];
                ldsm4(r, st + A_ARR + b_off + p * (16 * PADB) + ks * 32);
                bh[2*p][0] = r[0]; bh[2*p][1] = r[1];
                bh[2*p+1][0] = r[2]; bh[2*p+1][1] = r[3];
            }
            #pragma unroll
            for (int mi = 0; mi < 4; mi++)
                #pragma unroll
                for (int ni = 0; ni < 4; ni++)
                    mma16816(acc[mi][ni], ah[mi], bh[ni]);
        }
    }

    // ---- epilogue ----
    const int er = lane >> 2;
    const int ec = (lane & 3) * 2;
    #pragma unroll
    for (int mi = 0; mi < 4; mi++) {
        const int gm0 = tile_m + wm2*64 + mi*16 + er;
        #pragma unroll
        for (int ni = 0; ni < 4; ni++) {
            const int gn = tile_n + wn4*32 + ni*8 + ec;
            float bx = 0.f, by = 0.f;
            if (bias) { float2 bb = *reinterpret_cast<const float2*>(bias + gn);
                        bx = bb.x; by = bb.y; }
            float v0 = acc[mi][ni][0] + bx, v1 = acc[mi][ni][1] + by;
            float v2 = acc[mi][ni][2] + bx, v3 = acc[mi][ni][3] + by;
            if (act == 1) {
                v0 = fmaxf(v0, 0.f); v1 = fmaxf(v1, 0.f);
                v2 = fmaxf(v2, 0.f); v3 = fmaxf(v3, 0.f);
            } else if (act == 2) {
                v0 = tanhf(v0); v1 = tanhf(v1); v2 = tanhf(v2); v3 = tanhf(v3);
            }
            if (Cf) {
                if (gm0 < Mdim)
                    *reinterpret_cast<float2*>(Cf + (size_t)gm0 * Ndim + gn) = make_float2(v0, v1);
                if (gm0 + 8 < Mdim)
                    *reinterpret_cast<float2*>(Cf + (size_t)(gm0+8) * Ndim + gn) = make_float2(v2, v3);
            }
            if (Chalf) {
                if (gm0 < Mdim) {
                    __half2 h; h.x = __float2half_rn(v0); h.y = __float2half_rn(v1);
                    *reinterpret_cast<__half2*>(Chalf + (size_t)gm0 * Ndim + gn) = h;
                }
                if (gm0 + 8 < Mdim) {
                    __half2 h; h.x = __float2half_rn(v2); h.y = __float2half_rn(v3);
                    *reinterpret_cast<__half2*>(Chalf + (size_t)(gm0+8) * Ndim + gn) = h;
                }
            }
        }
    }
}

// ---------------- fp32 -> fp16 convert (multi-tensor) ----------------
__device__ __forceinline__ void cvt_one(const float* in, __half* o, int i) {
    float4 v = *reinterpret_cast<const float4*>(in + (size_t)i * 4);
    __half2 h0, h1;
    h0.x = __float2half_rn(v.x); h0.y = __float2half_rn(v.y);
    h1.x = __float2half_rn(v.z); h1.y = __float2half_rn(v.w);
    uint2 u;
    u.x = *reinterpret_cast<uint32_t*>(&h0);
    u.y = *reinterpret_cast<uint32_t*>(&h1);
    *reinterpret_cast<uint2*>(o + (size_t)i * 4) = u;
}
__global__ void cvt3_kernel(const float* i1, __half* o1, int n1,
                            const float* i2, __half* o2, int n2,
                            const float* i3, __half* o3, int n3) {
    int i = blockIdx.x * blockDim.x + threadIdx.x;
    if (i < n1) { cvt_one(i1, o1, i); return; }
    i -= n1;
    if (i < n2) { cvt_one(i2, o2, i); return; }
    i -= n2;
    if (i < n3) cvt_one(i3, o3, i);
}
__global__ void cvt2_kernel(const float* i1, __half* o1, int n1,
                            const float* i2, __half* o2, int n2) {
    int i = blockIdx.x * blockDim.x + threadIdx.x;
    if (i < n1) { cvt_one(i1, o1, i); return; }
    i -= n1;
    if (i < n2) cvt_one(i2, o2, i);
}

// ---------------- fused span-id + PE table ----------------
__global__ void spanpe_kernel(const int* __restrict__ pos1, int* __restrict__ span,
                              float* __restrict__ pe) {
    if (blockIdx.x < 32) {
        int b = blockIdx.x;
        int j = threadIdx.x;
        __shared__ int firstZero;
        span[b*M_ + j] = -1;
        if (j == 0) firstZero = M_;
        __syncthreads();
        int endv = pos1[((size_t)b*M_ + j)*2 + 1];
        if (endv == 0) atomicMin(&firstZero, j);
        __syncthreads();
        if (j < firstZero) {
            int st = pos1[((size_t)b*M_ + j)*2];
            int en = endv; if (en > M_) en = M_;
            for (int k = st; k < en; k++)
                atomicMax(&span[b*M_ + k], j);
        }
    } else {
        int idx = (blockIdx.x - 32) * 512 + threadIdx.x;
        if (idx >= M_ * E_) return;
        int pos = idx / E_, i = idx % E_;
        double e2  = (double)((i / 2) * 2);
        double ang = (double)pos / pow(10000.0, e2 / (double)E_);
        pe[idx] = (float)((i % 2 == 0) ? sin(ang) : cos(ang));
    }
}

// ---------------- build x [B,S,E] + f16 copy ----------------
__global__ void build_x_kernel(const int* __restrict__ pos2,
                               const float* __restrict__ fbase,
                               const float* __restrict__ emb,
                               const int* __restrict__ span,
                               const float* __restrict__ pe,
                               float* __restrict__ X,
                               __half* __restrict__ Xf) {
    int row = blockIdx.x;
    int b = row / S_, s = row % S_;
    size_t base = (size_t)row * E_;
    int e = threadIdx.x;
    float val;
    if (s == 0) {
        val = emb[(size_t)1*E_ + e];
    } else {
        int k = s - 1;
        int sid = span[b*M_ + k];
        if (sid >= 0) {
            int p = pos2[b*M_ + sid];
            val = (p == 0 ? 0.0f : emb[(size_t)p*E_ + e]) + pe[(size_t)sid*E_ + e];
        } else {
            val = fbase[((size_t)b*M_ + k)*E_ + e];
        }
    }
    X[base + e] = val;
    Xf[base + e] = __float2half_rn(val);
}

// ---------------- fused attention over the B axis ----------------
__global__ void attn_kernel(const __half* __restrict__ QKV,
                            __half* __restrict__ CXf) {
    int z = blockIdx.x;
    int s = z / NHEAD_, h = z % NHEAD_;
    __shared__ float q[B_][DH_];
    __shared__ float k[B_][DH_ + 1];   // pad: conflict-free scores
    __shared__ float v[B_][DH_];
    __shared__ float sc[B_][B_ + 1];

    const __half* base = QKV + (size_t)s * 3*E_ + (size_t)h * DH_;
    int t = threadIdx.x;

    for (int i = t; i < B_*(DH_/2); i += 256) {
        int b = i / (DH_/2), d2 = i % (DH_/2);
        size_t off = (size_t)b * S_ * 3*E_ + 2*d2;
        __half2 hq = *reinterpret_cast<const __half2*>(base + off);
        __half2 hk = *reinterpret_cast<const __half2*>(base + off + E_);
        __half2 hv = *reinterpret_cast<const __half2*>(base + off + 2*E_);
        q[b][2*d2] = __half2float(hq.x); q[b][2*d2+1] = __half2float(hq.y);
        k[b][2*d2] = __half2float(hk.x); k[b][2*d2+1] = __half2float(hk.y);
        v[b][2*d2] = __half2float(hv.x); v[b][2*d2+1] = __half2float(hv.y);
    }
    __syncthreads();

    for (int i = t; i < B_*B_; i += 256) {
        int l = i / B_, m = i % B_;
        float acc = 0.0f;
        #pragma unroll
        for (int d = 0; d < DH_; d++) acc += q[l][d] * k[m][d];
        sc[l][m] = acc * 0.125f;
    }
    __syncthreads();

    int warp = t >> 5, lane = t & 31;
    for (int l = warp; l < B_; l += 8) {
        float val = sc[l][lane];
        float mx = val;
        #pragma unroll
        for (int o = 16; o; o >>= 1) mx = fmaxf(mx, __shfl_xor_sync(0xffffffffu, mx, o));
        float e = expf(val - mx);
        float sum = e;
        #pragma unroll
        for (int o = 16; o; o >>= 1) sum += __shfl_xor_sync(0xffffffffu, sum, o);
        sc[l][lane] = e / sum;
    }
    __syncthreads();

    for (int i = t; i < B_*DH_; i += 256) {
        int l = i / DH_, d = i % DH_;
        float acc = 0.0f;
        #pragma unroll
        for (int m = 0; m < B_; m++) acc += sc[l][m] * v[m][d];
        CXf[((size_t)l * S_ + s) * E_ + (size_t)h * DH_ + d] = __float2half_rn(acc);
    }
}

// ---------------- residual add + layernorm: warp per row, no block syncs ------
__global__ void add_ln_kernel(float* __restrict__ x, const float* __restrict__ y,
                              const float* __restrict__ w, const float* __restrict__ b,
                              __half* __restrict__ Xf, int storeX) {
    int row  = blockIdx.x * 8 + (threadIdx.x >> 5);   // 8 warps = 8 rows
    int lane = threadIdx.x & 31;
    const float4* xr = reinterpret_cast<const float4*>(x + (size_t)row * E_);
    const float4* yr = reinterpret_cast<const float4*>(y + (size_t)row * E_);

    float4 vv[4];
    float s = 0.f, s2 = 0.f;
    #pragma unroll
    for (int j = 0; j < 4; j++) {
        float4 a = xr[lane + 32*j];
        float4 c = yr[lane + 32*j];
        a.x += c.x; a.y += c.y; a.z += c.z; a.w += c.w;
        s  += a.x + a.y + a.z + a.w;
        s2 += a.x*a.x + a.y*a.y + a.z*a.z + a.w*a.w;
        vv[j] = a;
    }
    #pragma unroll
    for (int o = 16; o; o >>= 1) {
        s  += __shfl_xor_sync(0xffffffffu, s,  o);
        s2 += __shfl_xor_sync(0xffffffffu, s2, o);
    }
    float mean = s * (1.0f / E_);
    float rstd = rsqrtf(s2 * (1.0f / E_) - mean*mean + 1e-5f);

    float4* xw = reinterpret_cast<float4*>(x + (size_t)row * E_);
    #pragma unroll
    for (int j = 0; j < 4; j++) {
        int i4 = lane + 32*j;
        float4 wf = reinterpret_cast<const float4*>(w)[i4];
        float4 bf = reinterpret_cast<const float4*>(b)[i4];
        float4 o;
        o.x = (vv[j].x - mean) * rstd * wf.x + bf.x;
        o.y = (vv[j].y - mean) * rstd * wf.y + bf.y;
        o.z = (vv[j].z - mean) * rstd * wf.z + bf.z;
        o.w = (vv[j].w - mean) * rstd * wf.w + bf.w;
        if (storeX) xw[i4] = o;
        __half2 h0, h1;
        h0.x = __float2half_rn(o.x); h0.y = __float2half_rn(o.y);
        h1.x = __float2half_rn(o.z); h1.y = __float2half_rn(o.w);
        uint2 u;
        u.x = *reinterpret_cast<uint32_t*>(&h0);
        u.y = *reinterpret_cast<uint32_t*>(&h1);
        *reinterpret_cast<uint2*>(Xf + (size_t)row * E_ + 4*i4) = u;
    }
}

// ---------------- discriminator head (posf fp16) ----------------
__global__ void disc_kernel(const float* __restrict__ bert,
                            const __half* __restrict__ posf,
                            const float* __restrict__ wd,
                            const float* __restrict__ bd,
                            float* __restrict__ out, int ntok) {
    int n = (blockIdx.x * blockDim.x + threadIdx.x) >> 5;
    int lane = threadIdx.x & 31;
    if (n >= ntok) return;
    float acc = 0.0f;
    const float*  br = bert + (size_t)n * F_;
    const __half* pr = posf + (size_t)n * F_;
    for (int i = lane; i < F_; i += 32) acc += br[i] * wd[i];
    for (int i = lane; i < F_; i += 32) acc += __half2float(pr[i]) * wd[F_ + i];
    #pragma unroll
    for (int o = 16; o; o >>= 1) acc += __shfl_xor_sync(0xffffffffu, acc, o);
    if (lane == 0) out[n] = 1.0f / (1.0f + expf(-(acc + bd[0])));
}

// ---------------- host orchestration ----------------
static inline int cdiv(int a, int b) { return (a + b - 1) / b; }

extern "C" void kernel_launch(void* const* d_in, const int* in_sizes, int n_in,
                              void* d_out, int out_size) {
    const int*   pos1  = (const int*)d_in[0];
    const int*   pos2  = (const int*)d_in[1];
    const float* bert  = (const float*)d_in[2];
    const float* fbase = (const float*)d_in[3];
    const float* emb   = (const float*)d_in[4];
    const float* wqkv  = (const float*)d_in[5];
    const float* bqkv  = (const float*)d_in[6];
    const float* wo    = (const float*)d_in[7];
    const float* bo    = (const float*)d_in[8];
    const float* ln1w  = (const float*)d_in[9];
    const float* ln1b  = (const float*)d_in[10];
    const float* ln2w  = (const float*)d_in[11];
    const float* ln2b  = (const float*)d_in[12];
    const float* w1    = (const float*)d_in[13];
    const float* b1    = (const float*)d_in[14];
    const float* w2    = (const float*)d_in[15];
    const float* b2    = (const float*)d_in[16];
    const float* wm    = (const float*)d_in[17];
    const float* wd    = (const float*)d_in[18];
    const float* bd    = (const float*)d_in[19];
    float* out = (float*)d_out;

    float *PE, *X, *Y; int* SPAN;
    __half *Xf, *QKVf, *CXf, *Hf, *POSFh, *WQf, *WOf, *W1f, *W2f, *WMf;
    cudaGetSymbolAddress((void**)&PE,    d_PE);
    cudaGetSymbolAddress((void**)&SPAN,  d_SPAN);
    cudaGetSymbolAddress((void**)&X,     d_X);
    cudaGetSymbolAddress((void**)&Y,     d_Y);
    cudaGetSymbolAddress((void**)&Xf,    d_Xf);
    cudaGetSymbolAddress((void**)&QKVf,  d_QKVf);
    cudaGetSymbolAddress((void**)&CXf,   d_CXf);
    cudaGetSymbolAddress((void**)&Hf,    d_Hf);
    cudaGetSymbolAddress((void**)&POSFh, d_POSFh);
    cudaGetSymbolAddress((void**)&WQf,   d_WQf);
    cudaGetSymbolAddress((void**)&WOf,   d_WOf);
    cudaGetSymbolAddress((void**)&W1f,   d_W1f);
    cudaGetSymbolAddress((void**)&W2f,   d_W2f);
    cudaGetSymbolAddress((void**)&WMf,   d_WMf);

    cudaFuncSetAttribute(gemm_tc, cudaFuncAttributeMaxDynamicSharedMemorySize, SMEM_GEMM);

    // launch 0: convert wqkv + wo
    {
        int n1 = 2*3*E_*E_/4, n2 = 2*E_*E_/4;
        cvt2_kernel<<<cdiv(n1+n2,256),256>>>(wqkv, WQf, n1, wo, WOf, n2);
    }
    // launch 1: fused span + PE
    spanpe_kernel<<<32 + cdiv(M_*E_, 512), 512>>>(pos1, SPAN, PE);
    // launch 2: build x
    build_x_kernel<<<NTOK, 512>>>(pos2, fbase, emb, SPAN, PE, X, Xf);

    const int MY = cdiv(NTOK, BM);   // 129
    bool cvt3_done = false;

    for (int l = 0; l < 2; l++) {
        const size_t oq = (size_t)l * 3*E_ * E_;
        const size_t oo = (size_t)l * E_ * E_;
        const size_t o1 = (size_t)l * DFF_ * E_;
        const size_t o2 = (size_t)l * E_ * DFF_;

        { dim3 g(3*E_/BN, MY);   // QKV (fp16 out) — launch 3, layer 0
          gemm_tc<<<g, NTHR_G, SMEM_GEMM>>>(Xf, WQf+oq,
              nullptr, QKVf, NTOK, 3*E_, E_, bqkv + l*3*E_, 0); }

        if (!cvt3_done) {
            int n1 = 2*DFF_*E_/4, n2 = 2*E_*DFF_/4, n3 = F_*E_/4;
            cvt3_kernel<<<cdiv(n1+n2+n3,256),256>>>(w1, W1f, n1,
                                                    w2, W2f, n2,
                                                    wm, WMf, n3);
            cvt3_done = true;
        }

        attn_kernel<<<S_*NHEAD_, 256>>>(QKVf, CXf);

        { dim3 g(E_/BN, MY);     // Wo
          gemm_tc<<<g, NTHR_G, SMEM_GEMM>>>(CXf, WOf+oo,
              Y, nullptr, NTOK, E_, E_, bo + l*E_, 0); }

        add_ln_kernel<<<NTOK/8, 256>>>(X, Y, ln1w + l*E_, ln1b + l*E_, Xf, 1);

        { dim3 g(DFF_/BN, MY);   // FFN1 -> f16 H
          gemm_tc<<<g, NTHR_G, SMEM_GEMM>>>(Xf, W1f+o1,
              nullptr, Hf, NTOK, DFF_, E_, b1 + l*DFF_, 1); }

        { dim3 g(E_/BN, MY);     // FFN2
          gemm_tc<<<g, NTHR_G, SMEM_GEMM>>>(Hf, W2f+o2,
              Y, nullptr, NTOK, E_, DFF_, b2 + l*E_, 0); }

        // last LN: X fp32 not needed afterwards (only Xf feeds wm GEMM)
        add_ln_kernel<<<NTOK/8, 256>>>(X, Y, ln2w + l*E_, ln2b + l*E_, Xf,
                                       (l == 1) ? 0 : 1);
    }

    { dim3 g(F_/BN, MY);         // pos_feature = tanh(X @ wm^T), fp16 out
      gemm_tc<<<g, NTHR_G, SMEM_GEMM>>>(Xf, WMf,
          nullptr, POSFh, NTOK, F_, E_, nullptr, 2); }

    disc_kernel<<<cdiv(NTOK*32, 256), 256>>>(bert, POSFh, wd, bd, out, NTOK);
}

// round 13
// speedup vs baseline: 10.8907x; 1.0001x over previous
#include <cuda_runtime.h>
#include <cuda_fp16.h>
#include <math.h>
#include <stdint.h>

// ---------------- problem constants ----------------
#define B_    32
#define M_    512
#define E_    512
#define S_    513
#define NTOK  (B_*S_)          // 16416
#define NHEAD_ 8
#define DH_   64
#define DFF_  2048
#define F_    768

// ---------------- scratch ----------------
__device__ float d_PE[M_*E_];
__device__ int   d_SPAN[B_*M_];

// ---------------- fp16 activation / weight buffers ----------------
__device__ __align__(16) __half d_Xf   [(size_t)NTOK*E_];
__device__ __align__(16) __half d_Yh   [(size_t)NTOK*E_];
__device__ __align__(16) __half d_QKVf [(size_t)NTOK*3*E_];
__device__ __align__(16) __half d_CXf  [(size_t)NTOK*E_];
__device__ __align__(16) __half d_Hf   [(size_t)NTOK*DFF_];
__device__ __align__(16) __half d_POSFh[(size_t)NTOK*F_];
__device__ __align__(16) __half d_WQf  [(size_t)2*3*E_*E_];
__device__ __align__(16) __half d_WOf  [(size_t)2*E_*E_];
__device__ __align__(16) __half d_W1f  [(size_t)2*DFF_*E_];
__device__ __align__(16) __half d_W2f  [(size_t)2*E_*DFF_];
__device__ __align__(16) __half d_WMf  [(size_t)F_*E_];

// ================= fp16 tensor-core GEMM (BK=64, 2 CTAs/SM) ========
#define BM 128
#define BN 128
#define BK 64
#define PADB 144
#define A_ARR (128*PADB)
#define B_ARR (128*PADB)
#define STAGE (A_ARR + B_ARR)
#define NSTAGE 3
#define SMEM_GEMM (NSTAGE*STAGE)
#define NTHR_G 256

__device__ __forceinline__ uint32_t smem_u32(const void* p) {
    uint32_t a;
    asm("{ .reg .u64 t; cvta.to.shared.u64 t, %1; cvt.u32.u64 %0, t; }"
        : "=r"(a) : "l"(p));
    return a;
}
__device__ __forceinline__ void ldsm4(uint32_t* r, uint32_t addr) {
    asm volatile("ldmatrix.sync.aligned.m8n8.x4.shared.b16 {%0,%1,%2,%3}, [%4];"
        : "=r"(r[0]), "=r"(r[1]), "=r"(r[2]), "=r"(r[3]) : "r"(addr));
}
__device__ __forceinline__ void mma16816(float* c, const uint32_t* a, const uint32_t* b) {
    asm volatile(
        "mma.sync.aligned.m16n8k16.row.col.f32.f16.f16.f32 "
        "{%0,%1,%2,%3}, {%4,%5,%6,%7}, {%8,%9}, {%0,%1,%2,%3};"
        : "+f"(c[0]), "+f"(c[1]), "+f"(c[2]), "+f"(c[3])
        : "r"(a[0]), "r"(a[1]), "r"(a[2]), "r"(a[3]), "r"(b[0]), "r"(b[1]));
}
__device__ __forceinline__ void cpa16(uint32_t dst, const void* src, int srcsize) {
    asm volatile("cp.async.cg.shared.global [%0], [%1], 16, %2;"
                 :: "r"(dst), "l"(src), "r"(srcsize));
}

__device__ __forceinline__ void load_stage(
    uint32_t st,
    const __half* __restrict__ Af, const __half* __restrict__ Bf,
    int tile_m, int tile_n, int Mdim, int Kdim, int kc, int tid)
{
    const int k0 = kc * BK;
    #pragma unroll
    for (int i = 0; i < 4; i++) {
        int id = tid + NTHR_G*i;
        int row = id >> 3, c = id & 7;
        const __half* src = Af + (size_t)(tile_m + row) * Kdim + k0 + c*8;
        cpa16(st + row*PADB + c*16, src, (tile_m + row) < Mdim ? 16 : 0);
    }
    #pragma unroll
    for (int i = 0; i < 4; i++) {
        int id = tid + NTHR_G*i;
        int row = id >> 3, c = id & 7;
        const __half* src = Bf + (size_t)(tile_n + row) * Kdim + k0 + c*8;
        cpa16(st + A_ARR + row*PADB + c*16, src, 16);
    }
    asm volatile("cp.async.commit_group;" ::: "memory");
}

__global__ __launch_bounds__(NTHR_G, 2)
void gemm_tc(const __half* __restrict__ Af, const __half* __restrict__ Bf,
             float* __restrict__ Cf, __half* __restrict__ Chalf,
             int Mdim, int Ndim, int Kdim,
             const float* __restrict__ bias, int act)
{
    extern __shared__ __align__(16) char smem[];
    const uint32_t sb = smem_u32(smem);
    const int tid    = threadIdx.x;
    const int tile_m = blockIdx.y * BM;
    const int tile_n = blockIdx.x * BN;
    const int warp = tid >> 5, lane = tid & 31;
    const int wm2 = warp >> 2, wn4 = warp & 3;

    float acc[4][4][4];
    #pragma unroll
    for (int a = 0; a < 4; a++)
        #pragma unroll
        for (int b = 0; b < 4; b++)
            #pragma unroll
            for (int q = 0; q < 4; q++) acc[a][b][q] = 0.0f;

    const int nst = Kdim / BK;
    load_stage(sb,         Af, Bf, tile_m, tile_n, Mdim, Kdim, 0, tid);
    load_stage(sb + STAGE, Af, Bf, tile_m, tile_n, Mdim, Kdim, 1, tid);

    const uint32_t a_off = (uint32_t)(wm2*64 + (lane & 7) + ((lane >> 3) & 1) * 8) * PADB
                         + ((lane >> 4) * 16);
    const uint32_t b_off = (uint32_t)(wn4*32 + (lane & 7) + ((lane >> 4) & 1) * 8) * PADB
                         + (((lane >> 3) & 1) * 16);

    for (int s = 0; s < nst; s++) {
        if (s + 1 < nst) asm volatile("cp.async.wait_group 1;" ::: "memory");
        else             asm volatile("cp.async.wait_group 0;" ::: "memory");
        __syncthreads();
        if (s + 2 < nst)
            load_stage(sb + ((s + 2) % NSTAGE) * STAGE, Af, Bf,
                       tile_m, tile_n, Mdim, Kdim, s + 2, tid);
        const uint32_t st = sb + (s % NSTAGE) * STAGE;

        #pragma unroll
        for (int ks = 0; ks < 4; ks++) {
            uint32_t ah[4][4], bh[4][2];
            #pragma unroll
            for (int mi = 0; mi < 4; mi++)
                ldsm4(ah[mi], st + a_off + mi * (16 * PADB) + ks * 32);
            #pragma unroll
            for (int p = 0; p < 2; p++) {
                uint32_t r[4];
                ldsm4(r, st + A_ARR + b_off + p * (16 * PADB) + ks * 32);
                bh[2*p][0] = r[0]; bh[2*p][1] = r[1];
                bh[2*p+1][0] = r[2]; bh[2*p+1][1] = r[3];
            }
            #pragma unroll
            for (int mi = 0; mi < 4; mi++)
                #pragma unroll
                for (int ni = 0; ni < 4; ni++)
                    mma16816(acc[mi][ni], ah[mi], bh[ni]);
        }
    }

    // ---- epilogue ----
    const int er = lane >> 2;
    const int ec = (lane & 3) * 2;
    #pragma unroll
    for (int mi = 0; mi < 4; mi++) {
        const int gm0 = tile_m + wm2*64 + mi*16 + er;
        #pragma unroll
        for (int ni = 0; ni < 4; ni++) {
            const int gn = tile_n + wn4*32 + ni*8 + ec;
            float bx = 0.f, by = 0.f;
            if (bias) { float2 bb = *reinterpret_cast<const float2*>(bias + gn);
                        bx = bb.x; by = bb.y; }
            float v0 = acc[mi][ni][0] + bx, v1 = acc[mi][ni][1] + by;
            float v2 = acc[mi][ni][2] + bx, v3 = acc[mi][ni][3] + by;
            if (act == 1) {
                v0 = fmaxf(v0, 0.f); v1 = fmaxf(v1, 0.f);
                v2 = fmaxf(v2, 0.f); v3 = fmaxf(v3, 0.f);
            } else if (act == 2) {
                v0 = tanhf(v0); v1 = tanhf(v1); v2 = tanhf(v2); v3 = tanhf(v3);
            }
            if (Cf) {
                if (gm0 < Mdim)
                    *reinterpret_cast<float2*>(Cf + (size_t)gm0 * Ndim + gn) = make_float2(v0, v1);
                if (gm0 + 8 < Mdim)
                    *reinterpret_cast<float2*>(Cf + (size_t)(gm0+8) * Ndim + gn) = make_float2(v2, v3);
            }
            if (Chalf) {
                if (gm0 < Mdim) {
                    __half2 h; h.x = __float2half_rn(v0); h.y = __float2half_rn(v1);
                    *reinterpret_cast<__half2*>(Chalf + (size_t)gm0 * Ndim + gn) = h;
                }
                if (gm0 + 8 < Mdim) {
                    __half2 h; h.x = __float2half_rn(v2); h.y = __float2half_rn(v3);
                    *reinterpret_cast<__half2*>(Chalf + (size_t)(gm0+8) * Ndim + gn) = h;
                }
            }
        }
    }
}

// ---------------- fp32 -> fp16 convert (multi-tensor) ----------------
__device__ __forceinline__ void cvt_one(const float* in, __half* o, int i) {
    float4 v = *reinterpret_cast<const float4*>(in + (size_t)i * 4);
    __half2 h0, h1;
    h0.x = __float2half_rn(v.x); h0.y = __float2half_rn(v.y);
    h1.x = __float2half_rn(v.z); h1.y = __float2half_rn(v.w);
    uint2 u;
    u.x = *reinterpret_cast<uint32_t*>(&h0);
    u.y = *reinterpret_cast<uint32_t*>(&h1);
    *reinterpret_cast<uint2*>(o + (size_t)i * 4) = u;
}
__global__ void cvt3_kernel(const float* i1, __half* o1, int n1,
                            const float* i2, __half* o2, int n2,
                            const float* i3, __half* o3, int n3) {
    int i = blockIdx.x * blockDim.x + threadIdx.x;
    if (i < n1) { cvt_one(i1, o1, i); return; }
    i -= n1;
    if (i < n2) { cvt_one(i2, o2, i); return; }
    i -= n2;
    if (i < n3) cvt_one(i3, o3, i);
}
__global__ void cvt2_kernel(const float* i1, __half* o1, int n1,
                            const float* i2, __half* o2, int n2) {
    int i = blockIdx.x * blockDim.x + threadIdx.x;
    if (i < n1) { cvt_one(i1, o1, i); return; }
    i -= n1;
    if (i < n2) cvt_one(i2, o2, i);
}

// ---------------- fused span-id + PE table ----------------
__global__ void spanpe_kernel(const int* __restrict__ pos1, int* __restrict__ span,
                              float* __restrict__ pe) {
    if (blockIdx.x < 32) {
        int b = blockIdx.x;
        int j = threadIdx.x;
        __shared__ int firstZero;
        span[b*M_ + j] = -1;
        if (j == 0) firstZero = M_;
        __syncthreads();
        int endv = pos1[((size_t)b*M_ + j)*2 + 1];
        if (endv == 0) atomicMin(&firstZero, j);
        __syncthreads();
        if (j < firstZero) {
            int st = pos1[((size_t)b*M_ + j)*2];
            int en = endv; if (en > M_) en = M_;
            for (int k = st; k < en; k++)
                atomicMax(&span[b*M_ + k], j);
        }
    } else {
        int idx = (blockIdx.x - 32) * 512 + threadIdx.x;
        if (idx >= M_ * E_) return;
        int pos = idx / E_, i = idx % E_;
        double e2  = (double)((i / 2) * 2);
        double ang = (double)pos / pow(10000.0, e2 / (double)E_);
        pe[idx] = (float)((i % 2 == 0) ? sin(ang) : cos(ang));
    }
}

// ---------------- build x [B,S,E] -> fp16 ----------------
__global__ void build_x_kernel(const int* __restrict__ pos2,
                               const float* __restrict__ fbase,
                               const float* __restrict__ emb,
                               const int* __restrict__ span,
                               const float* __restrict__ pe,
                               __half* __restrict__ Xf) {
    int row = blockIdx.x;
    int b = row / S_, s = row % S_;
    size_t base = (size_t)row * E_;
    int e = threadIdx.x;
    float val;
    if (s == 0) {
        val = emb[(size_t)1*E_ + e];
    } else {
        int k = s - 1;
        int sid = span[b*M_ + k];
        if (sid >= 0) {
            int p = pos2[b*M_ + sid];
            val = (p == 0 ? 0.0f : emb[(size_t)p*E_ + e]) + pe[(size_t)sid*E_ + e];
        } else {
            val = fbase[((size_t)b*M_ + k)*E_ + e];
        }
    }
    Xf[base + e] = __float2half_rn(val);
}

// ---------------- fused attention over the B axis ----------------
__global__ void attn_kernel(const __half* __restrict__ QKV,
                            __half* __restrict__ CXf) {
    int z = blockIdx.x;
    int s = z / NHEAD_, h = z % NHEAD_;
    __shared__ float q[B_][DH_];
    __shared__ float k[B_][DH_ + 1];   // pad: conflict-free scores
    __shared__ float v[B_][DH_];
    __shared__ float sc[B_][B_ + 1];

    const __half* base = QKV + (size_t)s * 3*E_ + (size_t)h * DH_;
    int t = threadIdx.x;

    for (int i = t; i < B_*(DH_/2); i += 256) {
        int b = i / (DH_/2), d2 = i % (DH_/2);
        size_t off = (size_t)b * S_ * 3*E_ + 2*d2;
        __half2 hq = *reinterpret_cast<const __half2*>(base + off);
        __half2 hk = *reinterpret_cast<const __half2*>(base + off + E_);
        __half2 hv = *reinterpret_cast<const __half2*>(base + off + 2*E_);
        q[b][2*d2] = __half2float(hq.x); q[b][2*d2+1] = __half2float(hq.y);
        k[b][2*d2] = __half2float(hk.x); k[b][2*d2+1] = __half2float(hk.y);
        v[b][2*d2] = __half2float(hv.x); v[b][2*d2+1] = __half2float(hv.y);
    }
    __syncthreads();

    for (int i = t; i < B_*B_; i += 256) {
        int l = i / B_, m = i % B_;
        float acc = 0.0f;
        #pragma unroll
        for (int d = 0; d < DH_; d++) acc += q[l][d] * k[m][d];
        sc[l][m] = acc * 0.125f;
    }
    __syncthreads();

    int warp = t >> 5, lane = t & 31;
    for (int l = warp; l < B_; l += 8) {
        float val = sc[l][lane];
        float mx = val;
        #pragma unroll
        for (int o = 16; o; o >>= 1) mx = fmaxf(mx, __shfl_xor_sync(0xffffffffu, mx, o));
        float e = expf(val - mx);
        float sum = e;
        #pragma unroll
        for (int o = 16; o; o >>= 1) sum += __shfl_xor_sync(0xffffffffu, sum, o);
        sc[l][lane] = e / sum;
    }
    __syncthreads();

    for (int i = t; i < B_*DH_; i += 256) {
        int l = i / DH_, d = i % DH_;
        float acc = 0.0f;
        #pragma unroll
        for (int m = 0; m < B_; m++) acc += sc[l][m] * v[m][d];
        CXf[((size_t)l * S_ + s) * E_ + (size_t)h * DH_ + d] = __float2half_rn(acc);
    }
}

// ---------------- residual add + layernorm: all-fp16 IO, warp per row ------
__global__ void add_ln_kernel(__half* __restrict__ Xf, const __half* __restrict__ Yh,
                              const float* __restrict__ w, const float* __restrict__ b) {
    int row  = blockIdx.x * 8 + (threadIdx.x >> 5);   // 8 warps = 8 rows
    int lane = threadIdx.x & 31;
    const uint4* xr = reinterpret_cast<const uint4*>(Xf + (size_t)row * E_);  // 64 uint4
    const uint4* yr = reinterpret_cast<const uint4*>(Yh + (size_t)row * E_);

    float vals[16];
    float s = 0.f, s2 = 0.f;
    #pragma unroll
    for (int j = 0; j < 2; j++) {
        uint4 xa = xr[lane + 32*j];
        uint4 ya = yr[lane + 32*j];
        const __half2* xh = reinterpret_cast<const __half2*>(&xa);
        const __half2* yh = reinterpret_cast<const __half2*>(&ya);
        #pragma unroll
        for (int q = 0; q < 4; q++) {
            float2 fx = __half22float2(xh[q]);
            float2 fy = __half22float2(yh[q]);
            float a0 = fx.x + fy.x, a1 = fx.y + fy.y;
            vals[j*8 + 2*q]     = a0;
            vals[j*8 + 2*q + 1] = a1;
            s  += a0 + a1;
            s2 += a0*a0 + a1*a1;
        }
    }
    #pragma unroll
    for (int o = 16; o; o >>= 1) {
        s  += __shfl_xor_sync(0xffffffffu, s,  o);
        s2 += __shfl_xor_sync(0xffffffffu, s2, o);
    }
    float mean = s * (1.0f / E_);
    float rstd = rsqrtf(s2 * (1.0f / E_) - mean*mean + 1e-5f);

    uint4* xw = reinterpret_cast<uint4*>(Xf + (size_t)row * E_);
    #pragma unroll
    for (int j = 0; j < 2; j++) {
        int base = (lane + 32*j) * 8;
        uint4 o;
        __half2* oh = reinterpret_cast<__half2*>(&o);
        #pragma unroll
        for (int q = 0; q < 4; q++) {
            float2 wv = *reinterpret_cast<const float2*>(w + base + 2*q);
            float2 bv = *reinterpret_cast<const float2*>(b + base + 2*q);
            float o0 = (vals[j*8 + 2*q]     - mean) * rstd * wv.x + bv.x;
            float o1 = (vals[j*8 + 2*q + 1] - mean) * rstd * wv.y + bv.y;
            __half2 h; h.x = __float2half_rn(o0); h.y = __float2half_rn(o1);
            oh[q] = h;
        }
        xw[lane + 32*j] = o;
    }
}

// ---------------- discriminator head (vectorized) ----------------
__global__ void disc_kernel(const float* __restrict__ bert,
                            const __half* __restrict__ posf,
                            const float* __restrict__ wd,
                            const float* __restrict__ bd,
                            float* __restrict__ out, int ntok) {
    int n = (blockIdx.x * blockDim.x + threadIdx.x) >> 5;
    int lane = threadIdx.x & 31;
    if (n >= ntok) return;
    float acc = 0.0f;
    const float4* br4 = reinterpret_cast<const float4*>(bert + (size_t)n * F_);
    const float4* wd4 = reinterpret_cast<const float4*>(wd);
    #pragma unroll
    for (int j = 0; j < 6; j++) {                    // 6*32*4 = 768 floats
        int idx = lane + 32*j;
        float4 v = br4[idx];
        float4 wv = wd4[idx];
        acc += v.x*wv.x + v.y*wv.y + v.z*wv.z + v.w*wv.w;
    }
    const uint4* pr4 = reinterpret_cast<const uint4*>(posf + (size_t)n * F_); // 96 uint4
    #pragma unroll
    for (int j = 0; j < 3; j++) {                    // 3*32*8 = 768 halves
        int idx = lane + 32*j;
        uint4 u = pr4[idx];
        const __half2* ph = reinterpret_cast<const __half2*>(&u);
        const float* wp = wd + F_ + idx*8;
        #pragma unroll
        for (int q = 0; q < 4; q++) {
            float2 f = __half22float2(ph[q]);
            acc += f.x * wp[2*q] + f.y * wp[2*q + 1];
        }
    }
    #pragma unroll
    for (int o = 16; o; o >>= 1) acc += __shfl_xor_sync(0xffffffffu, acc, o);
    if (lane == 0) out[n] = 1.0f / (1.0f + expf(-(acc + bd[0])));
}

// ---------------- host orchestration ----------------
static inline int cdiv(int a, int b) { return (a + b - 1) / b; }

extern "C" void kernel_launch(void* const* d_in, const int* in_sizes, int n_in,
                              void* d_out, int out_size) {
    const int*   pos1  = (const int*)d_in[0];
    const int*   pos2  = (const int*)d_in[1];
    const float* bert  = (const float*)d_in[2];
    const float* fbase = (const float*)d_in[3];
    const float* emb   = (const float*)d_in[4];
    const float* wqkv  = (const float*)d_in[5];
    const float* bqkv  = (const float*)d_in[6];
    const float* wo    = (const float*)d_in[7];
    const float* bo    = (const float*)d_in[8];
    const float* ln1w  = (const float*)d_in[9];
    const float* ln1b  = (const float*)d_in[10];
    const float* ln2w  = (const float*)d_in[11];
    const float* ln2b  = (const float*)d_in[12];
    const float* w1    = (const float*)d_in[13];
    const float* b1    = (const float*)d_in[14];
    const float* w2    = (const float*)d_in[15];
    const float* b2    = (const float*)d_in[16];
    const float* wm    = (const float*)d_in[17];
    const float* wd    = (const float*)d_in[18];
    const float* bd    = (const float*)d_in[19];
    float* out = (float*)d_out;

    float *PE; int* SPAN;
    __half *Xf, *Yh, *QKVf, *CXf, *Hf, *POSFh, *WQf, *WOf, *W1f, *W2f, *WMf;
    cudaGetSymbolAddress((void**)&PE,    d_PE);
    cudaGetSymbolAddress((void**)&SPAN,  d_SPAN);
    cudaGetSymbolAddress((void**)&Xf,    d_Xf);
    cudaGetSymbolAddress((void**)&Yh,    d_Yh);
    cudaGetSymbolAddress((void**)&QKVf,  d_QKVf);
    cudaGetSymbolAddress((void**)&CXf,   d_CXf);
    cudaGetSymbolAddress((void**)&Hf,    d_Hf);
    cudaGetSymbolAddress((void**)&POSFh, d_POSFh);
    cudaGetSymbolAddress((void**)&WQf,   d_WQf);
    cudaGetSymbolAddress((void**)&WOf,   d_WOf);
    cudaGetSymbolAddress((void**)&W1f,   d_W1f);
    cudaGetSymbolAddress((void**)&W2f,   d_W2f);
    cudaGetSymbolAddress((void**)&WMf,   d_WMf);

    cudaFuncSetAttribute(gemm_tc, cudaFuncAttributeMaxDynamicSharedMemorySize, SMEM_GEMM);

    // launch 0: convert wqkv + wo
    {
        int n1 = 2*3*E_*E_/4, n2 = 2*E_*E_/4;
        cvt2_kernel<<<cdiv(n1+n2,256),256>>>(wqkv, WQf, n1, wo, WOf, n2);
    }
    // launch 1: fused span + PE
    spanpe_kernel<<<32 + cdiv(M_*E_, 512), 512>>>(pos1, SPAN, PE);
    // launch 2: build x (fp16 only)
    build_x_kernel<<<NTOK, 512>>>(pos2, fbase, emb, SPAN, PE, Xf);

    const int MY = cdiv(NTOK, BM);   // 129
    bool cvt3_done = false;

    for (int l = 0; l < 2; l++) {
        const size_t oq = (size_t)l * 3*E_ * E_;
        const size_t oo = (size_t)l * E_ * E_;
        const size_t o1 = (size_t)l * DFF_ * E_;
        const size_t o2 = (size_t)l * E_ * DFF_;

        { dim3 g(3*E_/BN, MY);   // QKV (fp16 out) — launch 3, layer 0
          gemm_tc<<<g, NTHR_G, SMEM_GEMM>>>(Xf, WQf+oq,
              nullptr, QKVf, NTOK, 3*E_, E_, bqkv + l*3*E_, 0); }

        if (!cvt3_done) {
            int n1 = 2*DFF_*E_/4, n2 = 2*E_*DFF_/4, n3 = F_*E_/4;
            cvt3_kernel<<<cdiv(n1+n2+n3,256),256>>>(w1, W1f, n1,
                                                    w2, W2f, n2,
                                                    wm, WMf, n3);
            cvt3_done = true;
        }

        attn_kernel<<<S_*NHEAD_, 256>>>(QKVf, CXf);

        { dim3 g(E_/BN, MY);     // Wo -> fp16 Y
          gemm_tc<<<g, NTHR_G, SMEM_GEMM>>>(CXf, WOf+oo,
              nullptr, Yh, NTOK, E_, E_, bo + l*E_, 0); }

        add_ln_kernel<<<NTOK/8, 256>>>(Xf, Yh, ln1w + l*E_, ln1b + l*E_);

        { dim3 g(DFF_/BN, MY);   // FFN1 -> f16 H
          gemm_tc<<<g, NTHR_G, SMEM_GEMM>>>(Xf, W1f+o1,
              nullptr, Hf, NTOK, DFF_, E_, b1 + l*DFF_, 1); }

        { dim3 g(E_/BN, MY);     // FFN2 -> fp16 Y
          gemm_tc<<<g, NTHR_G, SMEM_GEMM>>>(Hf, W2f+o2,
              nullptr, Yh, NTOK, E_, DFF_, b2 + l*E_, 0); }

        add_ln_kernel<<<NTOK/8, 256>>>(Xf, Yh, ln2w + l*E_, ln2b + l*E_);
    }

    { dim3 g(F_/BN, MY);         // pos_feature = tanh(X @ wm^T), fp16 out
      gemm_tc<<<g, NTHR_G, SMEM_GEMM>>>(Xf, WMf,
          nullptr, POSFh, NTOK, F_, E_, nullptr, 2); }

    disc_kernel<<<cdiv(NTOK*32, 256), 256>>>(bert, POSFh, wd, bd, out, NTOK);
}